// round 3
// baseline (speedup 1.0000x reference)
#include <cuda_runtime.h>
#include <math.h>

#define BB 4
#define CC 256
#define NN 4096
#define CR 32

typedef unsigned long long ull;

// Scratch (allocation-free rule: __device__ globals)
__device__ float g_qk[(size_t)BB * NN * 64];   // [b][n][0:32]=q, [32:64]=k   (4 MB)
__device__ float g_v [(size_t)BB * NN * CC];   // [b][m][c]                   (16 MB)

// ---------------- packed fp32x2 helpers (Blackwell) ----------------
__device__ __forceinline__ ull ffma2(ull a, ull b, ull c) {
    ull d;
    asm("fma.rn.f32x2 %0, %1, %2, %3;" : "=l"(d) : "l"(a), "l"(b), "l"(c));
    return d;
}
__device__ __forceinline__ ull fmul2(ull a, ull b) {
    ull d;
    asm("mul.rn.f32x2 %0, %1, %2;" : "=l"(d) : "l"(a), "l"(b));
    return d;
}
__device__ __forceinline__ ull pack2(float lo, float hi) {
    ull r;
    asm("mov.b64 %0, {%1, %2};" : "=l"(r) : "f"(lo), "f"(hi));
    return r;
}
__device__ __forceinline__ void unpack2(ull v, float& lo, float& hi) {
    asm("mov.b64 {%0, %1}, %2;" : "=f"(lo), "=f"(hi) : "l"(v));
}

// ---------------------------------------------------------------------------
// Projection GEMM: y[b, n, o0+o] = sum_c W[o, c] * x[b, c, n]
// ---------------------------------------------------------------------------
template<bool QK>
__global__ __launch_bounds__(256) void proj_kernel(
    const float* __restrict__ x,
    const float* __restrict__ W0,
    const float* __restrict__ W1,
    float* __restrict__ out, int ldo)
{
    const int b  = blockIdx.z;
    const int n0 = blockIdx.x * 64;
    const int o0 = blockIdx.y * 64;
    const int tid = threadIdx.x;
    const int tx = tid & 15;
    const int ty = tid >> 4;

    __shared__ float xs[16][64];
    __shared__ float ws[64][17];

    float acc[4][4];
#pragma unroll
    for (int i = 0; i < 4; i++)
#pragma unroll
        for (int j = 0; j < 4; j++) acc[i][j] = 0.f;

    const float* xb = x + (size_t)b * CC * NN;

    for (int c0 = 0; c0 < CC; c0 += 16) {
#pragma unroll
        for (int i = 0; i < 4; i++) {
            int e  = tid + i * 256;
            int cc = e >> 6, nn = e & 63;
            xs[cc][nn] = xb[(size_t)(c0 + cc) * NN + n0 + nn];
        }
#pragma unroll
        for (int i = 0; i < 4; i++) {
            int e  = tid + i * 256;
            int o  = e >> 4, cc = e & 15;
            int og = o0 + o;
            float wv;
            if (QK) wv = (og < 32) ? W0[og * CC + c0 + cc]
                                   : W1[(og - 32) * CC + c0 + cc];
            else    wv = W0[og * CC + c0 + cc];
            ws[o][cc] = wv;
        }
        __syncthreads();
#pragma unroll
        for (int cc = 0; cc < 16; cc++) {
            float a[4], w[4];
#pragma unroll
            for (int i = 0; i < 4; i++) a[i] = xs[cc][tx * 4 + i];
#pragma unroll
            for (int j = 0; j < 4; j++) w[j] = ws[ty * 4 + j][cc];
#pragma unroll
            for (int i = 0; i < 4; i++)
#pragma unroll
                for (int j = 0; j < 4; j++) acc[i][j] = fmaf(a[i], w[j], acc[i][j]);
        }
        __syncthreads();
    }

#pragma unroll
    for (int i = 0; i < 4; i++) {
        int n = n0 + tx * 4 + i;
#pragma unroll
        for (int j = 0; j < 4; j++) {
            int o = o0 + ty * 4 + j;
            out[((size_t)b * NN + n) * ldo + o] = acc[i][j];
        }
    }
}

// ---------------------------------------------------------------------------
// Fused flash attention + residual. 64 queries per CTA, 256 threads.
// S/exp phases: thread (qi = tid&63, g = tid>>6).
// PV phase:     thread (qb = tid>>4, cb = tid&15) owns 4 queries x 16 channels
//               in 32 packed f32x2 accumulators (outer-product form).
// ---------------------------------------------------------------------------
#define QS_LD 36
#define SS_LD 65

__global__ __launch_bounds__(256, 2) void attn_kernel(
    const float* __restrict__ x, float* __restrict__ out)
{
    extern __shared__ float sm[];
    float* qs   = sm;                    // [64][36]   9216 B (rows 16B-aligned)
    float* ks   = qs + 64 * QS_LD;       // [64][32]   8192 B
    float* ss   = ks + 64 * 32;          // [64][65]   16640 B  (s, then p in-place)
    float* vs   = ss + 64 * SS_LD;       // [64][256]  65536 B
    float* mrow = vs + 64 * 256;         // [64] running max
    float* lrow = mrow + 64;             // [64] running sum
    float* mns  = lrow + 64;             // [64] current tile new max
    float* cs   = mns + 64;              // [64] correction factor
    float* pms  = cs + 64;               // [4][64] partial maxima
    float* pls  = pms + 256;             // [4][64] partial sums

    const int b   = blockIdx.z;
    const int n0  = blockIdx.x * 64;
    const int tid = threadIdx.x;
    const int qi  = tid & 63;
    const int g   = tid >> 6;
    const int qb  = tid >> 4;   // 0..15 (4 queries each)
    const int cb  = tid & 15;   // 0..15 (16 channels each)

    // stage Q tile once: [64 q][32 d]
#pragma unroll
    for (int i = 0; i < 8; i++) {
        int e = tid + i * 256;
        int q = e >> 5, d = e & 31;
        qs[q * QS_LD + d] = g_qk[((size_t)b * NN + n0 + q) * 64 + d];
    }
    if (tid < 64) { mrow[tid] = -1e30f; lrow[tid] = 0.f; }

    ull acc2[32];   // acc2[k*8+cc] = channels (cb*16+2cc, +1) for query qb*4+k
#pragma unroll
    for (int i = 0; i < 32; i++) acc2[i] = 0ULL;

    for (int m0 = 0; m0 < NN; m0 += 64) {
        __syncthreads();   // prev tile consumed; also covers qs/mrow init

        // ---- stage K [64 j][32 d] and V [64 j][256 c] ----
        {
            const float* kbase = g_qk + ((size_t)b * NN + m0) * 64 + 32;
#pragma unroll
            for (int i = 0; i < 2; i++) {
                int e = tid + i * 256;           // j = e>>3, d4 = e&7
                int j = e >> 3, d4 = e & 7;
                float4 kv = *(const float4*)(kbase + (size_t)j * 64 + d4 * 4);
                *(float4*)(ks + j * 32 + d4 * 4) = kv;
            }
            const float4* vsrc = (const float4*)(g_v + ((size_t)b * NN + m0) * CC);
            float4* vdst = (float4*)vs;
#pragma unroll
            for (int i = 0; i < 16; i++) vdst[tid + i * 256] = vsrc[tid + i * 256];
        }
        __syncthreads();

        // ---- S phase: s[qi][j] for 16 j's; Q row in transient registers ----
        {
            ull q2[16];
            const ulonglong2* qsrc = (const ulonglong2*)(qs + qi * QS_LD);
#pragma unroll
            for (int i = 0; i < 8; i++) {
                ulonglong2 qv = qsrc[i];
                q2[2 * i] = qv.x; q2[2 * i + 1] = qv.y;
            }
            float pmax = -1e30f;
#pragma unroll 8
            for (int jj = 0; jj < 16; jj++) {
                int j = g * 16 + jj;
                const ulonglong2* kr = (const ulonglong2*)(ks + j * 32);
                ull s2 = 0ULL;
#pragma unroll
                for (int i = 0; i < 8; i++) {
                    ulonglong2 kv = kr[i];           // broadcast within warp
                    s2 = ffma2(q2[2 * i],     kv.x, s2);
                    s2 = ffma2(q2[2 * i + 1], kv.y, s2);
                }
                float slo, shi;
                unpack2(s2, slo, shi);
                float s = slo + shi;
                ss[qi * SS_LD + j] = s;
                pmax = fmaxf(pmax, s);
            }
            pms[g * 64 + qi] = pmax;
        }
        __syncthreads();

        // ---- row stats: tile max, new running max, correction factor ----
        if (tid < 64) {
            float tmax = fmaxf(fmaxf(pms[tid], pms[64 + tid]),
                               fmaxf(pms[128 + tid], pms[192 + tid]));
            float mold = mrow[tid];
            float mn   = fmaxf(mold, tmax);
            mns[tid]  = mn;
            cs[tid]   = __expf(mold - mn);
            mrow[tid] = mn;
        }
        __syncthreads();

        // ---- exp phase: p = exp(s - mn), in place; partial row sums ----
        {
            float mn = mns[qi];
            float lp = 0.f;
            float* srow = ss + qi * SS_LD + g * 16;
#pragma unroll
            for (int jj = 0; jj < 16; jj++) {
                float p = __expf(srow[jj] - mn);
                srow[jj] = p;
                lp += p;
            }
            pls[g * 64 + qi] = lp;
        }
        __syncthreads();

        // ---- l update for this tile (no sync needed before PV: disjoint data) ----
        if (tid < 64)
            lrow[tid] = lrow[tid] * cs[tid]
                      + pls[tid] + pls[64 + tid] + pls[128 + tid] + pls[192 + tid];

        // ---- PV phase: rescale + accumulate ----
        {
#pragma unroll
            for (int k = 0; k < 4; k++) {
                float corr = cs[qb * 4 + k];
                ull c2 = pack2(corr, corr);
#pragma unroll
                for (int cc = 0; cc < 8; cc++)
                    acc2[k * 8 + cc] = fmul2(acc2[k * 8 + cc], c2);
            }
#pragma unroll 4
            for (int j = 0; j < 64; j++) {
                float p0 = ss[(qb * 4 + 0) * SS_LD + j];
                float p1 = ss[(qb * 4 + 1) * SS_LD + j];
                float p2 = ss[(qb * 4 + 2) * SS_LD + j];
                float p3 = ss[(qb * 4 + 3) * SS_LD + j];
                ull pp0 = pack2(p0, p0), pp1 = pack2(p1, p1);
                ull pp2 = pack2(p2, p2), pp3 = pack2(p3, p3);
                const ulonglong2* vr = (const ulonglong2*)(vs + j * 256 + cb * 16);
                ulonglong2 va = vr[0], vb = vr[1];
                acc2[0]  = ffma2(pp0, va.x, acc2[0]);
                acc2[1]  = ffma2(pp0, va.y, acc2[1]);
                acc2[2]  = ffma2(pp0, vb.x, acc2[2]);
                acc2[3]  = ffma2(pp0, vb.y, acc2[3]);
                acc2[8]  = ffma2(pp1, va.x, acc2[8]);
                acc2[9]  = ffma2(pp1, va.y, acc2[9]);
                acc2[10] = ffma2(pp1, vb.x, acc2[10]);
                acc2[11] = ffma2(pp1, vb.y, acc2[11]);
                acc2[16] = ffma2(pp2, va.x, acc2[16]);
                acc2[17] = ffma2(pp2, va.y, acc2[17]);
                acc2[18] = ffma2(pp2, vb.x, acc2[18]);
                acc2[19] = ffma2(pp2, vb.y, acc2[19]);
                acc2[24] = ffma2(pp3, va.x, acc2[24]);
                acc2[25] = ffma2(pp3, va.y, acc2[25]);
                acc2[26] = ffma2(pp3, vb.x, acc2[26]);
                acc2[27] = ffma2(pp3, vb.y, acc2[27]);
                const ulonglong2* vr2 = (const ulonglong2*)(vs + j * 256 + cb * 16 + 8);
                ulonglong2 vc = vr2[0], vd = vr2[1];
                acc2[4]  = ffma2(pp0, vc.x, acc2[4]);
                acc2[5]  = ffma2(pp0, vc.y, acc2[5]);
                acc2[6]  = ffma2(pp0, vd.x, acc2[6]);
                acc2[7]  = ffma2(pp0, vd.y, acc2[7]);
                acc2[12] = ffma2(pp1, vc.x, acc2[12]);
                acc2[13] = ffma2(pp1, vc.y, acc2[13]);
                acc2[14] = ffma2(pp1, vd.x, acc2[14]);
                acc2[15] = ffma2(pp1, vd.y, acc2[15]);
                acc2[20] = ffma2(pp2, vc.x, acc2[20]);
                acc2[21] = ffma2(pp2, vc.y, acc2[21]);
                acc2[22] = ffma2(pp2, vd.x, acc2[22]);
                acc2[23] = ffma2(pp2, vd.y, acc2[23]);
                acc2[28] = ffma2(pp3, vc.x, acc2[28]);
                acc2[29] = ffma2(pp3, vc.y, acc2[29]);
                acc2[30] = ffma2(pp3, vd.x, acc2[30]);
                acc2[31] = ffma2(pp3, vd.y, acc2[31]);
            }
        }
    }
    __syncthreads();   // lrow final

    // ---- epilogue: out[b, c, n0+q] = acc/l + x, float4 over the 4 q's ----
    // acc2 layout: acc2[k*8 + cc] = (channel cb*16 + 2*cc, +1) — note cc order
    // above packs cc = {0,1,2,3} from va/vb and cc = {4,5,6,7} from vc/vd.
    float inv[4];
#pragma unroll
    for (int k = 0; k < 4; k++) inv[k] = 1.f / lrow[qb * 4 + k];

#pragma unroll
    for (int cc = 0; cc < 8; cc++) {
        float lo0, hi0, lo1, hi1, lo2, hi2, lo3, hi3;
        unpack2(acc2[0 * 8 + cc], lo0, hi0);
        unpack2(acc2[1 * 8 + cc], lo1, hi1);
        unpack2(acc2[2 * 8 + cc], lo2, hi2);
        unpack2(acc2[3 * 8 + cc], lo3, hi3);
        int c0 = cb * 16 + 2 * cc;
        {
            size_t base = ((size_t)b * CC + c0) * NN + n0 + qb * 4;
            float4 xr = *(const float4*)(x + base);
            float4 o;
            o.x = lo0 * inv[0] + xr.x;
            o.y = lo1 * inv[1] + xr.y;
            o.z = lo2 * inv[2] + xr.z;
            o.w = lo3 * inv[3] + xr.w;
            *(float4*)(out + base) = o;
        }
        {
            size_t base = ((size_t)b * CC + c0 + 1) * NN + n0 + qb * 4;
            float4 xr = *(const float4*)(x + base);
            float4 o;
            o.x = hi0 * inv[0] + xr.x;
            o.y = hi1 * inv[1] + xr.y;
            o.z = hi2 * inv[2] + xr.z;
            o.w = hi3 * inv[3] + xr.w;
            *(float4*)(out + base) = o;
        }
    }
}

// ---------------------------------------------------------------------------
extern "C" void kernel_launch(void* const* d_in, const int* in_sizes, int n_in,
                              void* d_out, int out_size)
{
    const float* x  = (const float*)d_in[0];
    const float* Wq = (const float*)d_in[1];
    const float* Wk = (const float*)d_in[2];
    const float* Wv = (const float*)d_in[3];
    float* out = (float*)d_out;

    float* qk_ptr = nullptr;
    float* v_ptr  = nullptr;
    cudaGetSymbolAddress((void**)&qk_ptr, g_qk);
    cudaGetSymbolAddress((void**)&v_ptr,  g_v);

    static const size_t attn_smem =
        (size_t)(64 * QS_LD + 64 * 32 + 64 * SS_LD + 64 * 256 + 4 * 64 + 2 * 256)
        * sizeof(float);   // 102656 B
    cudaFuncSetAttribute(attn_kernel,
                         cudaFuncAttributeMaxDynamicSharedMemorySize,
                         (int)attn_smem);

    proj_kernel<true ><<<dim3(NN / 64, 1, BB), 256>>>(x, Wq, Wk, qk_ptr, 64);
    proj_kernel<false><<<dim3(NN / 64, CC / 64, BB), 256>>>(x, Wv, nullptr, v_ptr, CC);
    attn_kernel<<<dim3(NN / 64, 1, BB), 256, attn_smem>>>(x, out);
}

// round 5
// speedup vs baseline: 4.4183x; 4.4183x over previous
#include <cuda_runtime.h>
#include <cuda_fp16.h>
#include <math.h>
#include <stdint.h>

#define BB 4
#define CC 256
#define NN 4096

typedef unsigned long long ull;

// ---------------- scratch (__device__ globals; no allocs allowed) ----------
__device__ float  g_qk[(size_t)BB * NN * 64];        // [b][n][0:32]=q,[32:64]=k (4 MB)
__device__ __half g_p [(size_t)BB * NN * NN];        // [b][q][j] p=exp(s-m)/l (128 MB)
__device__ __half g_vh[(size_t)BB * CC * NN];        // [b][c][j] fp16 V        (8 MB)

// ---------------- helpers ---------------------------------------------------
__device__ __forceinline__ uint32_t smem_u32(const void* p) {
    uint32_t a;
    asm("{ .reg .u64 t; cvta.to.shared.u64 t, %1; cvt.u32.u64 %0, t; }"
        : "=r"(a) : "l"(p));
    return a;
}
__device__ __forceinline__ void cp16(uint32_t dst, const void* src) {
    asm volatile("cp.async.cg.shared.global [%0], [%1], 16;" :: "r"(dst), "l"(src)
                 : "memory");
}
// SW128-swizzled address of 16B unit u in 128B row `row` (u,row&7 XOR trick)
__device__ __forceinline__ uint32_t swaddr(uint32_t base, int row, int u) {
    return base + row * 128 + (((u) ^ (row & 7)) << 4);
}
__device__ __forceinline__ void ldm_x4(uint32_t& r0, uint32_t& r1,
                                       uint32_t& r2, uint32_t& r3, uint32_t a) {
    asm volatile("ldmatrix.sync.aligned.m8n8.x4.shared.b16 {%0,%1,%2,%3}, [%4];"
                 : "=r"(r0), "=r"(r1), "=r"(r2), "=r"(r3) : "r"(a));
}
__device__ __forceinline__ void mma16816(float* d, const uint32_t* a,
                                         uint32_t b0, uint32_t b1) {
    asm volatile(
        "mma.sync.aligned.m16n8k16.row.col.f32.f16.f16.f32 "
        "{%0,%1,%2,%3}, {%4,%5,%6,%7}, {%8,%9}, {%0,%1,%2,%3};"
        : "+f"(d[0]), "+f"(d[1]), "+f"(d[2]), "+f"(d[3])
        : "r"(a[0]), "r"(a[1]), "r"(a[2]), "r"(a[3]), "r"(b0), "r"(b1));
}
__device__ __forceinline__ ull ffma2_(ull a, ull b, ull c) {
    ull d; asm("fma.rn.f32x2 %0, %1, %2, %3;" : "=l"(d) : "l"(a), "l"(b), "l"(c));
    return d;
}
__device__ __forceinline__ uint32_t pkh2(float a, float b) {
    __half2 h = __floats2half2_rn(a, b);
    return *reinterpret_cast<uint32_t*>(&h);
}

// ---------------------------------------------------------------------------
// proj_qk: q||k [b][n][64] fp32   (proven)
// ---------------------------------------------------------------------------
__global__ __launch_bounds__(256) void proj_qk_kernel(
    const float* __restrict__ x, const float* __restrict__ Wq,
    const float* __restrict__ Wk, float* __restrict__ out)
{
    const int b = blockIdx.z, n0 = blockIdx.x * 64;
    const int tid = threadIdx.x, tx = tid & 15, ty = tid >> 4;
    __shared__ float xs[16][64];
    __shared__ float ws[64][17];
    float acc[4][4];
#pragma unroll
    for (int i = 0; i < 4; i++)
#pragma unroll
        for (int j = 0; j < 4; j++) acc[i][j] = 0.f;
    const float* xb = x + (size_t)b * CC * NN;
    for (int c0 = 0; c0 < CC; c0 += 16) {
#pragma unroll
        for (int i = 0; i < 4; i++) {
            int e = tid + i * 256, cc = e >> 6, nn = e & 63;
            xs[cc][nn] = xb[(size_t)(c0 + cc) * NN + n0 + nn];
        }
#pragma unroll
        for (int i = 0; i < 4; i++) {
            int e = tid + i * 256, o = e >> 4, cc = e & 15;
            ws[o][cc] = (o < 32) ? Wq[o * CC + c0 + cc] : Wk[(o - 32) * CC + c0 + cc];
        }
        __syncthreads();
#pragma unroll
        for (int cc = 0; cc < 16; cc++) {
            float a[4], w[4];
#pragma unroll
            for (int i = 0; i < 4; i++) a[i] = xs[cc][tx * 4 + i];
#pragma unroll
            for (int j = 0; j < 4; j++) w[j] = ws[ty * 4 + j][cc];
#pragma unroll
            for (int i = 0; i < 4; i++)
#pragma unroll
                for (int j = 0; j < 4; j++) acc[i][j] = fmaf(a[i], w[j], acc[i][j]);
        }
        __syncthreads();
    }
#pragma unroll
    for (int i = 0; i < 4; i++)
#pragma unroll
        for (int j = 0; j < 4; j++)
            out[((size_t)b * NN + n0 + tx * 4 + i) * 64 + ty * 4 + j] = acc[i][j];
}

// ---------------------------------------------------------------------------
// proj_v: v fp16 [b][c][n]  (row=c, K-major over n -> B operand for mma)
// ---------------------------------------------------------------------------
__global__ __launch_bounds__(256) void proj_v_kernel(
    const float* __restrict__ x, const float* __restrict__ Wv,
    __half* __restrict__ vout)
{
    const int b = blockIdx.z, n0 = blockIdx.x * 64, o0 = blockIdx.y * 64;
    const int tid = threadIdx.x, tx = tid & 15, ty = tid >> 4;
    __shared__ float xs[16][64];
    __shared__ float ws[64][17];
    float acc[4][4];
#pragma unroll
    for (int i = 0; i < 4; i++)
#pragma unroll
        for (int j = 0; j < 4; j++) acc[i][j] = 0.f;
    const float* xb = x + (size_t)b * CC * NN;
    for (int c0 = 0; c0 < CC; c0 += 16) {
#pragma unroll
        for (int i = 0; i < 4; i++) {
            int e = tid + i * 256, cc = e >> 6, nn = e & 63;
            xs[cc][nn] = xb[(size_t)(c0 + cc) * NN + n0 + nn];
        }
#pragma unroll
        for (int i = 0; i < 4; i++) {
            int e = tid + i * 256, o = e >> 4, cc = e & 15;
            ws[o][cc] = Wv[(o0 + o) * CC + c0 + cc];
        }
        __syncthreads();
#pragma unroll
        for (int cc = 0; cc < 16; cc++) {
            float a[4], w[4];
#pragma unroll
            for (int i = 0; i < 4; i++) a[i] = xs[cc][tx * 4 + i];
#pragma unroll
            for (int j = 0; j < 4; j++) w[j] = ws[ty * 4 + j][cc];
#pragma unroll
            for (int i = 0; i < 4; i++)
#pragma unroll
                for (int j = 0; j < 4; j++) acc[i][j] = fmaf(a[i], w[j], acc[i][j]);
        }
        __syncthreads();
    }
#pragma unroll
    for (int i = 0; i < 4; i++)
#pragma unroll
        for (int j = 0; j < 4; j++)
            vout[((size_t)b * CC + o0 + ty * 4 + j) * NN + n0 + tx * 4 + i] =
                __float2half_rn(acc[i][j]);
}

// ---------------------------------------------------------------------------
// softmax: per CTA 64 q-rows. Pass A: online (m,l). Pass B: write P fp16.
// ---------------------------------------------------------------------------
__global__ __launch_bounds__(256) void softmax_kernel()
{
    __shared__ float ks[64 * 32];
    __shared__ float pms[256], pls[256];
    __shared__ float mrow[64], rrow[64];

    const int b = blockIdx.y, n0 = blockIdx.x * 64;
    const int tid = threadIdx.x, qi = tid & 63, g = tid >> 6;

    ull q2[16];
    {
        const ulonglong2* qsrc =
            (const ulonglong2*)(g_qk + ((size_t)b * NN + n0 + qi) * 64);
#pragma unroll
        for (int i = 0; i < 8; i++) {
            ulonglong2 v = qsrc[i];
            q2[2 * i] = v.x; q2[2 * i + 1] = v.y;
        }
    }

    float M = -1e30f, L = 0.f;
    for (int m0 = 0; m0 < NN; m0 += 64) {
        __syncthreads();
        const float* kbase = g_qk + ((size_t)b * NN + m0) * 64 + 32;
#pragma unroll
        for (int i = 0; i < 2; i++) {
            int e = tid + i * 256, j = e >> 3, d4 = e & 7;
            *(float4*)(ks + j * 32 + d4 * 4) =
                *(const float4*)(kbase + (size_t)j * 64 + d4 * 4);
        }
        __syncthreads();

        float s[16], tmax = -1e30f;
#pragma unroll
        for (int jj = 0; jj < 16; jj++) {
            const ulonglong2* kr = (const ulonglong2*)(ks + (g * 16 + jj) * 32);
            ull s2 = 0ULL;
#pragma unroll
            for (int i = 0; i < 8; i++) {
                ulonglong2 kv = kr[i];
                s2 = ffma2_(q2[2 * i],     kv.x, s2);
                s2 = ffma2_(q2[2 * i + 1], kv.y, s2);
            }
            float lo, hi;
            asm("mov.b64 {%0, %1}, %2;" : "=f"(lo), "=f"(hi) : "l"(s2));
            s[jj] = lo + hi;
            tmax = fmaxf(tmax, s[jj]);
        }
        float mn = fmaxf(M, tmax);
        float sum = 0.f;
#pragma unroll
        for (int jj = 0; jj < 16; jj++) sum += __expf(s[jj] - mn);
        L = L * __expf(M - mn) + sum;
        M = mn;
    }
    pms[g * 64 + qi] = M;
    pls[g * 64 + qi] = L;
    __syncthreads();
    if (tid < 64) {
        float a = pms[tid], bq = pms[64 + tid], c = pms[128 + tid], d = pms[192 + tid];
        float m = fmaxf(fmaxf(a, bq), fmaxf(c, d));
        float l = pls[tid] * __expf(a - m) + pls[64 + tid] * __expf(bq - m)
                + pls[128 + tid] * __expf(c - m) + pls[192 + tid] * __expf(d - m);
        mrow[tid] = m;
        rrow[tid] = 1.f / l;
    }
    __syncthreads();
    const float m = mrow[qi], r = rrow[qi];
    __half* prow = g_p + ((size_t)b * NN + n0 + qi) * NN;

    for (int m0 = 0; m0 < NN; m0 += 64) {
        __syncthreads();
        const float* kbase = g_qk + ((size_t)b * NN + m0) * 64 + 32;
#pragma unroll
        for (int i = 0; i < 2; i++) {
            int e = tid + i * 256, j = e >> 3, d4 = e & 7;
            *(float4*)(ks + j * 32 + d4 * 4) =
                *(const float4*)(kbase + (size_t)j * 64 + d4 * 4);
        }
        __syncthreads();

        float p[16];
#pragma unroll
        for (int jj = 0; jj < 16; jj++) {
            const ulonglong2* kr = (const ulonglong2*)(ks + (g * 16 + jj) * 32);
            ull s2 = 0ULL;
#pragma unroll
            for (int i = 0; i < 8; i++) {
                ulonglong2 kv = kr[i];
                s2 = ffma2_(q2[2 * i],     kv.x, s2);
                s2 = ffma2_(q2[2 * i + 1], kv.y, s2);
            }
            float lo, hi;
            asm("mov.b64 {%0, %1}, %2;" : "=f"(lo), "=f"(hi) : "l"(s2));
            p[jj] = __expf((lo + hi) - m) * r;
        }
        uint4 v0 = make_uint4(pkh2(p[0], p[1]),  pkh2(p[2], p[3]),
                              pkh2(p[4], p[5]),  pkh2(p[6], p[7]));
        uint4 v1 = make_uint4(pkh2(p[8], p[9]),  pkh2(p[10], p[11]),
                              pkh2(p[12], p[13]), pkh2(p[14], p[15]));
        uint4* dst = (uint4*)(prow + m0 + g * 16);
        dst[0] = v0; dst[1] = v1;
    }
}

// ---------------------------------------------------------------------------
// pv: D[128q,128c] per CTA = P[q,:] x V[c,:]^T via mma.sync m16n8k16 fp16.
// 8 warps (2q x 4c), warp tile 64q x 32c. K-chunks 64, cp.async double buffer.
// SW128-swizzled smem rows (128B), ldmatrix.x4 loads. Epilogue adds residual.
// ---------------------------------------------------------------------------
#define PV_STAGE 32768   // A: 128*128B  + B: 128*128B
#define PV_SMEM  (2 * PV_STAGE + 256)

__device__ __forceinline__ void pv_load_chunk(uint32_t sbase, int stage,
                                              int b, int q0, int c0, int ch, int tid)
{
    uint32_t ab = sbase + stage * PV_STAGE;
    uint32_t bb = ab + 16384;
    const int j0 = ch * 64;
    const __half* psrc = g_p + ((size_t)b * NN + q0) * NN + j0;
#pragma unroll
    for (int rr = 0; rr < 4; rr++) {
        int e = tid + rr * 256, row = e >> 3, u = e & 7;
        cp16(swaddr(ab, row, u), psrc + (size_t)row * NN + u * 8);
    }
    const __half* vsrc = g_vh + ((size_t)b * CC + c0) * NN + j0;
#pragma unroll
    for (int rr = 0; rr < 4; rr++) {
        int e = tid + rr * 256, row = e >> 3, u = e & 7;
        cp16(swaddr(bb, row, u), vsrc + (size_t)row * NN + u * 8);
    }
    asm volatile("cp.async.commit_group;" ::: "memory");
}

__global__ __launch_bounds__(256) void pv_kernel(
    const float* __restrict__ x, float* __restrict__ out)
{
    extern __shared__ char dsm[];
    const int b = blockIdx.z, q0 = blockIdx.x * 128, c0 = blockIdx.y * 128;
    const int tid = threadIdx.x, wid = tid >> 5, lane = tid & 31;
    const int wq = wid >> 2;          // 0..1  -> q offset wq*64
    const int wc = wid & 3;           // 0..3  -> c offset wc*32
    const uint32_t sbase = (smem_u32(dsm) + 127) & ~127u;

    float acc[4][4][4];
#pragma unroll
    for (int i = 0; i < 4; i++)
#pragma unroll
        for (int j = 0; j < 4; j++)
#pragma unroll
            for (int k = 0; k < 4; k++) acc[i][j][k] = 0.f;

    // ldmatrix lane-role constants
    const int a_row = wq * 64 + (lane & 15);            // + qt*16
    const int a_uo  = lane >> 4;                        // + ks*2
    const int b_row = wc * 32 + (lane & 7) + ((lane >> 4) << 3);  // + nt2*16
    const int b_uo  = (lane >> 3) & 1;                  // + ks*2

    pv_load_chunk(sbase, 0, b, q0, c0, 0, tid);

    const int NCH = NN / 64;   // 64
    for (int i = 0; i < NCH; i++) {
        if (i + 1 < NCH) {
            pv_load_chunk(sbase, (i + 1) & 1, b, q0, c0, i + 1, tid);
            asm volatile("cp.async.wait_group 1;" ::: "memory");
        } else {
            asm volatile("cp.async.wait_group 0;" ::: "memory");
        }
        __syncthreads();

        uint32_t ab = sbase + (i & 1) * PV_STAGE;
        uint32_t bb = ab + 16384;
#pragma unroll
        for (int ks = 0; ks < 4; ks++) {
            uint32_t a[4][4];
#pragma unroll
            for (int qt = 0; qt < 4; qt++)
                ldm_x4(a[qt][0], a[qt][1], a[qt][2], a[qt][3],
                       swaddr(ab, a_row + qt * 16, a_uo + ks * 2));
            uint32_t bfr[4][2];
#pragma unroll
            for (int nt2 = 0; nt2 < 2; nt2++) {
                uint32_t r0, r1, r2, r3;
                ldm_x4(r0, r1, r2, r3,
                       swaddr(bb, b_row + nt2 * 16, b_uo + ks * 2));
                bfr[nt2 * 2][0] = r0;     bfr[nt2 * 2][1] = r1;
                bfr[nt2 * 2 + 1][0] = r2; bfr[nt2 * 2 + 1][1] = r3;
            }
#pragma unroll
            for (int qt = 0; qt < 4; qt++)
#pragma unroll
                for (int nt = 0; nt < 4; nt++)
                    mma16816(acc[qt][nt], a[qt], bfr[nt][0], bfr[nt][1]);
        }
        __syncthreads();
    }

    // epilogue: out[b][c][q] = acc + x  (D frag: r0=(q,c) r1=(q,c+1) r2=(q+8,c) r3)
#pragma unroll
    for (int qt = 0; qt < 4; qt++) {
#pragma unroll
        for (int nt = 0; nt < 4; nt++) {
            int q = q0 + wq * 64 + qt * 16 + (lane >> 2);
            int c = c0 + wc * 32 + nt * 8 + 2 * (lane & 3);
            size_t i00 = ((size_t)b * CC + c) * NN + q;
            out[i00]            = acc[qt][nt][0] + x[i00];
            out[i00 + NN]       = acc[qt][nt][1] + x[i00 + NN];
            out[i00 + 8]        = acc[qt][nt][2] + x[i00 + 8];
            out[i00 + NN + 8]   = acc[qt][nt][3] + x[i00 + NN + 8];
        }
    }
}

// ---------------------------------------------------------------------------
extern "C" void kernel_launch(void* const* d_in, const int* in_sizes, int n_in,
                              void* d_out, int out_size)
{
    const float* x  = (const float*)d_in[0];
    const float* Wq = (const float*)d_in[1];
    const float* Wk = (const float*)d_in[2];
    const float* Wv = (const float*)d_in[3];
    float* out = (float*)d_out;

    float*  qk_ptr = nullptr;
    __half* vh_ptr = nullptr;
    cudaGetSymbolAddress((void**)&qk_ptr, g_qk);
    cudaGetSymbolAddress((void**)&vh_ptr, g_vh);

    cudaFuncSetAttribute(pv_kernel,
                         cudaFuncAttributeMaxDynamicSharedMemorySize, PV_SMEM);

    proj_qk_kernel<<<dim3(NN / 64, 1, BB), 256>>>(x, Wq, Wk, qk_ptr);
    proj_v_kernel <<<dim3(NN / 64, CC / 64, BB), 256>>>(x, Wv, vh_ptr);
    softmax_kernel<<<dim3(NN / 64, BB), 256>>>();
    pv_kernel     <<<dim3(NN / 128, CC / 128, BB), 256, PV_SMEM>>>(x, out);
}

// round 6
// speedup vs baseline: 7.5214x; 1.7023x over previous
#include <cuda_runtime.h>
#include <cuda_fp16.h>
#include <math.h>
#include <stdint.h>

#define BB 4
#define CC 256
#define NN 4096

typedef unsigned long long ull;

// ---------------- scratch (__device__ globals; no allocs allowed) ----------
__device__ __half g_qh[(size_t)BB * NN * 64];   // [b][n][32 q_hi | 32 q_lo] (2 MB)
__device__ __half g_kh[(size_t)BB * NN * 64];   // [b][n][32 k_hi | 32 k_lo] (2 MB)
__device__ __half g_p [(size_t)BB * NN * NN];   // [b][q][j] p (128 MB)
__device__ __half g_vh[(size_t)BB * CC * NN];   // [b][c][j] fp16 V (8 MB)

// ---------------- helpers ---------------------------------------------------
__device__ __forceinline__ uint32_t smem_u32(const void* p) {
    uint32_t a;
    asm("{ .reg .u64 t; cvta.to.shared.u64 t, %1; cvt.u32.u64 %0, t; }"
        : "=r"(a) : "l"(p));
    return a;
}
__device__ __forceinline__ void cp16(uint32_t dst, const void* src) {
    asm volatile("cp.async.cg.shared.global [%0], [%1], 16;" :: "r"(dst), "l"(src)
                 : "memory");
}
__device__ __forceinline__ uint32_t swaddr(uint32_t base, int row, int u) {
    return base + row * 128 + (((u) ^ (row & 7)) << 4);
}
__device__ __forceinline__ void ldm_x4(uint32_t& r0, uint32_t& r1,
                                       uint32_t& r2, uint32_t& r3, uint32_t a) {
    asm volatile("ldmatrix.sync.aligned.m8n8.x4.shared.b16 {%0,%1,%2,%3}, [%4];"
                 : "=r"(r0), "=r"(r1), "=r"(r2), "=r"(r3) : "r"(a));
}
__device__ __forceinline__ void mma16816(float* d, const uint32_t* a,
                                         uint32_t b0, uint32_t b1) {
    asm volatile(
        "mma.sync.aligned.m16n8k16.row.col.f32.f16.f16.f32 "
        "{%0,%1,%2,%3}, {%4,%5,%6,%7}, {%8,%9}, {%0,%1,%2,%3};"
        : "+f"(d[0]), "+f"(d[1]), "+f"(d[2]), "+f"(d[3])
        : "r"(a[0]), "r"(a[1]), "r"(a[2]), "r"(a[3]), "r"(b0), "r"(b1));
}
__device__ __forceinline__ uint32_t pkh2(float a, float b) {
    __half2 h = __floats2half2_rn(a, b);
    return *reinterpret_cast<uint32_t*>(&h);
}

// ---------------------------------------------------------------------------
// proj_qk: q,k as split fp16 hi|lo rows [b][n][64]
// ---------------------------------------------------------------------------
__global__ __launch_bounds__(256) void proj_qk_kernel(
    const float* __restrict__ x, const float* __restrict__ Wq,
    const float* __restrict__ Wk)
{
    const int b = blockIdx.z, n0 = blockIdx.x * 64;
    const int tid = threadIdx.x, tx = tid & 15, ty = tid >> 4;
    __shared__ float xs[16][64];
    __shared__ float ws[64][17];
    float acc[4][4];
#pragma unroll
    for (int i = 0; i < 4; i++)
#pragma unroll
        for (int j = 0; j < 4; j++) acc[i][j] = 0.f;
    const float* xb = x + (size_t)b * CC * NN;
    for (int c0 = 0; c0 < CC; c0 += 16) {
#pragma unroll
        for (int i = 0; i < 4; i++) {
            int e = tid + i * 256, cc = e >> 6, nn = e & 63;
            xs[cc][nn] = xb[(size_t)(c0 + cc) * NN + n0 + nn];
        }
#pragma unroll
        for (int i = 0; i < 4; i++) {
            int e = tid + i * 256, o = e >> 4, cc = e & 15;
            ws[o][cc] = (o < 32) ? Wq[o * CC + c0 + cc] : Wk[(o - 32) * CC + c0 + cc];
        }
        __syncthreads();
#pragma unroll
        for (int cc = 0; cc < 16; cc++) {
            float a[4], w[4];
#pragma unroll
            for (int i = 0; i < 4; i++) a[i] = xs[cc][tx * 4 + i];
#pragma unroll
            for (int j = 0; j < 4; j++) w[j] = ws[ty * 4 + j][cc];
#pragma unroll
            for (int i = 0; i < 4; i++)
#pragma unroll
                for (int j = 0; j < 4; j++) acc[i][j] = fmaf(a[i], w[j], acc[i][j]);
        }
        __syncthreads();
    }
#pragma unroll
    for (int i = 0; i < 4; i++) {
        int n = n0 + tx * 4 + i;
        size_t base = ((size_t)b * NN + n) * 64;
#pragma unroll
        for (int j = 0; j < 4; j++) {
            int o = ty * 4 + j;
            float a = acc[i][j];
            __half hi = __float2half_rn(a);
            __half lo = __float2half_rn(a - __half2float(hi));
            if (o < 32) { g_qh[base + o]  = hi; g_qh[base + 32 + o] = lo; }
            else        { g_kh[base + o - 32] = hi; g_kh[base + o]  = lo; }
        }
    }
}

// ---------------------------------------------------------------------------
// proj_v: v fp16 [b][c][n]
// ---------------------------------------------------------------------------
__global__ __launch_bounds__(256) void proj_v_kernel(
    const float* __restrict__ x, const float* __restrict__ Wv,
    __half* __restrict__ vout)
{
    const int b = blockIdx.z, n0 = blockIdx.x * 64, o0 = blockIdx.y * 64;
    const int tid = threadIdx.x, tx = tid & 15, ty = tid >> 4;
    __shared__ float xs[16][64];
    __shared__ float ws[64][17];
    float acc[4][4];
#pragma unroll
    for (int i = 0; i < 4; i++)
#pragma unroll
        for (int j = 0; j < 4; j++) acc[i][j] = 0.f;
    const float* xb = x + (size_t)b * CC * NN;
    for (int c0 = 0; c0 < CC; c0 += 16) {
#pragma unroll
        for (int i = 0; i < 4; i++) {
            int e = tid + i * 256, cc = e >> 6, nn = e & 63;
            xs[cc][nn] = xb[(size_t)(c0 + cc) * NN + n0 + nn];
        }
#pragma unroll
        for (int i = 0; i < 4; i++) {
            int e = tid + i * 256, o = e >> 4, cc = e & 15;
            ws[o][cc] = Wv[(o0 + o) * CC + c0 + cc];
        }
        __syncthreads();
#pragma unroll
        for (int cc = 0; cc < 16; cc++) {
            float a[4], w[4];
#pragma unroll
            for (int i = 0; i < 4; i++) a[i] = xs[cc][tx * 4 + i];
#pragma unroll
            for (int j = 0; j < 4; j++) w[j] = ws[ty * 4 + j][cc];
#pragma unroll
            for (int i = 0; i < 4; i++)
#pragma unroll
                for (int j = 0; j < 4; j++) acc[i][j] = fmaf(a[i], w[j], acc[i][j]);
        }
        __syncthreads();
    }
#pragma unroll
    for (int i = 0; i < 4; i++)
#pragma unroll
        for (int j = 0; j < 4; j++)
            vout[((size_t)b * CC + o0 + ty * 4 + j) * NN + n0 + tx * 4 + i] =
                __float2half_rn(acc[i][j]);
}

// ---------------------------------------------------------------------------
// s_softmax: S = QK^T via split-fp16 mma (3 cross terms), two passes:
//   pass 1 -> online row (m, l);  pass 2 -> P = exp(s-m)/l fp16 to g_p.
// CTA: 128 q rows, 8 warps = 4q x 2j, warp tile 32q x 64j per 128-j tile.
// ---------------------------------------------------------------------------
#define S_SMEM (3 * 16384 + 128)

__device__ __forceinline__ void load_k_tile(uint32_t kb, int b, int jt, int tid)
{
    const __half* ksrc = g_kh + ((size_t)b * NN + jt * 128) * 64;
#pragma unroll
    for (int rr = 0; rr < 4; rr++) {
        int e = tid + rr * 256, row = e >> 3, u = e & 7;
        cp16(swaddr(kb, row, u), ksrc + (size_t)row * 64 + u * 8);
    }
    asm volatile("cp.async.commit_group;" ::: "memory");
}

__device__ __forceinline__ void s_tile(uint32_t qb, uint32_t kb,
                                       int wq, int wj, int lane,
                                       float acc[2][8][4])
{
#pragma unroll
    for (int i = 0; i < 2; i++)
#pragma unroll
        for (int j = 0; j < 8; j++)
#pragma unroll
            for (int k = 0; k < 4; k++) acc[i][j][k] = 0.f;

    const int arow = wq * 32 + (lane & 15);
    const int au   = lane >> 4;
    const int brow = wj * 64 + (lane & 7) + ((lane >> 4) << 3);
    const int bu   = (lane >> 3) & 1;
    const int pa[3] = {0, 0, 4};   // A part unit base (hi, hi, lo)
    const int pb[3] = {0, 4, 0};   // B part unit base (hi, lo, hi)

#pragma unroll
    for (int part = 0; part < 3; part++) {
#pragma unroll
        for (int ks = 0; ks < 2; ks++) {
            uint32_t a[2][4];
#pragma unroll
            for (int qt = 0; qt < 2; qt++)
                ldm_x4(a[qt][0], a[qt][1], a[qt][2], a[qt][3],
                       swaddr(qb, arow + qt * 16, pa[part] + ks * 2 + au));
            uint32_t bf[8][2];
#pragma unroll
            for (int ntp = 0; ntp < 4; ntp++) {
                uint32_t r0, r1, r2, r3;
                ldm_x4(r0, r1, r2, r3,
                       swaddr(kb, brow + ntp * 16, pb[part] + ks * 2 + bu));
                bf[ntp * 2][0] = r0;     bf[ntp * 2][1] = r1;
                bf[ntp * 2 + 1][0] = r2; bf[ntp * 2 + 1][1] = r3;
            }
#pragma unroll
            for (int qt = 0; qt < 2; qt++)
#pragma unroll
                for (int nt = 0; nt < 8; nt++)
                    mma16816(acc[qt][nt], a[qt], bf[nt][0], bf[nt][1]);
        }
    }
}

__global__ __launch_bounds__(256) void s_softmax_kernel()
{
    extern __shared__ char dsm[];
    __shared__ float sM[2][128], sL[2][128], mfin[128], rfin[128];

    const int b = blockIdx.y, q0 = blockIdx.x * 128;
    const int tid = threadIdx.x, wid = tid >> 5, lane = tid & 31;
    const int wq = wid >> 1, wj = wid & 1;
    const uint32_t qb  = (smem_u32(dsm) + 127) & ~127u;
    const uint32_t kb0 = qb + 16384;
    const uint32_t kb1 = kb0 + 16384;

    // stage Q tile (persistent)
    {
        const __half* qsrc = g_qh + ((size_t)b * NN + q0) * 64;
#pragma unroll
        for (int rr = 0; rr < 4; rr++) {
            int e = tid + rr * 256, row = e >> 3, u = e & 7;
            cp16(swaddr(qb, row, u), qsrc + (size_t)row * 64 + u * 8);
        }
        asm volatile("cp.async.commit_group;" ::: "memory");
    }

    float M[4], L[4];
#pragma unroll
    for (int i = 0; i < 4; i++) { M[i] = -1e30f; L[i] = 0.f; }

    const int NT = NN / 128;   // 32

    // ---------------- pass 1: stats ----------------
    load_k_tile(kb0, b, 0, tid);
    for (int jt = 0; jt < NT; jt++) {
        uint32_t kb = (jt & 1) ? kb1 : kb0;
        if (jt + 1 < NT) {
            load_k_tile((jt & 1) ? kb0 : kb1, b, jt + 1, tid);
            asm volatile("cp.async.wait_group 1;" ::: "memory");
        } else {
            asm volatile("cp.async.wait_group 0;" ::: "memory");
        }
        __syncthreads();

        float acc[2][8][4];
        s_tile(qb, kb, wq, wj, lane, acc);

#pragma unroll
        for (int qt = 0; qt < 2; qt++)
#pragma unroll
            for (int h = 0; h < 2; h++) {
                int i = qt * 2 + h;
                float tmax = -1e30f;
#pragma unroll
                for (int nt = 0; nt < 8; nt++)
                    tmax = fmaxf(tmax, fmaxf(acc[qt][nt][2 * h],
                                             acc[qt][nt][2 * h + 1]));
                float mn = fmaxf(M[i], tmax);
                float s = 0.f;
#pragma unroll
                for (int nt = 0; nt < 8; nt++)
                    s += __expf(acc[qt][nt][2 * h] - mn)
                       + __expf(acc[qt][nt][2 * h + 1] - mn);
                L[i] = L[i] * __expf(M[i] - mn) + s;
                M[i] = mn;
            }
        __syncthreads();
    }

    // reduce within row quad (lanes 4r..4r+3 share rows)
#pragma unroll
    for (int i = 0; i < 4; i++) {
#pragma unroll
        for (int off = 1; off <= 2; off <<= 1) {
            float mo = __shfl_xor_sync(0xffffffffu, M[i], off);
            float lo = __shfl_xor_sync(0xffffffffu, L[i], off);
            float mn = fmaxf(M[i], mo);
            L[i] = L[i] * __expf(M[i] - mn) + lo * __expf(mo - mn);
            M[i] = mn;
        }
    }
    if ((lane & 3) == 0) {
#pragma unroll
        for (int i = 0; i < 4; i++) {
            int r = wq * 32 + i * 8 + (lane >> 2);
            sM[wj][r] = M[i];
            sL[wj][r] = L[i];
        }
    }
    __syncthreads();
    if (tid < 128) {
        float m0 = sM[0][tid], m1 = sM[1][tid];
        float m = fmaxf(m0, m1);
        float l = sL[0][tid] * __expf(m0 - m) + sL[1][tid] * __expf(m1 - m);
        mfin[tid] = m;
        rfin[tid] = 1.f / l;
    }
    __syncthreads();

    float mf[4], rf[4];
#pragma unroll
    for (int i = 0; i < 4; i++) {
        int r = wq * 32 + i * 8 + (lane >> 2);
        mf[i] = mfin[r];
        rf[i] = rfin[r];
    }

    // ---------------- pass 2: write P ----------------
    load_k_tile(kb0, b, 0, tid);
    for (int jt = 0; jt < NT; jt++) {
        uint32_t kb = (jt & 1) ? kb1 : kb0;
        if (jt + 1 < NT) {
            load_k_tile((jt & 1) ? kb0 : kb1, b, jt + 1, tid);
            asm volatile("cp.async.wait_group 1;" ::: "memory");
        } else {
            asm volatile("cp.async.wait_group 0;" ::: "memory");
        }
        __syncthreads();

        float acc[2][8][4];
        s_tile(qb, kb, wq, wj, lane, acc);

#pragma unroll
        for (int qt = 0; qt < 2; qt++)
#pragma unroll
            for (int h = 0; h < 2; h++) {
                int i = qt * 2 + h;
                int q = q0 + wq * 32 + qt * 16 + h * 8 + (lane >> 2);
                __half* prow = g_p + ((size_t)b * NN + q) * NN
                             + jt * 128 + wj * 64 + 2 * (lane & 3);
#pragma unroll
                for (int nt = 0; nt < 8; nt++) {
                    float p0 = __expf(acc[qt][nt][2 * h]     - mf[i]) * rf[i];
                    float p1 = __expf(acc[qt][nt][2 * h + 1] - mf[i]) * rf[i];
                    *(uint32_t*)(prow + nt * 8) = pkh2(p0, p1);
                }
            }
        __syncthreads();
    }
}

// ---------------------------------------------------------------------------
// pv: D[128q,128c] per CTA = P x V^T via mma.sync m16n8k16 (proven round 5)
// ---------------------------------------------------------------------------
#define PV_STAGE 32768
#define PV_SMEM  (2 * PV_STAGE + 256)

__device__ __forceinline__ void pv_load_chunk(uint32_t sbase, int stage,
                                              int b, int q0, int c0, int ch, int tid)
{
    uint32_t ab = sbase + stage * PV_STAGE;
    uint32_t bb = ab + 16384;
    const int j0 = ch * 64;
    const __half* psrc = g_p + ((size_t)b * NN + q0) * NN + j0;
#pragma unroll
    for (int rr = 0; rr < 4; rr++) {
        int e = tid + rr * 256, row = e >> 3, u = e & 7;
        cp16(swaddr(ab, row, u), psrc + (size_t)row * NN + u * 8);
    }
    const __half* vsrc = g_vh + ((size_t)b * CC + c0) * NN + j0;
#pragma unroll
    for (int rr = 0; rr < 4; rr++) {
        int e = tid + rr * 256, row = e >> 3, u = e & 7;
        cp16(swaddr(bb, row, u), vsrc + (size_t)row * NN + u * 8);
    }
    asm volatile("cp.async.commit_group;" ::: "memory");
}

__global__ __launch_bounds__(256) void pv_kernel(
    const float* __restrict__ x, float* __restrict__ out)
{
    extern __shared__ char dsm[];
    const int b = blockIdx.z, q0 = blockIdx.x * 128, c0 = blockIdx.y * 128;
    const int tid = threadIdx.x, wid = tid >> 5, lane = tid & 31;
    const int wq = wid >> 2;
    const int wc = wid & 3;
    const uint32_t sbase = (smem_u32(dsm) + 127) & ~127u;

    float acc[4][4][4];
#pragma unroll
    for (int i = 0; i < 4; i++)
#pragma unroll
        for (int j = 0; j < 4; j++)
#pragma unroll
            for (int k = 0; k < 4; k++) acc[i][j][k] = 0.f;

    const int a_row = wq * 64 + (lane & 15);
    const int a_uo  = lane >> 4;
    const int b_row = wc * 32 + (lane & 7) + ((lane >> 4) << 3);
    const int b_uo  = (lane >> 3) & 1;

    pv_load_chunk(sbase, 0, b, q0, c0, 0, tid);

    const int NCH = NN / 64;
    for (int i = 0; i < NCH; i++) {
        if (i + 1 < NCH) {
            pv_load_chunk(sbase, (i + 1) & 1, b, q0, c0, i + 1, tid);
            asm volatile("cp.async.wait_group 1;" ::: "memory");
        } else {
            asm volatile("cp.async.wait_group 0;" ::: "memory");
        }
        __syncthreads();

        uint32_t ab = sbase + (i & 1) * PV_STAGE;
        uint32_t bb = ab + 16384;
#pragma unroll
        for (int ks = 0; ks < 4; ks++) {
            uint32_t a[4][4];
#pragma unroll
            for (int qt = 0; qt < 4; qt++)
                ldm_x4(a[qt][0], a[qt][1], a[qt][2], a[qt][3],
                       swaddr(ab, a_row + qt * 16, a_uo + ks * 2));
            uint32_t bfr[4][2];
#pragma unroll
            for (int nt2 = 0; nt2 < 2; nt2++) {
                uint32_t r0, r1, r2, r3;
                ldm_x4(r0, r1, r2, r3,
                       swaddr(bb, b_row + nt2 * 16, b_uo + ks * 2));
                bfr[nt2 * 2][0] = r0;     bfr[nt2 * 2][1] = r1;
                bfr[nt2 * 2 + 1][0] = r2; bfr[nt2 * 2 + 1][1] = r3;
            }
#pragma unroll
            for (int qt = 0; qt < 4; qt++)
#pragma unroll
                for (int nt = 0; nt < 4; nt++)
                    mma16816(acc[qt][nt], a[qt], bfr[nt][0], bfr[nt][1]);
        }
        __syncthreads();
    }

#pragma unroll
    for (int qt = 0; qt < 4; qt++) {
#pragma unroll
        for (int nt = 0; nt < 4; nt++) {
            int q = q0 + wq * 64 + qt * 16 + (lane >> 2);
            int c = c0 + wc * 32 + nt * 8 + 2 * (lane & 3);
            size_t i00 = ((size_t)b * CC + c) * NN + q;
            out[i00]          = acc[qt][nt][0] + x[i00];
            out[i00 + NN]     = acc[qt][nt][1] + x[i00 + NN];
            out[i00 + 8]      = acc[qt][nt][2] + x[i00 + 8];
            out[i00 + NN + 8] = acc[qt][nt][3] + x[i00 + NN + 8];
        }
    }
}

// ---------------------------------------------------------------------------
extern "C" void kernel_launch(void* const* d_in, const int* in_sizes, int n_in,
                              void* d_out, int out_size)
{
    const float* x  = (const float*)d_in[0];
    const float* Wq = (const float*)d_in[1];
    const float* Wk = (const float*)d_in[2];
    const float* Wv = (const float*)d_in[3];
    float* out = (float*)d_out;

    __half* vh_ptr = nullptr;
    cudaGetSymbolAddress((void**)&vh_ptr, g_vh);

    cudaFuncSetAttribute(pv_kernel,
                         cudaFuncAttributeMaxDynamicSharedMemorySize, PV_SMEM);
    cudaFuncSetAttribute(s_softmax_kernel,
                         cudaFuncAttributeMaxDynamicSharedMemorySize, S_SMEM);

    proj_qk_kernel  <<<dim3(NN / 64, 1, BB), 256>>>(x, Wq, Wk);
    proj_v_kernel   <<<dim3(NN / 64, CC / 64, BB), 256>>>(x, Wv, vh_ptr);
    s_softmax_kernel<<<dim3(NN / 128, BB), 256, S_SMEM>>>();
    pv_kernel       <<<dim3(NN / 128, CC / 128, BB), 256, PV_SMEM>>>(x, out);
}

// round 8
// speedup vs baseline: 7.7908x; 1.0358x over previous
#include <cuda_runtime.h>
#include <cuda_fp16.h>
#include <math.h>
#include <stdint.h>

#define BB 4
#define CC 256
#define NN 4096

typedef unsigned long long ull;

// ---------------- scratch (__device__ globals; no allocs allowed) ----------
__device__ __half g_qh[(size_t)BB * NN * 64];   // [b][n][32 q_hi | 32 q_lo] (2 MB)
__device__ __half g_kh[(size_t)BB * NN * 64];   // [b][n][32 k_hi | 32 k_lo] (2 MB)
__device__ __half g_p [(size_t)BB * NN * NN];   // [b][q][j] p (128 MB)
__device__ __half g_vh[(size_t)BB * CC * NN];   // [b][c][j] fp16 V (8 MB)
__device__ __half g_wvh[CC * CC];               // Wv hi (128 KB)
__device__ __half g_wvl[CC * CC];               // Wv lo (128 KB)

// ---------------- helpers ---------------------------------------------------
__device__ __forceinline__ uint32_t smem_u32(const void* p) {
    uint32_t a;
    asm("{ .reg .u64 t; cvta.to.shared.u64 t, %1; cvt.u32.u64 %0, t; }"
        : "=r"(a) : "l"(p));
    return a;
}
__device__ __forceinline__ void cp16(uint32_t dst, const void* src) {
    asm volatile("cp.async.cg.shared.global [%0], [%1], 16;" :: "r"(dst), "l"(src)
                 : "memory");
}
__device__ __forceinline__ void sts16(uint32_t a, __half v) {
    unsigned short u = *reinterpret_cast<unsigned short*>(&v);
    asm volatile("st.shared.u16 [%0], %1;" :: "r"(a), "h"(u) : "memory");
}
__device__ __forceinline__ uint32_t swaddr(uint32_t base, int row, int u) {
    return base + row * 128 + (((u) ^ (row & 7)) << 4);
}
__device__ __forceinline__ void ldm_x4(uint32_t& r0, uint32_t& r1,
                                       uint32_t& r2, uint32_t& r3, uint32_t a) {
    asm volatile("ldmatrix.sync.aligned.m8n8.x4.shared.b16 {%0,%1,%2,%3}, [%4];"
                 : "=r"(r0), "=r"(r1), "=r"(r2), "=r"(r3) : "r"(a));
}
__device__ __forceinline__ void mma16816(float* d, const uint32_t* a,
                                         uint32_t b0, uint32_t b1) {
    asm volatile(
        "mma.sync.aligned.m16n8k16.row.col.f32.f16.f16.f32 "
        "{%0,%1,%2,%3}, {%4,%5,%6,%7}, {%8,%9}, {%0,%1,%2,%3};"
        : "+f"(d[0]), "+f"(d[1]), "+f"(d[2]), "+f"(d[3])
        : "r"(a[0]), "r"(a[1]), "r"(a[2]), "r"(a[3]), "r"(b0), "r"(b1));
}
__device__ __forceinline__ uint32_t pkh2(float a, float b) {
    __half2 h = __floats2half2_rn(a, b);
    return *reinterpret_cast<uint32_t*>(&h);
}

// ---------------------------------------------------------------------------
// wsplit: Wv fp32 -> hi/lo fp16 (elementwise)
// ---------------------------------------------------------------------------
__global__ __launch_bounds__(256) void wsplit_kernel(const float* __restrict__ Wv)
{
    int e4 = blockIdx.x * 256 + threadIdx.x;   // 16384 float4 groups
    float4 v = ((const float4*)Wv)[e4];
    int base = e4 * 4;
    float f[4] = {v.x, v.y, v.z, v.w};
#pragma unroll
    for (int t = 0; t < 4; t++) {
        __half hi = __float2half_rn(f[t]);
        __half lo = __float2half_rn(f[t] - __half2float(hi));
        g_wvh[base + t] = hi;
        g_wvl[base + t] = lo;
    }
}

// ---------------------------------------------------------------------------
// proj_qk: q,k as split fp16 hi|lo rows [b][n][64]  (proven)
// ---------------------------------------------------------------------------
__global__ __launch_bounds__(256) void proj_qk_kernel(
    const float* __restrict__ x, const float* __restrict__ Wq,
    const float* __restrict__ Wk)
{
    const int b = blockIdx.z, n0 = blockIdx.x * 64;
    const int tid = threadIdx.x, tx = tid & 15, ty = tid >> 4;
    __shared__ float xs[16][64];
    __shared__ float ws[64][17];
    float acc[4][4];
#pragma unroll
    for (int i = 0; i < 4; i++)
#pragma unroll
        for (int j = 0; j < 4; j++) acc[i][j] = 0.f;
    const float* xb = x + (size_t)b * CC * NN;
    for (int c0 = 0; c0 < CC; c0 += 16) {
#pragma unroll
        for (int i = 0; i < 4; i++) {
            int e = tid + i * 256, cc = e >> 6, nn = e & 63;
            xs[cc][nn] = xb[(size_t)(c0 + cc) * NN + n0 + nn];
        }
#pragma unroll
        for (int i = 0; i < 4; i++) {
            int e = tid + i * 256, o = e >> 4, cc = e & 15;
            ws[o][cc] = (o < 32) ? Wq[o * CC + c0 + cc] : Wk[(o - 32) * CC + c0 + cc];
        }
        __syncthreads();
#pragma unroll
        for (int cc = 0; cc < 16; cc++) {
            float a[4], w[4];
#pragma unroll
            for (int i = 0; i < 4; i++) a[i] = xs[cc][tx * 4 + i];
#pragma unroll
            for (int j = 0; j < 4; j++) w[j] = ws[ty * 4 + j][cc];
#pragma unroll
            for (int i = 0; i < 4; i++)
#pragma unroll
                for (int j = 0; j < 4; j++) acc[i][j] = fmaf(a[i], w[j], acc[i][j]);
        }
        __syncthreads();
    }
#pragma unroll
    for (int i = 0; i < 4; i++) {
        int n = n0 + tx * 4 + i;
        size_t base = ((size_t)b * NN + n) * 64;
#pragma unroll
        for (int j = 0; j < 4; j++) {
            int o = ty * 4 + j;
            float a = acc[i][j];
            __half hi = __float2half_rn(a);
            __half lo = __float2half_rn(a - __half2float(hi));
            if (o < 32) { g_qh[base + o]  = hi; g_qh[base + 32 + o] = lo; }
            else        { g_kh[base + o - 32] = hi; g_kh[base + o]  = lo; }
        }
    }
}

// ---------------------------------------------------------------------------
// proj_v_mma: V[c, n] = Wv x via split-fp16 mma (Wh*xh + Wl*xh + Wh*xl).
// CTA 128c x 128n, K = 256 in 4 chunks of 64. x transposed+split into smem.
// ---------------------------------------------------------------------------
#define PVW_SMEM (4 * 16384 + 256)

__global__ __launch_bounds__(256) void proj_v_mma_kernel(
    const float* __restrict__ x)
{
    extern __shared__ char dsm[];
    const int b = blockIdx.z, n0 = blockIdx.x * 128, c0 = blockIdx.y * 128;
    const int tid = threadIdx.x, wid = tid >> 5, lane = tid & 31;
    const int wcc = wid >> 2, wn = wid & 3;
    const uint32_t whb = (smem_u32(dsm) + 127) & ~127u;
    const uint32_t wlb = whb + 16384;
    const uint32_t xhb = wlb + 16384;
    const uint32_t xlb = xhb + 16384;

    float acc[4][4][4];
#pragma unroll
    for (int i = 0; i < 4; i++)
#pragma unroll
        for (int j = 0; j < 4; j++)
#pragma unroll
            for (int k = 0; k < 4; k++) acc[i][j][k] = 0.f;

    const int a_row = wcc * 64 + (lane & 15);
    const int a_uo  = lane >> 4;
    const int b_row = wn * 32 + (lane & 7) + ((lane >> 4) << 3);
    const int b_uo  = (lane >> 3) & 1;

    for (int kc = 0; kc < 4; kc++) {
        __syncthreads();   // previous chunk fully consumed
        // stage W tiles (hi & lo) via cp.async, then commit the group
#pragma unroll
        for (int i = 0; i < 4; i++) {
            int e = tid + i * 256, row = e >> 3, u = e & 7;
            const __half* sh = g_wvh + (size_t)(c0 + row) * CC + kc * 64 + u * 8;
            const __half* sl = g_wvl + (size_t)(c0 + row) * CC + kc * 64 + u * 8;
            cp16(swaddr(whb, row, u), sh);
            cp16(swaddr(wlb, row, u), sl);
        }
        asm volatile("cp.async.commit_group;" ::: "memory");

        // stage x chunk: read fp32 [k][n] coalesced, split, store fp16 [n][k]
        // (st.shared — swaddr values are shared-window addresses)
#pragma unroll
        for (int i = 0; i < 8; i++) {
            int e = tid + i * 256;            // 0..2047
            int k = e >> 5, n4 = (e & 31) * 4;
            const float* src = x + ((size_t)b * CC + kc * 64 + k) * NN + n0 + n4;
            float4 v = *(const float4*)src;
            float f[4] = {v.x, v.y, v.z, v.w};
            uint32_t ucol = (uint32_t)(k >> 3);
            uint32_t boff = (uint32_t)(k & 7) * 2;
#pragma unroll
            for (int t = 0; t < 4; t++) {
                __half hi = __float2half_rn(f[t]);
                __half lo = __float2half_rn(f[t] - __half2float(hi));
                sts16(swaddr(xhb, n4 + t, ucol) + boff, hi);
                sts16(swaddr(xlb, n4 + t, ucol) + boff, lo);
            }
        }
        asm volatile("cp.async.wait_group 0;" ::: "memory");
        __syncthreads();

#pragma unroll
        for (int ks = 0; ks < 4; ks++) {
            uint32_t ah[4][4], al[4][4];
#pragma unroll
            for (int qt = 0; qt < 4; qt++) {
                ldm_x4(ah[qt][0], ah[qt][1], ah[qt][2], ah[qt][3],
                       swaddr(whb, a_row + qt * 16, a_uo + ks * 2));
                ldm_x4(al[qt][0], al[qt][1], al[qt][2], al[qt][3],
                       swaddr(wlb, a_row + qt * 16, a_uo + ks * 2));
            }
            uint32_t bh[4][2], bl[4][2];
#pragma unroll
            for (int nt2 = 0; nt2 < 2; nt2++) {
                uint32_t r0, r1, r2, r3;
                ldm_x4(r0, r1, r2, r3,
                       swaddr(xhb, b_row + nt2 * 16, b_uo + ks * 2));
                bh[nt2 * 2][0] = r0;     bh[nt2 * 2][1] = r1;
                bh[nt2 * 2 + 1][0] = r2; bh[nt2 * 2 + 1][1] = r3;
                ldm_x4(r0, r1, r2, r3,
                       swaddr(xlb, b_row + nt2 * 16, b_uo + ks * 2));
                bl[nt2 * 2][0] = r0;     bl[nt2 * 2][1] = r1;
                bl[nt2 * 2 + 1][0] = r2; bl[nt2 * 2 + 1][1] = r3;
            }
#pragma unroll
            for (int qt = 0; qt < 4; qt++)
#pragma unroll
                for (int nt = 0; nt < 4; nt++) {
                    mma16816(acc[qt][nt], ah[qt], bh[nt][0], bh[nt][1]);
                    mma16816(acc[qt][nt], al[qt], bh[nt][0], bh[nt][1]);
                    mma16816(acc[qt][nt], ah[qt], bl[nt][0], bl[nt][1]);
                }
        }
    }

    // epilogue: g_vh[b][c][n] fp16 (pairs of n are 4B-aligned)
#pragma unroll
    for (int qt = 0; qt < 4; qt++)
#pragma unroll
        for (int nt = 0; nt < 4; nt++) {
            int c = c0 + wcc * 64 + qt * 16 + (lane >> 2);
            int n = n0 + wn * 32 + nt * 8 + 2 * (lane & 3);
            *(uint32_t*)(g_vh + ((size_t)b * CC + c) * NN + n) =
                pkh2(acc[qt][nt][0], acc[qt][nt][1]);
            *(uint32_t*)(g_vh + ((size_t)b * CC + c + 8) * NN + n) =
                pkh2(acc[qt][nt][2], acc[qt][nt][3]);
        }
}

// ---------------------------------------------------------------------------
// s_softmax: S = QK^T via split-fp16 mma (3 cross terms), two passes (proven)
// ---------------------------------------------------------------------------
#define S_SMEM (3 * 16384 + 128)

__device__ __forceinline__ void load_k_tile(uint32_t kb, int b, int jt, int tid)
{
    const __half* ksrc = g_kh + ((size_t)b * NN + jt * 128) * 64;
#pragma unroll
    for (int rr = 0; rr < 4; rr++) {
        int e = tid + rr * 256, row = e >> 3, u = e & 7;
        cp16(swaddr(kb, row, u), ksrc + (size_t)row * 64 + u * 8);
    }
    asm volatile("cp.async.commit_group;" ::: "memory");
}

__device__ __forceinline__ void s_tile(uint32_t qb, uint32_t kb,
                                       int wq, int wj, int lane,
                                       float acc[2][8][4])
{
#pragma unroll
    for (int i = 0; i < 2; i++)
#pragma unroll
        for (int j = 0; j < 8; j++)
#pragma unroll
            for (int k = 0; k < 4; k++) acc[i][j][k] = 0.f;

    const int arow = wq * 32 + (lane & 15);
    const int au   = lane >> 4;
    const int brow = wj * 64 + (lane & 7) + ((lane >> 4) << 3);
    const int bu   = (lane >> 3) & 1;
    const int pa[3] = {0, 0, 4};
    const int pb[3] = {0, 4, 0};

#pragma unroll
    for (int part = 0; part < 3; part++) {
#pragma unroll
        for (int ks = 0; ks < 2; ks++) {
            uint32_t a[2][4];
#pragma unroll
            for (int qt = 0; qt < 2; qt++)
                ldm_x4(a[qt][0], a[qt][1], a[qt][2], a[qt][3],
                       swaddr(qb, arow + qt * 16, pa[part] + ks * 2 + au));
            uint32_t bf[8][2];
#pragma unroll
            for (int ntp = 0; ntp < 4; ntp++) {
                uint32_t r0, r1, r2, r3;
                ldm_x4(r0, r1, r2, r3,
                       swaddr(kb, brow + ntp * 16, pb[part] + ks * 2 + bu));
                bf[ntp * 2][0] = r0;     bf[ntp * 2][1] = r1;
                bf[ntp * 2 + 1][0] = r2; bf[ntp * 2 + 1][1] = r3;
            }
#pragma unroll
            for (int qt = 0; qt < 2; qt++)
#pragma unroll
                for (int nt = 0; nt < 8; nt++)
                    mma16816(acc[qt][nt], a[qt], bf[nt][0], bf[nt][1]);
        }
    }
}

__global__ __launch_bounds__(256) void s_softmax_kernel()
{
    extern __shared__ char dsm[];
    __shared__ float sM[2][128], sL[2][128], mfin[128], rfin[128];

    const int b = blockIdx.y, q0 = blockIdx.x * 128;
    const int tid = threadIdx.x, wid = tid >> 5, lane = tid & 31;
    const int wq = wid >> 1, wj = wid & 1;
    const uint32_t qb  = (smem_u32(dsm) + 127) & ~127u;
    const uint32_t kb0 = qb + 16384;
    const uint32_t kb1 = kb0 + 16384;

    {
        const __half* qsrc = g_qh + ((size_t)b * NN + q0) * 64;
#pragma unroll
        for (int rr = 0; rr < 4; rr++) {
            int e = tid + rr * 256, row = e >> 3, u = e & 7;
            cp16(swaddr(qb, row, u), qsrc + (size_t)row * 64 + u * 8);
        }
        asm volatile("cp.async.commit_group;" ::: "memory");
    }

    float M[4], L[4];
#pragma unroll
    for (int i = 0; i < 4; i++) { M[i] = -1e30f; L[i] = 0.f; }

    const int NT = NN / 128;

    load_k_tile(kb0, b, 0, tid);
    for (int jt = 0; jt < NT; jt++) {
        uint32_t kb = (jt & 1) ? kb1 : kb0;
        if (jt + 1 < NT) {
            load_k_tile((jt & 1) ? kb0 : kb1, b, jt + 1, tid);
            asm volatile("cp.async.wait_group 1;" ::: "memory");
        } else {
            asm volatile("cp.async.wait_group 0;" ::: "memory");
        }
        __syncthreads();

        float acc[2][8][4];
        s_tile(qb, kb, wq, wj, lane, acc);

#pragma unroll
        for (int qt = 0; qt < 2; qt++)
#pragma unroll
            for (int h = 0; h < 2; h++) {
                int i = qt * 2 + h;
                float tmax = -1e30f;
#pragma unroll
                for (int nt = 0; nt < 8; nt++)
                    tmax = fmaxf(tmax, fmaxf(acc[qt][nt][2 * h],
                                             acc[qt][nt][2 * h + 1]));
                float mn = fmaxf(M[i], tmax);
                float s = 0.f;
#pragma unroll
                for (int nt = 0; nt < 8; nt++)
                    s += __expf(acc[qt][nt][2 * h] - mn)
                       + __expf(acc[qt][nt][2 * h + 1] - mn);
                L[i] = L[i] * __expf(M[i] - mn) + s;
                M[i] = mn;
            }
        __syncthreads();
    }

#pragma unroll
    for (int i = 0; i < 4; i++) {
#pragma unroll
        for (int off = 1; off <= 2; off <<= 1) {
            float mo = __shfl_xor_sync(0xffffffffu, M[i], off);
            float lo = __shfl_xor_sync(0xffffffffu, L[i], off);
            float mn = fmaxf(M[i], mo);
            L[i] = L[i] * __expf(M[i] - mn) + lo * __expf(mo - mn);
            M[i] = mn;
        }
    }
    if ((lane & 3) == 0) {
#pragma unroll
        for (int i = 0; i < 4; i++) {
            int r = wq * 32 + i * 8 + (lane >> 2);
            sM[wj][r] = M[i];
            sL[wj][r] = L[i];
        }
    }
    __syncthreads();
    if (tid < 128) {
        float m0 = sM[0][tid], m1 = sM[1][tid];
        float m = fmaxf(m0, m1);
        float l = sL[0][tid] * __expf(m0 - m) + sL[1][tid] * __expf(m1 - m);
        mfin[tid] = m;
        rfin[tid] = 1.f / l;
    }
    __syncthreads();

    float mf[4], rf[4];
#pragma unroll
    for (int i = 0; i < 4; i++) {
        int r = wq * 32 + i * 8 + (lane >> 2);
        mf[i] = mfin[r];
        rf[i] = rfin[r];
    }

    load_k_tile(kb0, b, 0, tid);
    for (int jt = 0; jt < NT; jt++) {
        uint32_t kb = (jt & 1) ? kb1 : kb0;
        if (jt + 1 < NT) {
            load_k_tile((jt & 1) ? kb0 : kb1, b, jt + 1, tid);
            asm volatile("cp.async.wait_group 1;" ::: "memory");
        } else {
            asm volatile("cp.async.wait_group 0;" ::: "memory");
        }
        __syncthreads();

        float acc[2][8][4];
        s_tile(qb, kb, wq, wj, lane, acc);

#pragma unroll
        for (int qt = 0; qt < 2; qt++)
#pragma unroll
            for (int h = 0; h < 2; h++) {
                int i = qt * 2 + h;
                int q = q0 + wq * 32 + qt * 16 + h * 8 + (lane >> 2);
                __half* prow = g_p + ((size_t)b * NN + q) * NN
                             + jt * 128 + wj * 64 + 2 * (lane & 3);
#pragma unroll
                for (int nt = 0; nt < 8; nt++) {
                    float p0 = __expf(acc[qt][nt][2 * h]     - mf[i]) * rf[i];
                    float p1 = __expf(acc[qt][nt][2 * h + 1] - mf[i]) * rf[i];
                    *(uint32_t*)(prow + nt * 8) = pkh2(p0, p1);
                }
            }
        __syncthreads();
    }
}

// ---------------------------------------------------------------------------
// pv: D[128q,128c] per CTA = P x V^T via mma.sync (proven round 5)
// ---------------------------------------------------------------------------
#define PV_STAGE 32768
#define PV_SMEM  (2 * PV_STAGE + 256)

__device__ __forceinline__ void pv_load_chunk(uint32_t sbase, int stage,
                                              int b, int q0, int c0, int ch, int tid)
{
    uint32_t ab = sbase + stage * PV_STAGE;
    uint32_t bb = ab + 16384;
    const int j0 = ch * 64;
    const __half* psrc = g_p + ((size_t)b * NN + q0) * NN + j0;
#pragma unroll
    for (int rr = 0; rr < 4; rr++) {
        int e = tid + rr * 256, row = e >> 3, u = e & 7;
        cp16(swaddr(ab, row, u), psrc + (size_t)row * NN + u * 8);
    }
    const __half* vsrc = g_vh + ((size_t)b * CC + c0) * NN + j0;
#pragma unroll
    for (int rr = 0; rr < 4; rr++) {
        int e = tid + rr * 256, row = e >> 3, u = e & 7;
        cp16(swaddr(bb, row, u), vsrc + (size_t)row * NN + u * 8);
    }
    asm volatile("cp.async.commit_group;" ::: "memory");
}

__global__ __launch_bounds__(256) void pv_kernel(
    const float* __restrict__ x, float* __restrict__ out)
{
    extern __shared__ char dsm[];
    const int b = blockIdx.z, q0 = blockIdx.x * 128, c0 = blockIdx.y * 128;
    const int tid = threadIdx.x, wid = tid >> 5, lane = tid & 31;
    const int wq = wid >> 2;
    const int wc = wid & 3;
    const uint32_t sbase = (smem_u32(dsm) + 127) & ~127u;

    float acc[4][4][4];
#pragma unroll
    for (int i = 0; i < 4; i++)
#pragma unroll
        for (int j = 0; j < 4; j++)
#pragma unroll
            for (int k = 0; k < 4; k++) acc[i][j][k] = 0.f;

    const int a_row = wq * 64 + (lane & 15);
    const int a_uo  = lane >> 4;
    const int b_row = wc * 32 + (lane & 7) + ((lane >> 4) << 3);
    const int b_uo  = (lane >> 3) & 1;

    pv_load_chunk(sbase, 0, b, q0, c0, 0, tid);

    const int NCH = NN / 64;
    for (int i = 0; i < NCH; i++) {
        if (i + 1 < NCH) {
            pv_load_chunk(sbase, (i + 1) & 1, b, q0, c0, i + 1, tid);
            asm volatile("cp.async.wait_group 1;" ::: "memory");
        } else {
            asm volatile("cp.async.wait_group 0;" ::: "memory");
        }
        __syncthreads();

        uint32_t ab = sbase + (i & 1) * PV_STAGE;
        uint32_t bb = ab + 16384;
#pragma unroll
        for (int ks = 0; ks < 4; ks++) {
            uint32_t a[4][4];
#pragma unroll
            for (int qt = 0; qt < 4; qt++)
                ldm_x4(a[qt][0], a[qt][1], a[qt][2], a[qt][3],
                       swaddr(ab, a_row + qt * 16, a_uo + ks * 2));
            uint32_t bfr[4][2];
#pragma unroll
            for (int nt2 = 0; nt2 < 2; nt2++) {
                uint32_t r0, r1, r2, r3;
                ldm_x4(r0, r1, r2, r3,
                       swaddr(bb, b_row + nt2 * 16, b_uo + ks * 2));
                bfr[nt2 * 2][0] = r0;     bfr[nt2 * 2][1] = r1;
                bfr[nt2 * 2 + 1][0] = r2; bfr[nt2 * 2 + 1][1] = r3;
            }
#pragma unroll
            for (int qt = 0; qt < 4; qt++)
#pragma unroll
                for (int nt = 0; nt < 4; nt++)
                    mma16816(acc[qt][nt], a[qt], bfr[nt][0], bfr[nt][1]);
        }
        __syncthreads();
    }

#pragma unroll
    for (int qt = 0; qt < 4; qt++) {
#pragma unroll
        for (int nt = 0; nt < 4; nt++) {
            int q = q0 + wq * 64 + qt * 16 + (lane >> 2);
            int c = c0 + wc * 32 + nt * 8 + 2 * (lane & 3);
            size_t i00 = ((size_t)b * CC + c) * NN + q;
            out[i00]          = acc[qt][nt][0] + x[i00];
            out[i00 + NN]     = acc[qt][nt][1] + x[i00 + NN];
            out[i00 + 8]      = acc[qt][nt][2] + x[i00 + 8];
            out[i00 + NN + 8] = acc[qt][nt][3] + x[i00 + NN + 8];
        }
    }
}

// ---------------------------------------------------------------------------
extern "C" void kernel_launch(void* const* d_in, const int* in_sizes, int n_in,
                              void* d_out, int out_size)
{
    const float* x  = (const float*)d_in[0];
    const float* Wq = (const float*)d_in[1];
    const float* Wk = (const float*)d_in[2];
    const float* Wv = (const float*)d_in[3];
    float* out = (float*)d_out;

    cudaFuncSetAttribute(pv_kernel,
                         cudaFuncAttributeMaxDynamicSharedMemorySize, PV_SMEM);
    cudaFuncSetAttribute(s_softmax_kernel,
                         cudaFuncAttributeMaxDynamicSharedMemorySize, S_SMEM);
    cudaFuncSetAttribute(proj_v_mma_kernel,
                         cudaFuncAttributeMaxDynamicSharedMemorySize, PVW_SMEM);

    wsplit_kernel    <<<64, 256>>>(Wv);
    proj_qk_kernel   <<<dim3(NN / 64, 1, BB), 256>>>(x, Wq, Wk);
    proj_v_mma_kernel<<<dim3(NN / 128, CC / 128, BB), 256, PVW_SMEM>>>(x);
    s_softmax_kernel <<<dim3(NN / 128, BB), 256, S_SMEM>>>();
    pv_kernel        <<<dim3(NN / 128, CC / 128, BB), 256, PV_SMEM>>>(x, out);
}

// round 9
// speedup vs baseline: 8.0187x; 1.0292x over previous
#include <cuda_runtime.h>
#include <cuda_fp16.h>
#include <math.h>
#include <stdint.h>

#define BB 4
#define CC 256
#define NN 4096

// ---------------- scratch (__device__ globals; no allocs allowed) ----------
__device__ __half g_qh[(size_t)BB * NN * 64];   // [b][n][32 q_hi | 32 q_lo] (2 MB)
__device__ __half g_kh[(size_t)BB * NN * 64];   // [b][n][32 k_hi | 32 k_lo] (2 MB)
__device__ __half g_vh[(size_t)BB * CC * NN];   // [b][c][j] fp16 V (8 MB)
__device__ __half g_wvh[CC * CC];               // Wv hi (128 KB)
__device__ __half g_wvl[CC * CC];               // Wv lo (128 KB)

// ---------------- helpers ---------------------------------------------------
__device__ __forceinline__ uint32_t smem_u32(const void* p) {
    uint32_t a;
    asm("{ .reg .u64 t; cvta.to.shared.u64 t, %1; cvt.u32.u64 %0, t; }"
        : "=r"(a) : "l"(p));
    return a;
}
__device__ __forceinline__ void cp16(uint32_t dst, const void* src) {
    asm volatile("cp.async.cg.shared.global [%0], [%1], 16;" :: "r"(dst), "l"(src)
                 : "memory");
}
__device__ __forceinline__ void sts16(uint32_t a, __half v) {
    unsigned short u = *reinterpret_cast<unsigned short*>(&v);
    asm volatile("st.shared.u16 [%0], %1;" :: "r"(a), "h"(u) : "memory");
}
__device__ __forceinline__ uint32_t swaddr(uint32_t base, int row, int u) {
    return base + row * 128 + (((u) ^ (row & 7)) << 4);
}
__device__ __forceinline__ void ldm_x4(uint32_t& r0, uint32_t& r1,
                                       uint32_t& r2, uint32_t& r3, uint32_t a) {
    asm volatile("ldmatrix.sync.aligned.m8n8.x4.shared.b16 {%0,%1,%2,%3}, [%4];"
                 : "=r"(r0), "=r"(r1), "=r"(r2), "=r"(r3) : "r"(a));
}
__device__ __forceinline__ void mma16816(float* d, const uint32_t* a,
                                         uint32_t b0, uint32_t b1) {
    asm volatile(
        "mma.sync.aligned.m16n8k16.row.col.f32.f16.f16.f32 "
        "{%0,%1,%2,%3}, {%4,%5,%6,%7}, {%8,%9}, {%0,%1,%2,%3};"
        : "+f"(d[0]), "+f"(d[1]), "+f"(d[2]), "+f"(d[3])
        : "r"(a[0]), "r"(a[1]), "r"(a[2]), "r"(a[3]), "r"(b0), "r"(b1));
}
__device__ __forceinline__ uint32_t pkh2(float a, float b) {
    __half2 h = __floats2half2_rn(a, b);
    return *reinterpret_cast<uint32_t*>(&h);
}

// ---------------------------------------------------------------------------
// wsplit: Wv fp32 -> hi/lo fp16 (elementwise)
// ---------------------------------------------------------------------------
__global__ __launch_bounds__(256) void wsplit_kernel(const float* __restrict__ Wv)
{
    int e4 = blockIdx.x * 256 + threadIdx.x;
    float4 v = ((const float4*)Wv)[e4];
    int base = e4 * 4;
    float f[4] = {v.x, v.y, v.z, v.w};
#pragma unroll
    for (int t = 0; t < 4; t++) {
        __half hi = __float2half_rn(f[t]);
        __half lo = __float2half_rn(f[t] - __half2float(hi));
        g_wvh[base + t] = hi;
        g_wvl[base + t] = lo;
    }
}

// ---------------------------------------------------------------------------
// proj_qk: q,k as split fp16 hi|lo rows [b][n][64]  (proven)
// ---------------------------------------------------------------------------
__global__ __launch_bounds__(256) void proj_qk_kernel(
    const float* __restrict__ x, const float* __restrict__ Wq,
    const float* __restrict__ Wk)
{
    const int b = blockIdx.z, n0 = blockIdx.x * 64;
    const int tid = threadIdx.x, tx = tid & 15, ty = tid >> 4;
    __shared__ float xs[16][64];
    __shared__ float ws[64][17];
    float acc[4][4];
#pragma unroll
    for (int i = 0; i < 4; i++)
#pragma unroll
        for (int j = 0; j < 4; j++) acc[i][j] = 0.f;
    const float* xb = x + (size_t)b * CC * NN;
    for (int c0 = 0; c0 < CC; c0 += 16) {
#pragma unroll
        for (int i = 0; i < 4; i++) {
            int e = tid + i * 256, cc = e >> 6, nn = e & 63;
            xs[cc][nn] = xb[(size_t)(c0 + cc) * NN + n0 + nn];
        }
#pragma unroll
        for (int i = 0; i < 4; i++) {
            int e = tid + i * 256, o = e >> 4, cc = e & 15;
            ws[o][cc] = (o < 32) ? Wq[o * CC + c0 + cc] : Wk[(o - 32) * CC + c0 + cc];
        }
        __syncthreads();
#pragma unroll
        for (int cc = 0; cc < 16; cc++) {
            float a[4], w[4];
#pragma unroll
            for (int i = 0; i < 4; i++) a[i] = xs[cc][tx * 4 + i];
#pragma unroll
            for (int j = 0; j < 4; j++) w[j] = ws[ty * 4 + j][cc];
#pragma unroll
            for (int i = 0; i < 4; i++)
#pragma unroll
                for (int j = 0; j < 4; j++) acc[i][j] = fmaf(a[i], w[j], acc[i][j]);
        }
        __syncthreads();
    }
#pragma unroll
    for (int i = 0; i < 4; i++) {
        int n = n0 + tx * 4 + i;
        size_t base = ((size_t)b * NN + n) * 64;
#pragma unroll
        for (int j = 0; j < 4; j++) {
            int o = ty * 4 + j;
            float a = acc[i][j];
            __half hi = __float2half_rn(a);
            __half lo = __float2half_rn(a - __half2float(hi));
            if (o < 32) { g_qh[base + o]  = hi; g_qh[base + 32 + o] = lo; }
            else        { g_kh[base + o - 32] = hi; g_kh[base + o]  = lo; }
        }
    }
}

// ---------------------------------------------------------------------------
// proj_v_mma: V[c, n] = Wv x via split-fp16 mma (proven round 8)
// ---------------------------------------------------------------------------
#define PVW_SMEM (4 * 16384 + 256)

__global__ __launch_bounds__(256) void proj_v_mma_kernel(
    const float* __restrict__ x)
{
    extern __shared__ char dsm[];
    const int b = blockIdx.z, n0 = blockIdx.x * 128, c0 = blockIdx.y * 128;
    const int tid = threadIdx.x, wid = tid >> 5, lane = tid & 31;
    const int wcc = wid >> 2, wn = wid & 3;
    const uint32_t whb = (smem_u32(dsm) + 127) & ~127u;
    const uint32_t wlb = whb + 16384;
    const uint32_t xhb = wlb + 16384;
    const uint32_t xlb = xhb + 16384;

    float acc[4][4][4];
#pragma unroll
    for (int i = 0; i < 4; i++)
#pragma unroll
        for (int j = 0; j < 4; j++)
#pragma unroll
            for (int k = 0; k < 4; k++) acc[i][j][k] = 0.f;

    const int a_row = wcc * 64 + (lane & 15);
    const int a_uo  = lane >> 4;
    const int b_row = wn * 32 + (lane & 7) + ((lane >> 4) << 3);
    const int b_uo  = (lane >> 3) & 1;

    for (int kc = 0; kc < 4; kc++) {
        __syncthreads();
#pragma unroll
        for (int i = 0; i < 4; i++) {
            int e = tid + i * 256, row = e >> 3, u = e & 7;
            const __half* sh = g_wvh + (size_t)(c0 + row) * CC + kc * 64 + u * 8;
            const __half* sl = g_wvl + (size_t)(c0 + row) * CC + kc * 64 + u * 8;
            cp16(swaddr(whb, row, u), sh);
            cp16(swaddr(wlb, row, u), sl);
        }
        asm volatile("cp.async.commit_group;" ::: "memory");

#pragma unroll
        for (int i = 0; i < 8; i++) {
            int e = tid + i * 256;
            int k = e >> 5, n4 = (e & 31) * 4;
            const float* src = x + ((size_t)b * CC + kc * 64 + k) * NN + n0 + n4;
            float4 v = *(const float4*)src;
            float f[4] = {v.x, v.y, v.z, v.w};
            uint32_t ucol = (uint32_t)(k >> 3);
            uint32_t boff = (uint32_t)(k & 7) * 2;
#pragma unroll
            for (int t = 0; t < 4; t++) {
                __half hi = __float2half_rn(f[t]);
                __half lo = __float2half_rn(f[t] - __half2float(hi));
                sts16(swaddr(xhb, n4 + t, ucol) + boff, hi);
                sts16(swaddr(xlb, n4 + t, ucol) + boff, lo);
            }
        }
        asm volatile("cp.async.wait_group 0;" ::: "memory");
        __syncthreads();

#pragma unroll
        for (int ks = 0; ks < 4; ks++) {
            uint32_t ah[4][4], al[4][4];
#pragma unroll
            for (int qt = 0; qt < 4; qt++) {
                ldm_x4(ah[qt][0], ah[qt][1], ah[qt][2], ah[qt][3],
                       swaddr(whb, a_row + qt * 16, a_uo + ks * 2));
                ldm_x4(al[qt][0], al[qt][1], al[qt][2], al[qt][3],
                       swaddr(wlb, a_row + qt * 16, a_uo + ks * 2));
            }
            uint32_t bh[4][2], bl[4][2];
#pragma unroll
            for (int nt2 = 0; nt2 < 2; nt2++) {
                uint32_t r0, r1, r2, r3;
                ldm_x4(r0, r1, r2, r3,
                       swaddr(xhb, b_row + nt2 * 16, b_uo + ks * 2));
                bh[nt2 * 2][0] = r0;     bh[nt2 * 2][1] = r1;
                bh[nt2 * 2 + 1][0] = r2; bh[nt2 * 2 + 1][1] = r3;
                ldm_x4(r0, r1, r2, r3,
                       swaddr(xlb, b_row + nt2 * 16, b_uo + ks * 2));
                bl[nt2 * 2][0] = r0;     bl[nt2 * 2][1] = r1;
                bl[nt2 * 2 + 1][0] = r2; bl[nt2 * 2 + 1][1] = r3;
            }
#pragma unroll
            for (int qt = 0; qt < 4; qt++)
#pragma unroll
                for (int nt = 0; nt < 4; nt++) {
                    mma16816(acc[qt][nt], ah[qt], bh[nt][0], bh[nt][1]);
                    mma16816(acc[qt][nt], al[qt], bh[nt][0], bh[nt][1]);
                    mma16816(acc[qt][nt], ah[qt], bl[nt][0], bl[nt][1]);
                }
        }
    }

#pragma unroll
    for (int qt = 0; qt < 4; qt++)
#pragma unroll
        for (int nt = 0; nt < 4; nt++) {
            int c = c0 + wcc * 64 + qt * 16 + (lane >> 2);
            int n = n0 + wn * 32 + nt * 8 + 2 * (lane & 3);
            *(uint32_t*)(g_vh + ((size_t)b * CC + c) * NN + n) =
                pkh2(acc[qt][nt][0], acc[qt][nt][1]);
            *(uint32_t*)(g_vh + ((size_t)b * CC + c + 8) * NN + n) =
                pkh2(acc[qt][nt][2], acc[qt][nt][3]);
        }
}

// ---------------------------------------------------------------------------
// fattn: fused flash attention + residual.
// Grid (32 q-tiles, 2 c-halves, 4 batches). CTA 256 thr, 8 warps.
// Warp w owns q rows [q0 + w*16, +16) x all 128 c of this c-half.
// Per 64-j tile: S (split-fp16, 3 terms, 48 mma) -> online softmax in regs
// -> P fragments in regs (D-frag == A-frag layout) -> PV (64 mma).
// ---------------------------------------------------------------------------
#define FA_SMEM (16384 + 2 * 24576 + 256)

__device__ __forceinline__ void fa_load_kv(uint32_t kbuf, uint32_t vbuf,
                                           int b, int c0, int jt, int tid)
{
    const __half* ksrc = g_kh + ((size_t)b * NN + jt * 64) * 64;
#pragma unroll
    for (int rr = 0; rr < 2; rr++) {
        int e = tid + rr * 256, row = e >> 3, u = e & 7;
        cp16(swaddr(kbuf, row, u), ksrc + (size_t)row * 64 + u * 8);
    }
    const __half* vsrc = g_vh + ((size_t)b * CC + c0) * NN + jt * 64;
#pragma unroll
    for (int rr = 0; rr < 4; rr++) {
        int e = tid + rr * 256, row = e >> 3, u = e & 7;
        cp16(swaddr(vbuf, row, u), vsrc + (size_t)row * NN + u * 8);
    }
    asm volatile("cp.async.commit_group;" ::: "memory");
}

__global__ __launch_bounds__(256) void fattn_kernel(
    const float* __restrict__ x, float* __restrict__ out)
{
    extern __shared__ char dsm[];
    const int b = blockIdx.z, q0 = blockIdx.x * 128, c0 = blockIdx.y * 128;
    const int tid = threadIdx.x, w = tid >> 5, lane = tid & 31;
    const uint32_t qb = (smem_u32(dsm) + 127) & ~127u;
    const uint32_t kbuf[2] = {qb + 16384, qb + 16384 + 24576};
    const uint32_t vbuf[2] = {qb + 16384 + 8192, qb + 16384 + 24576 + 8192};

    // stage Q tile [128 q][64 halves hi|lo]; first K/V shares the commit group
    {
        const __half* qsrc = g_qh + ((size_t)b * NN + q0) * 64;
#pragma unroll
        for (int rr = 0; rr < 4; rr++) {
            int e = tid + rr * 256, row = e >> 3, u = e & 7;
            cp16(swaddr(qb, row, u), qsrc + (size_t)row * 64 + u * 8);
        }
    }
    fa_load_kv(kbuf[0], vbuf[0], b, c0, 0, tid);

    float acc[16][4];
#pragma unroll
    for (int i = 0; i < 16; i++)
#pragma unroll
        for (int k = 0; k < 4; k++) acc[i][k] = 0.f;
    float M[2] = {-1e30f, -1e30f}, L[2] = {0.f, 0.f};

    const int arow = w * 16 + (lane & 15);
    const int au   = lane >> 4;
    const int brow = (lane & 7) + ((lane >> 4) << 3);
    const int bu   = (lane >> 3) & 1;
    const int vrow = brow, vu = bu;

    const int NTJ = NN / 64;   // 64
    for (int jt = 0; jt < NTJ; jt++) {
        if (jt + 1 < NTJ) {
            fa_load_kv(kbuf[(jt + 1) & 1], vbuf[(jt + 1) & 1], b, c0, jt + 1, tid);
            asm volatile("cp.async.wait_group 1;" ::: "memory");
        } else {
            asm volatile("cp.async.wait_group 0;" ::: "memory");
        }
        __syncthreads();

        const uint32_t kcur = kbuf[jt & 1], vcur = vbuf[jt & 1];

        // ---- S = Q K^T  (hi*hi + hi*lo + lo*hi) ----
        float s[8][4];
#pragma unroll
        for (int i = 0; i < 8; i++)
#pragma unroll
            for (int k = 0; k < 4; k++) s[i][k] = 0.f;
        const int poa[3] = {0, 0, 4}, pob[3] = {0, 4, 0};
#pragma unroll
        for (int part = 0; part < 3; part++)
#pragma unroll
            for (int ks = 0; ks < 2; ks++) {
                uint32_t a[4];
                ldm_x4(a[0], a[1], a[2], a[3],
                       swaddr(qb, arow, poa[part] + ks * 2 + au));
#pragma unroll
                for (int ntp = 0; ntp < 4; ntp++) {
                    uint32_t r0, r1, r2, r3;
                    ldm_x4(r0, r1, r2, r3,
                           swaddr(kcur, brow + ntp * 16, pob[part] + ks * 2 + bu));
                    mma16816(s[ntp * 2],     a, r0, r1);
                    mma16816(s[ntp * 2 + 1], a, r2, r3);
                }
            }

        // ---- online softmax in registers (rows lane>>2, lane>>2 + 8) ----
#pragma unroll
        for (int h = 0; h < 2; h++) {
            float tmax = -1e30f;
#pragma unroll
            for (int nt = 0; nt < 8; nt++)
                tmax = fmaxf(tmax, fmaxf(s[nt][2 * h], s[nt][2 * h + 1]));
            tmax = fmaxf(tmax, __shfl_xor_sync(0xffffffffu, tmax, 1));
            tmax = fmaxf(tmax, __shfl_xor_sync(0xffffffffu, tmax, 2));
            float mn = fmaxf(M[h], tmax);
            float corr = __expf(M[h] - mn);
            M[h] = mn;
            float lsum = 0.f;
#pragma unroll
            for (int nt = 0; nt < 8; nt++) {
                float p0 = __expf(s[nt][2 * h] - mn);
                float p1 = __expf(s[nt][2 * h + 1] - mn);
                s[nt][2 * h] = p0; s[nt][2 * h + 1] = p1;
                lsum += p0 + p1;
            }
            L[h] = L[h] * corr + lsum;
#pragma unroll
            for (int nt = 0; nt < 16; nt++) {
                acc[nt][2 * h]     *= corr;
                acc[nt][2 * h + 1] *= corr;
            }
        }

        // ---- P fragments (S D-frag layout == A-frag layout) ----
        uint32_t pa[4][4];
#pragma unroll
        for (int kt = 0; kt < 4; kt++) {
            pa[kt][0] = pkh2(s[2 * kt][0],     s[2 * kt][1]);
            pa[kt][1] = pkh2(s[2 * kt][2],     s[2 * kt][3]);
            pa[kt][2] = pkh2(s[2 * kt + 1][0], s[2 * kt + 1][1]);
            pa[kt][3] = pkh2(s[2 * kt + 1][2], s[2 * kt + 1][3]);
        }

        // ---- PV: acc += P x V^T ----
#pragma unroll
        for (int ks = 0; ks < 4; ks++)
#pragma unroll
            for (int nt2 = 0; nt2 < 8; nt2++) {
                uint32_t r0, r1, r2, r3;
                ldm_x4(r0, r1, r2, r3,
                       swaddr(vcur, vrow + nt2 * 16, vu + ks * 2));
                mma16816(acc[nt2 * 2],     pa[ks], r0, r1);
                mma16816(acc[nt2 * 2 + 1], pa[ks], r2, r3);
            }
        __syncthreads();
    }

    // ---- finalize: l across quad, normalize, add residual ----
#pragma unroll
    for (int h = 0; h < 2; h++) {
        L[h] += __shfl_xor_sync(0xffffffffu, L[h], 1);
        L[h] += __shfl_xor_sync(0xffffffffu, L[h], 2);
    }
    const float inv0 = 1.f / L[0], inv1 = 1.f / L[1];
    const int q = q0 + w * 16 + (lane >> 2);
#pragma unroll
    for (int nt = 0; nt < 16; nt++) {
        int c = c0 + nt * 8 + 2 * (lane & 3);
        size_t i00 = ((size_t)b * CC + c) * NN + q;
        out[i00]          = acc[nt][0] * inv0 + x[i00];
        out[i00 + NN]     = acc[nt][1] * inv0 + x[i00 + NN];
        out[i00 + 8]      = acc[nt][2] * inv1 + x[i00 + 8];
        out[i00 + NN + 8] = acc[nt][3] * inv1 + x[i00 + NN + 8];
    }
}

// ---------------------------------------------------------------------------
extern "C" void kernel_launch(void* const* d_in, const int* in_sizes, int n_in,
                              void* d_out, int out_size)
{
    const float* x  = (const float*)d_in[0];
    const float* Wq = (const float*)d_in[1];
    const float* Wk = (const float*)d_in[2];
    const float* Wv = (const float*)d_in[3];
    float* out = (float*)d_out;

    cudaFuncSetAttribute(fattn_kernel,
                         cudaFuncAttributeMaxDynamicSharedMemorySize, FA_SMEM);
    cudaFuncSetAttribute(proj_v_mma_kernel,
                         cudaFuncAttributeMaxDynamicSharedMemorySize, PVW_SMEM);

    wsplit_kernel    <<<64, 256>>>(Wv);
    proj_qk_kernel   <<<dim3(NN / 64, 1, BB), 256>>>(x, Wq, Wk);
    proj_v_mma_kernel<<<dim3(NN / 128, CC / 128, BB), 256, PVW_SMEM>>>(x);
    fattn_kernel     <<<dim3(NN / 128, CC / 128, BB), 256, FA_SMEM>>>(x, out);
}

// round 11
// speedup vs baseline: 8.7374x; 1.0896x over previous
#include <cuda_runtime.h>
#include <cuda_fp16.h>
#include <math.h>
#include <stdint.h>

#define BB 4
#define CC 256
#define NN 4096

// ---------------- scratch (__device__ globals; no allocs allowed) ----------
__device__ __half g_qh[(size_t)BB * NN * 64];   // [b][n][32 q_hi | 32 q_lo] (2 MB)
__device__ __half g_kh[(size_t)BB * NN * 64];   // [b][n][32 k_hi | 32 k_lo] (2 MB)
__device__ __half g_vh[(size_t)BB * CC * NN];   // [b][c][j] fp16 V (8 MB)
__device__ __half g_wvh[CC * CC];               // Wv hi (128 KB)
__device__ __half g_wvl[CC * CC];               // Wv lo (128 KB)

// ---------------- helpers ---------------------------------------------------
__device__ __forceinline__ uint32_t smem_u32(const void* p) {
    uint32_t a;
    asm("{ .reg .u64 t; cvta.to.shared.u64 t, %1; cvt.u32.u64 %0, t; }"
        : "=r"(a) : "l"(p));
    return a;
}
__device__ __forceinline__ void cp16(uint32_t dst, const void* src) {
    asm volatile("cp.async.cg.shared.global [%0], [%1], 16;" :: "r"(dst), "l"(src)
                 : "memory");
}
__device__ __forceinline__ void sts16(uint32_t a, __half v) {
    unsigned short u = *reinterpret_cast<unsigned short*>(&v);
    asm volatile("st.shared.u16 [%0], %1;" :: "r"(a), "h"(u) : "memory");
}
__device__ __forceinline__ void sts32(uint32_t a, uint32_t v) {
    asm volatile("st.shared.u32 [%0], %1;" :: "r"(a), "r"(v) : "memory");
}
__device__ __forceinline__ uint32_t swaddr(uint32_t base, int row, int u) {
    return base + row * 128 + (((u) ^ (row & 7)) << 4);
}
__device__ __forceinline__ void ldm_x4(uint32_t& r0, uint32_t& r1,
                                       uint32_t& r2, uint32_t& r3, uint32_t a) {
    asm volatile("ldmatrix.sync.aligned.m8n8.x4.shared.b16 {%0,%1,%2,%3}, [%4];"
                 : "=r"(r0), "=r"(r1), "=r"(r2), "=r"(r3) : "r"(a));
}
__device__ __forceinline__ void mma16816(float* d, const uint32_t* a,
                                         uint32_t b0, uint32_t b1) {
    asm volatile(
        "mma.sync.aligned.m16n8k16.row.col.f32.f16.f16.f32 "
        "{%0,%1,%2,%3}, {%4,%5,%6,%7}, {%8,%9}, {%0,%1,%2,%3};"
        : "+f"(d[0]), "+f"(d[1]), "+f"(d[2]), "+f"(d[3])
        : "r"(a[0]), "r"(a[1]), "r"(a[2]), "r"(a[3]), "r"(b0), "r"(b1));
}
__device__ __forceinline__ uint32_t pkh2(float a, float b) {
    __half2 h = __floats2half2_rn(a, b);
    return *reinterpret_cast<uint32_t*>(&h);
}

// ---------------------------------------------------------------------------
// wsplit: Wv fp32 -> hi/lo fp16 (elementwise)
// ---------------------------------------------------------------------------
__global__ __launch_bounds__(256) void wsplit_kernel(const float* __restrict__ Wv)
{
    int e4 = blockIdx.x * 256 + threadIdx.x;
    float4 v = ((const float4*)Wv)[e4];
    int base = e4 * 4;
    float f[4] = {v.x, v.y, v.z, v.w};
#pragma unroll
    for (int t = 0; t < 4; t++) {
        __half hi = __float2half_rn(f[t]);
        __half lo = __float2half_rn(f[t] - __half2float(hi));
        g_wvh[base + t] = hi;
        g_wvl[base + t] = lo;
    }
}

// ---------------------------------------------------------------------------
// proj_qk: q,k as split fp16 hi|lo rows [b][n][64]  (proven)
// ---------------------------------------------------------------------------
__global__ __launch_bounds__(256) void proj_qk_kernel(
    const float* __restrict__ x, const float* __restrict__ Wq,
    const float* __restrict__ Wk)
{
    const int b = blockIdx.z, n0 = blockIdx.x * 64;
    const int tid = threadIdx.x, tx = tid & 15, ty = tid >> 4;
    __shared__ float xs[16][64];
    __shared__ float ws[64][17];
    float acc[4][4];
#pragma unroll
    for (int i = 0; i < 4; i++)
#pragma unroll
        for (int j = 0; j < 4; j++) acc[i][j] = 0.f;
    const float* xb = x + (size_t)b * CC * NN;
    for (int c0 = 0; c0 < CC; c0 += 16) {
#pragma unroll
        for (int i = 0; i < 4; i++) {
            int e = tid + i * 256, cc = e >> 6, nn = e & 63;
            xs[cc][nn] = xb[(size_t)(c0 + cc) * NN + n0 + nn];
        }
#pragma unroll
        for (int i = 0; i < 4; i++) {
            int e = tid + i * 256, o = e >> 4, cc = e & 15;
            ws[o][cc] = (o < 32) ? Wq[o * CC + c0 + cc] : Wk[(o - 32) * CC + c0 + cc];
        }
        __syncthreads();
#pragma unroll
        for (int cc = 0; cc < 16; cc++) {
            float a[4], w[4];
#pragma unroll
            for (int i = 0; i < 4; i++) a[i] = xs[cc][tx * 4 + i];
#pragma unroll
            for (int j = 0; j < 4; j++) w[j] = ws[ty * 4 + j][cc];
#pragma unroll
            for (int i = 0; i < 4; i++)
#pragma unroll
                for (int j = 0; j < 4; j++) acc[i][j] = fmaf(a[i], w[j], acc[i][j]);
        }
        __syncthreads();
    }
#pragma unroll
    for (int i = 0; i < 4; i++) {
        int n = n0 + tx * 4 + i;
        size_t base = ((size_t)b * NN + n) * 64;
#pragma unroll
        for (int j = 0; j < 4; j++) {
            int o = ty * 4 + j;
            float a = acc[i][j];
            __half hi = __float2half_rn(a);
            __half lo = __float2half_rn(a - __half2float(hi));
            if (o < 32) { g_qh[base + o]  = hi; g_qh[base + 32 + o] = lo; }
            else        { g_kh[base + o - 32] = hi; g_kh[base + o]  = lo; }
        }
    }
}

// ---------------------------------------------------------------------------
// proj_v_mma: V[c, n] = Wv x via split-fp16 mma (proven round 8)
// ---------------------------------------------------------------------------
#define PVW_SMEM (4 * 16384 + 256)

__global__ __launch_bounds__(256) void proj_v_mma_kernel(
    const float* __restrict__ x)
{
    extern __shared__ char dsm[];
    const int b = blockIdx.z, n0 = blockIdx.x * 128, c0 = blockIdx.y * 128;
    const int tid = threadIdx.x, wid = tid >> 5, lane = tid & 31;
    const int wcc = wid >> 2, wn = wid & 3;
    const uint32_t whb = (smem_u32(dsm) + 127) & ~127u;
    const uint32_t wlb = whb + 16384;
    const uint32_t xhb = wlb + 16384;
    const uint32_t xlb = xhb + 16384;

    float acc[4][4][4];
#pragma unroll
    for (int i = 0; i < 4; i++)
#pragma unroll
        for (int j = 0; j < 4; j++)
#pragma unroll
            for (int k = 0; k < 4; k++) acc[i][j][k] = 0.f;

    const int a_row = wcc * 64 + (lane & 15);
    const int a_uo  = lane >> 4;
    const int b_row = wn * 32 + (lane & 7) + ((lane >> 4) << 3);
    const int b_uo  = (lane >> 3) & 1;

    for (int kc = 0; kc < 4; kc++) {
        __syncthreads();
#pragma unroll
        for (int i = 0; i < 4; i++) {
            int e = tid + i * 256, row = e >> 3, u = e & 7;
            const __half* sh = g_wvh + (size_t)(c0 + row) * CC + kc * 64 + u * 8;
            const __half* sl = g_wvl + (size_t)(c0 + row) * CC + kc * 64 + u * 8;
            cp16(swaddr(whb, row, u), sh);
            cp16(swaddr(wlb, row, u), sl);
        }
        asm volatile("cp.async.commit_group;" ::: "memory");

#pragma unroll
        for (int i = 0; i < 8; i++) {
            int e = tid + i * 256;
            int k = e >> 5, n4 = (e & 31) * 4;
            const float* src = x + ((size_t)b * CC + kc * 64 + k) * NN + n0 + n4;
            float4 v = *(const float4*)src;
            float f[4] = {v.x, v.y, v.z, v.w};
            uint32_t ucol = (uint32_t)(k >> 3);
            uint32_t boff = (uint32_t)(k & 7) * 2;
#pragma unroll
            for (int t = 0; t < 4; t++) {
                __half hi = __float2half_rn(f[t]);
                __half lo = __float2half_rn(f[t] - __half2float(hi));
                sts16(swaddr(xhb, n4 + t, ucol) + boff, hi);
                sts16(swaddr(xlb, n4 + t, ucol) + boff, lo);
            }
        }
        asm volatile("cp.async.wait_group 0;" ::: "memory");
        __syncthreads();

#pragma unroll
        for (int ks = 0; ks < 4; ks++) {
            uint32_t ah[4][4], al[4][4];
#pragma unroll
            for (int qt = 0; qt < 4; qt++) {
                ldm_x4(ah[qt][0], ah[qt][1], ah[qt][2], ah[qt][3],
                       swaddr(whb, a_row + qt * 16, a_uo + ks * 2));
                ldm_x4(al[qt][0], al[qt][1], al[qt][2], al[qt][3],
                       swaddr(wlb, a_row + qt * 16, a_uo + ks * 2));
            }
            uint32_t bh[4][2], bl[4][2];
#pragma unroll
            for (int nt2 = 0; nt2 < 2; nt2++) {
                uint32_t r0, r1, r2, r3;
                ldm_x4(r0, r1, r2, r3,
                       swaddr(xhb, b_row + nt2 * 16, b_uo + ks * 2));
                bh[nt2 * 2][0] = r0;     bh[nt2 * 2][1] = r1;
                bh[nt2 * 2 + 1][0] = r2; bh[nt2 * 2 + 1][1] = r3;
                ldm_x4(r0, r1, r2, r3,
                       swaddr(xlb, b_row + nt2 * 16, b_uo + ks * 2));
                bl[nt2 * 2][0] = r0;     bl[nt2 * 2][1] = r1;
                bl[nt2 * 2 + 1][0] = r2; bl[nt2 * 2 + 1][1] = r3;
            }
#pragma unroll
            for (int qt = 0; qt < 4; qt++)
#pragma unroll
                for (int nt = 0; nt < 4; nt++) {
                    mma16816(acc[qt][nt], ah[qt], bh[nt][0], bh[nt][1]);
                    mma16816(acc[qt][nt], al[qt], bh[nt][0], bh[nt][1]);
                    mma16816(acc[qt][nt], ah[qt], bl[nt][0], bl[nt][1]);
                }
        }
    }

#pragma unroll
    for (int qt = 0; qt < 4; qt++)
#pragma unroll
        for (int nt = 0; nt < 4; nt++) {
            int c = c0 + wcc * 64 + qt * 16 + (lane >> 2);
            int n = n0 + wn * 32 + nt * 8 + 2 * (lane & 3);
            *(uint32_t*)(g_vh + ((size_t)b * CC + c) * NN + n) =
                pkh2(acc[qt][nt][0], acc[qt][nt][1]);
            *(uint32_t*)(g_vh + ((size_t)b * CC + c + 8) * NN + n) =
                pkh2(acc[qt][nt][2], acc[qt][nt][3]);
        }
}

// ---------------------------------------------------------------------------
// fattn: fused flash attention + residual, S computed ONCE per q-row.
// CTA 64q x 256c, 256 thr, 8 warps: wq = w&3 (q-group 16), wh = w>>2.
// Pipeline (race-free): per tile:
//   wait_group 0            -> tile jt data landed (group committed in jt-1)
//   sync (1)                -> visibility; all threads done with bufs[nxt]
//   prefetch jt+1 -> bufs[nxt]   (safe: PV of jt-1 complete chip-wide in CTA)
//   S -> sync (2) -> combine/exp/P -> sync (3) -> Lb update + PV
// ---------------------------------------------------------------------------
#define FA_SMEM (8192 + 2 * 8192 + 2 * 32768 + 8192 + 128)

__device__ __forceinline__ void fa_load_kv(uint32_t kbuf, uint32_t vbuf,
                                           int b, int jt, int tid)
{
    const __half* ksrc = g_kh + ((size_t)b * NN + jt * 64) * 64;
#pragma unroll
    for (int rr = 0; rr < 2; rr++) {
        int e = tid + rr * 256, row = e >> 3, u = e & 7;
        cp16(swaddr(kbuf, row, u), ksrc + (size_t)row * 64 + u * 8);
    }
    const __half* vsrc = g_vh + (size_t)b * CC * NN + jt * 64;
#pragma unroll
    for (int rr = 0; rr < 8; rr++) {
        int e = tid + rr * 256, row = e >> 3, u = e & 7;
        cp16(swaddr(vbuf, row, u), vsrc + (size_t)row * NN + u * 8);
    }
    asm volatile("cp.async.commit_group;" ::: "memory");
}

__global__ __launch_bounds__(256, 2) void fattn_kernel(
    const float* __restrict__ x, float* __restrict__ out)
{
    extern __shared__ char dsm[];
    __shared__ float Mb[2][64], Lb[2][64];     // parity-buffered row stats
    __shared__ float pmS[2][64], plS[2][64];   // per-j-half partials

    const int b = blockIdx.z, q0 = blockIdx.x * 64;
    const int tid = threadIdx.x, w = tid >> 5, lane = tid & 31;
    const int wq = w & 3, wh = w >> 2;
    const uint32_t qb = (smem_u32(dsm) + 127) & ~127u;
    const uint32_t kbuf[2] = {qb + 8192,  qb + 16384};
    const uint32_t vbuf[2] = {qb + 24576, qb + 57344};
    const uint32_t ptile   = qb + 90112;

    // stage Q [64 rows, 128B] + first K/V (one commit group, from fa_load_kv)
    {
        const __half* qsrc = g_qh + ((size_t)b * NN + q0) * 64;
#pragma unroll
        for (int rr = 0; rr < 2; rr++) {
            int e = tid + rr * 256, row = e >> 3, u = e & 7;
            cp16(swaddr(qb, row, u), qsrc + (size_t)row * 64 + u * 8);
        }
    }
    fa_load_kv(kbuf[0], vbuf[0], b, 0, tid);
    if (tid < 64) { Mb[0][tid] = -1e30f; Lb[0][tid] = 0.f; }

    float acc[16][4];
#pragma unroll
    for (int i = 0; i < 16; i++)
#pragma unroll
        for (int k = 0; k < 4; k++) acc[i][k] = 0.f;

    // fragment lane roles
    const int arow = wq * 16 + (lane & 15);            // Q / P A-frag row
    const int au   = lane >> 4;
    const int krow = wh * 32 + (lane & 7) + ((lane >> 4) << 3);   // K B rows
    const int ku   = (lane >> 3) & 1;
    const int vrow = wh * 128 + (lane & 7) + ((lane >> 4) << 3);  // V B rows
    const int vu   = (lane >> 3) & 1;
    const int r0   = lane >> 2;                         // stat row (h=0)

    const int NTJ = NN / 64;   // 64
    for (int jt = 0; jt < NTJ; jt++) {
        const int par = jt & 1, nxt = par ^ 1;

        asm volatile("cp.async.wait_group 0;" ::: "memory");  // tile jt landed
        __syncthreads();            // (1) visibility; bufs[nxt] fully consumed

        if (jt + 1 < NTJ)
            fa_load_kv(kbuf[nxt], vbuf[nxt], b, jt + 1, tid);  // overlaps compute

        // ---- S: 16q x 32j (j-half wh), hi*hi + hi*lo + lo*hi ----
        float s[4][4];
#pragma unroll
        for (int i = 0; i < 4; i++)
#pragma unroll
            for (int k = 0; k < 4; k++) s[i][k] = 0.f;
        {
            const int poa[3] = {0, 0, 4}, pob[3] = {0, 4, 0};
            const uint32_t kcur = kbuf[par];
#pragma unroll
            for (int part = 0; part < 3; part++)
#pragma unroll
                for (int ks = 0; ks < 2; ks++) {
                    uint32_t a[4];
                    ldm_x4(a[0], a[1], a[2], a[3],
                           swaddr(qb, arow, poa[part] + ks * 2 + au));
#pragma unroll
                    for (int nt2 = 0; nt2 < 2; nt2++) {
                        uint32_t b0, b1, b2, b3;
                        ldm_x4(b0, b1, b2, b3,
                               swaddr(kcur, krow + nt2 * 16,
                                      pob[part] + ks * 2 + ku));
                        mma16816(s[nt2 * 2],     a, b0, b1);
                        mma16816(s[nt2 * 2 + 1], a, b2, b3);
                    }
                }
        }

        // ---- partial row max over this j-half ----
#pragma unroll
        for (int h = 0; h < 2; h++) {
            float t = -1e30f;
#pragma unroll
            for (int nt = 0; nt < 4; nt++)
                t = fmaxf(t, fmaxf(s[nt][2 * h], s[nt][2 * h + 1]));
            t = fmaxf(t, __shfl_xor_sync(0xffffffffu, t, 1));
            t = fmaxf(t, __shfl_xor_sync(0xffffffffu, t, 2));
            if ((lane & 3) == 0) pmS[wh][wq * 16 + r0 + h * 8] = t;
        }
        __syncthreads();                    // (2) pm ready

        // ---- combine stats, exp, write P + partial sums, rescale acc ----
#pragma unroll
        for (int h = 0; h < 2; h++) {
            const int row = wq * 16 + r0 + h * 8;
            float mold = Mb[par][row];
            float mn = fmaxf(mold, fmaxf(pmS[0][row], pmS[1][row]));
            float corr = __expf(mold - mn);
            float lp = 0.f;
#pragma unroll
            for (int nt = 0; nt < 4; nt++) {
                float p0 = __expf(s[nt][2 * h]     - mn);
                float p1 = __expf(s[nt][2 * h + 1] - mn);
                s[nt][2 * h] = p0; s[nt][2 * h + 1] = p1;
                lp += p0 + p1;
                int col = wh * 32 + nt * 8 + 2 * (lane & 3);
                int byte = col * 2;
                sts32(swaddr(ptile, row, byte >> 4) + (byte & 15), pkh2(p0, p1));
            }
            lp += __shfl_xor_sync(0xffffffffu, lp, 1);
            lp += __shfl_xor_sync(0xffffffffu, lp, 2);
            if ((lane & 3) == 0) {
                plS[wh][row] = lp;
                if (wh == 0) Mb[nxt][row] = mn;
            }
#pragma unroll
            for (int nt = 0; nt < 16; nt++) {
                acc[nt][2 * h]     *= corr;
                acc[nt][2 * h + 1] *= corr;
            }
        }
        __syncthreads();                    // (3) ptile + pl + Mnew ready

        if (tid < 64) {
            float corr = __expf(Mb[par][tid] - Mb[nxt][tid]);
            Lb[nxt][tid] = Lb[par][tid] * corr + plS[0][tid] + plS[1][tid];
        }

        // ---- PV: acc += P x V^T  (16q x 128c, c-half wh) ----
        {
            const uint32_t vcur = vbuf[par];
#pragma unroll
            for (int ks = 0; ks < 4; ks++) {
                uint32_t a[4];
                ldm_x4(a[0], a[1], a[2], a[3],
                       swaddr(ptile, arow, au + ks * 2));
#pragma unroll
                for (int nt2 = 0; nt2 < 8; nt2++) {
                    uint32_t b0, b1, b2, b3;
                    ldm_x4(b0, b1, b2, b3,
                           swaddr(vcur, vrow + nt2 * 16, vu + ks * 2));
                    mma16816(acc[nt2 * 2],     a, b0, b1);
                    mma16816(acc[nt2 * 2 + 1], a, b2, b3);
                }
            }
        }
    }
    __syncthreads();                        // final Lb[0] ready (NTJ even)

    // ---- epilogue: normalize + residual ----
    const float inv0 = 1.f / Lb[0][wq * 16 + r0];
    const float inv1 = 1.f / Lb[0][wq * 16 + r0 + 8];
    const int q = q0 + wq * 16 + r0;
#pragma unroll
    for (int nt = 0; nt < 16; nt++) {
        int c = wh * 128 + nt * 8 + 2 * (lane & 3);
        size_t i00 = ((size_t)b * CC + c) * NN + q;
        out[i00]          = acc[nt][0] * inv0 + x[i00];
        out[i00 + NN]     = acc[nt][1] * inv0 + x[i00 + NN];
        out[i00 + 8]      = acc[nt][2] * inv1 + x[i00 + 8];
        out[i00 + NN + 8] = acc[nt][3] * inv1 + x[i00 + NN + 8];
    }
}

// ---------------------------------------------------------------------------
extern "C" void kernel_launch(void* const* d_in, const int* in_sizes, int n_in,
                              void* d_out, int out_size)
{
    const float* x  = (const float*)d_in[0];
    const float* Wq = (const float*)d_in[1];
    const float* Wk = (const float*)d_in[2];
    const float* Wv = (const float*)d_in[3];
    float* out = (float*)d_out;

    cudaFuncSetAttribute(fattn_kernel,
                         cudaFuncAttributeMaxDynamicSharedMemorySize, FA_SMEM);
    cudaFuncSetAttribute(proj_v_mma_kernel,
                         cudaFuncAttributeMaxDynamicSharedMemorySize, PVW_SMEM);

    wsplit_kernel    <<<64, 256>>>(Wv);
    proj_qk_kernel   <<<dim3(NN / 64, 1, BB), 256>>>(x, Wq, Wk);
    proj_v_mma_kernel<<<dim3(NN / 128, CC / 128, BB), 256, PVW_SMEM>>>(x);
    fattn_kernel     <<<dim3(NN / 64, 1, BB), 256, FA_SMEM>>>(x, out);
}

// round 12
// speedup vs baseline: 9.0467x; 1.0354x over previous
#include <cuda_runtime.h>
#include <cuda_fp16.h>
#include <math.h>
#include <stdint.h>

#define BB 4
#define CC 256
#define NN 4096

// ---------------- scratch (__device__ globals; no allocs allowed) ----------
__device__ __half g_qh[(size_t)BB * NN * 64];   // [b][n][32 q_hi | 32 q_lo] (2 MB)
__device__ __half g_kh[(size_t)BB * NN * 64];   // [b][n][32 k_hi | 32 k_lo] (2 MB)
__device__ __half g_vh[(size_t)BB * CC * NN];   // [b][c][j] fp16 V (8 MB)
__device__ __half g_wvh[CC * CC];               // Wv hi (128 KB)
__device__ __half g_wvl[CC * CC];               // Wv lo (128 KB)

// ---------------- helpers ---------------------------------------------------
__device__ __forceinline__ uint32_t smem_u32(const void* p) {
    uint32_t a;
    asm("{ .reg .u64 t; cvta.to.shared.u64 t, %1; cvt.u32.u64 %0, t; }"
        : "=r"(a) : "l"(p));
    return a;
}
__device__ __forceinline__ void cp16(uint32_t dst, const void* src) {
    asm volatile("cp.async.cg.shared.global [%0], [%1], 16;" :: "r"(dst), "l"(src)
                 : "memory");
}
__device__ __forceinline__ void sts16(uint32_t a, __half v) {
    unsigned short u = *reinterpret_cast<unsigned short*>(&v);
    asm volatile("st.shared.u16 [%0], %1;" :: "r"(a), "h"(u) : "memory");
}
__device__ __forceinline__ void sts32(uint32_t a, uint32_t v) {
    asm volatile("st.shared.u32 [%0], %1;" :: "r"(a), "r"(v) : "memory");
}
__device__ __forceinline__ uint32_t swaddr(uint32_t base, int row, int u) {
    return base + row * 128 + (((u) ^ (row & 7)) << 4);
}
__device__ __forceinline__ void ldm_x4(uint32_t& r0, uint32_t& r1,
                                       uint32_t& r2, uint32_t& r3, uint32_t a) {
    asm volatile("ldmatrix.sync.aligned.m8n8.x4.shared.b16 {%0,%1,%2,%3}, [%4];"
                 : "=r"(r0), "=r"(r1), "=r"(r2), "=r"(r3) : "r"(a));
}
__device__ __forceinline__ void mma16816(float* d, const uint32_t* a,
                                         uint32_t b0, uint32_t b1) {
    asm volatile(
        "mma.sync.aligned.m16n8k16.row.col.f32.f16.f16.f32 "
        "{%0,%1,%2,%3}, {%4,%5,%6,%7}, {%8,%9}, {%0,%1,%2,%3};"
        : "+f"(d[0]), "+f"(d[1]), "+f"(d[2]), "+f"(d[3])
        : "r"(a[0]), "r"(a[1]), "r"(a[2]), "r"(a[3]), "r"(b0), "r"(b1));
}
__device__ __forceinline__ uint32_t pkh2(float a, float b) {
    __half2 h = __floats2half2_rn(a, b);
    return *reinterpret_cast<uint32_t*>(&h);
}

// ---------------------------------------------------------------------------
// wsplit: Wv fp32 -> hi/lo fp16 (elementwise)
// ---------------------------------------------------------------------------
__global__ __launch_bounds__(256) void wsplit_kernel(const float* __restrict__ Wv)
{
    int e4 = blockIdx.x * 256 + threadIdx.x;
    float4 v = ((const float4*)Wv)[e4];
    int base = e4 * 4;
    float f[4] = {v.x, v.y, v.z, v.w};
#pragma unroll
    for (int t = 0; t < 4; t++) {
        __half hi = __float2half_rn(f[t]);
        __half lo = __float2half_rn(f[t] - __half2float(hi));
        g_wvh[base + t] = hi;
        g_wvl[base + t] = lo;
    }
}

// ---------------------------------------------------------------------------
// proj_qk: q,k as split fp16 hi|lo rows [b][n][64]  (proven)
// ---------------------------------------------------------------------------
__global__ __launch_bounds__(256) void proj_qk_kernel(
    const float* __restrict__ x, const float* __restrict__ Wq,
    const float* __restrict__ Wk)
{
    const int b = blockIdx.z, n0 = blockIdx.x * 64;
    const int tid = threadIdx.x, tx = tid & 15, ty = tid >> 4;
    __shared__ float xs[16][64];
    __shared__ float ws[64][17];
    float acc[4][4];
#pragma unroll
    for (int i = 0; i < 4; i++)
#pragma unroll
        for (int j = 0; j < 4; j++) acc[i][j] = 0.f;
    const float* xb = x + (size_t)b * CC * NN;
    for (int c0 = 0; c0 < CC; c0 += 16) {
#pragma unroll
        for (int i = 0; i < 4; i++) {
            int e = tid + i * 256, cc = e >> 6, nn = e & 63;
            xs[cc][nn] = xb[(size_t)(c0 + cc) * NN + n0 + nn];
        }
#pragma unroll
        for (int i = 0; i < 4; i++) {
            int e = tid + i * 256, o = e >> 4, cc = e & 15;
            ws[o][cc] = (o < 32) ? Wq[o * CC + c0 + cc] : Wk[(o - 32) * CC + c0 + cc];
        }
        __syncthreads();
#pragma unroll
        for (int cc = 0; cc < 16; cc++) {
            float a[4], w[4];
#pragma unroll
            for (int i = 0; i < 4; i++) a[i] = xs[cc][tx * 4 + i];
#pragma unroll
            for (int j = 0; j < 4; j++) w[j] = ws[ty * 4 + j][cc];
#pragma unroll
            for (int i = 0; i < 4; i++)
#pragma unroll
                for (int j = 0; j < 4; j++) acc[i][j] = fmaf(a[i], w[j], acc[i][j]);
        }
        __syncthreads();
    }
#pragma unroll
    for (int i = 0; i < 4; i++) {
        int n = n0 + tx * 4 + i;
        size_t base = ((size_t)b * NN + n) * 64;
#pragma unroll
        for (int j = 0; j < 4; j++) {
            int o = ty * 4 + j;
            float a = acc[i][j];
            __half hi = __float2half_rn(a);
            __half lo = __float2half_rn(a - __half2float(hi));
            if (o < 32) { g_qh[base + o]  = hi; g_qh[base + 32 + o] = lo; }
            else        { g_kh[base + o - 32] = hi; g_kh[base + o]  = lo; }
        }
    }
}

// ---------------------------------------------------------------------------
// proj_v_mma: V[c, n] = Wv x via split-fp16 mma (proven round 8)
// ---------------------------------------------------------------------------
#define PVW_SMEM (4 * 16384 + 256)

__global__ __launch_bounds__(256) void proj_v_mma_kernel(
    const float* __restrict__ x)
{
    extern __shared__ char dsm[];
    const int b = blockIdx.z, n0 = blockIdx.x * 128, c0 = blockIdx.y * 128;
    const int tid = threadIdx.x, wid = tid >> 5, lane = tid & 31;
    const int wcc = wid >> 2, wn = wid & 3;
    const uint32_t whb = (smem_u32(dsm) + 127) & ~127u;
    const uint32_t wlb = whb + 16384;
    const uint32_t xhb = wlb + 16384;
    const uint32_t xlb = xhb + 16384;

    float acc[4][4][4];
#pragma unroll
    for (int i = 0; i < 4; i++)
#pragma unroll
        for (int j = 0; j < 4; j++)
#pragma unroll
            for (int k = 0; k < 4; k++) acc[i][j][k] = 0.f;

    const int a_row = wcc * 64 + (lane & 15);
    const int a_uo  = lane >> 4;
    const int b_row = wn * 32 + (lane & 7) + ((lane >> 4) << 3);
    const int b_uo  = (lane >> 3) & 1;

    for (int kc = 0; kc < 4; kc++) {
        __syncthreads();
#pragma unroll
        for (int i = 0; i < 4; i++) {
            int e = tid + i * 256, row = e >> 3, u = e & 7;
            const __half* sh = g_wvh + (size_t)(c0 + row) * CC + kc * 64 + u * 8;
            const __half* sl = g_wvl + (size_t)(c0 + row) * CC + kc * 64 + u * 8;
            cp16(swaddr(whb, row, u), sh);
            cp16(swaddr(wlb, row, u), sl);
        }
        asm volatile("cp.async.commit_group;" ::: "memory");

#pragma unroll
        for (int i = 0; i < 8; i++) {
            int e = tid + i * 256;
            int k = e >> 5, n4 = (e & 31) * 4;
            const float* src = x + ((size_t)b * CC + kc * 64 + k) * NN + n0 + n4;
            float4 v = *(const float4*)src;
            float f[4] = {v.x, v.y, v.z, v.w};
            uint32_t ucol = (uint32_t)(k >> 3);
            uint32_t boff = (uint32_t)(k & 7) * 2;
#pragma unroll
            for (int t = 0; t < 4; t++) {
                __half hi = __float2half_rn(f[t]);
                __half lo = __float2half_rn(f[t] - __half2float(hi));
                sts16(swaddr(xhb, n4 + t, ucol) + boff, hi);
                sts16(swaddr(xlb, n4 + t, ucol) + boff, lo);
            }
        }
        asm volatile("cp.async.wait_group 0;" ::: "memory");
        __syncthreads();

#pragma unroll
        for (int ks = 0; ks < 4; ks++) {
            uint32_t ah[4][4], al[4][4];
#pragma unroll
            for (int qt = 0; qt < 4; qt++) {
                ldm_x4(ah[qt][0], ah[qt][1], ah[qt][2], ah[qt][3],
                       swaddr(whb, a_row + qt * 16, a_uo + ks * 2));
                ldm_x4(al[qt][0], al[qt][1], al[qt][2], al[qt][3],
                       swaddr(wlb, a_row + qt * 16, a_uo + ks * 2));
            }
            uint32_t bh[4][2], bl[4][2];
#pragma unroll
            for (int nt2 = 0; nt2 < 2; nt2++) {
                uint32_t r0, r1, r2, r3;
                ldm_x4(r0, r1, r2, r3,
                       swaddr(xhb, b_row + nt2 * 16, b_uo + ks * 2));
                bh[nt2 * 2][0] = r0;     bh[nt2 * 2][1] = r1;
                bh[nt2 * 2 + 1][0] = r2; bh[nt2 * 2 + 1][1] = r3;
                ldm_x4(r0, r1, r2, r3,
                       swaddr(xlb, b_row + nt2 * 16, b_uo + ks * 2));
                bl[nt2 * 2][0] = r0;     bl[nt2 * 2][1] = r1;
                bl[nt2 * 2 + 1][0] = r2; bl[nt2 * 2 + 1][1] = r3;
            }
#pragma unroll
            for (int qt = 0; qt < 4; qt++)
#pragma unroll
                for (int nt = 0; nt < 4; nt++) {
                    mma16816(acc[qt][nt], ah[qt], bh[nt][0], bh[nt][1]);
                    mma16816(acc[qt][nt], al[qt], bh[nt][0], bh[nt][1]);
                    mma16816(acc[qt][nt], ah[qt], bl[nt][0], bl[nt][1]);
                }
        }
    }

#pragma unroll
    for (int qt = 0; qt < 4; qt++)
#pragma unroll
        for (int nt = 0; nt < 4; nt++) {
            int c = c0 + wcc * 64 + qt * 16 + (lane >> 2);
            int n = n0 + wn * 32 + nt * 8 + 2 * (lane & 3);
            *(uint32_t*)(g_vh + ((size_t)b * CC + c) * NN + n) =
                pkh2(acc[qt][nt][0], acc[qt][nt][1]);
            *(uint32_t*)(g_vh + ((size_t)b * CC + c + 8) * NN + n) =
                pkh2(acc[qt][nt][2], acc[qt][nt][3]);
        }
}

// ---------------------------------------------------------------------------
// fattn: fused flash attention + residual. S once per q-row; crossbar-lean.
// CTA 64q x 256c, 256 thr, 8 warps.
//   S phase : warp (wq=w&3, wh=w>>2) computes S 16q x 32j; Q frags REGISTER-
//             resident (hoisted, loop-invariant).
//   softmax : stats identical to round 11 (proven); also emits corrS[64].
//   PV phase: TRANSPOSED mapping — warp w owns 32c x 64q; V is the A operand
//             (read exactly once per CTA), P the B operand from ptile.
//             acc is c-major; per-q rescale via corrS float2 reads.
// Pipeline/barriers identical to round 11 (race-free, 3 syncs/tile).
// ---------------------------------------------------------------------------
#define FA_SMEM (8192 + 2 * 8192 + 2 * 32768 + 8192 + 128)

__device__ __forceinline__ void fa_load_kv(uint32_t kbuf, uint32_t vbuf,
                                           int b, int jt, int tid)
{
    const __half* ksrc = g_kh + ((size_t)b * NN + jt * 64) * 64;
#pragma unroll
    for (int rr = 0; rr < 2; rr++) {
        int e = tid + rr * 256, row = e >> 3, u = e & 7;
        cp16(swaddr(kbuf, row, u), ksrc + (size_t)row * 64 + u * 8);
    }
    const __half* vsrc = g_vh + (size_t)b * CC * NN + jt * 64;
#pragma unroll
    for (int rr = 0; rr < 8; rr++) {
        int e = tid + rr * 256, row = e >> 3, u = e & 7;
        cp16(swaddr(vbuf, row, u), vsrc + (size_t)row * NN + u * 8);
    }
    asm volatile("cp.async.commit_group;" ::: "memory");
}

__global__ __launch_bounds__(256, 2) void fattn_kernel(
    const float* __restrict__ x, float* __restrict__ out)
{
    extern __shared__ char dsm[];
    __shared__ float Mb[2][64], Lb[2][64];     // parity-buffered row stats
    __shared__ float pmS[2][64], plS[2][64];   // per-j-half partials
    __shared__ float corrS[64];                // per-q rescale factor, this tile

    const int b = blockIdx.z, q0 = blockIdx.x * 64;
    const int tid = threadIdx.x, w = tid >> 5, lane = tid & 31;
    const int wq = w & 3, wh = w >> 2;
    const uint32_t qb = (smem_u32(dsm) + 127) & ~127u;
    const uint32_t kbuf[2] = {qb + 8192,  qb + 16384};
    const uint32_t vbuf[2] = {qb + 24576, qb + 57344};
    const uint32_t ptile   = qb + 90112;

    // ---- prologue: stage Q (own group), then first K/V group ----
    {
        const __half* qsrc = g_qh + ((size_t)b * NN + q0) * 64;
#pragma unroll
        for (int rr = 0; rr < 2; rr++) {
            int e = tid + rr * 256, row = e >> 3, u = e & 7;
            cp16(swaddr(qb, row, u), qsrc + (size_t)row * 64 + u * 8);
        }
        asm volatile("cp.async.commit_group;" ::: "memory");
    }
    fa_load_kv(kbuf[0], vbuf[0], b, 0, tid);
    if (tid < 64) { Mb[0][tid] = -1e30f; Lb[0][tid] = 0.f; }

    // hoist Q fragments (loop-invariant): qf[part*2+ks][4]
    const int arow = wq * 16 + (lane & 15);
    const int au   = lane >> 4;
    uint32_t qf[6][4];
    {
        asm volatile("cp.async.wait_group 1;" ::: "memory");   // Q landed
        __syncthreads();
        const int poa[3] = {0, 0, 4};
#pragma unroll
        for (int part = 0; part < 3; part++)
#pragma unroll
            for (int ks = 0; ks < 2; ks++)
                ldm_x4(qf[part * 2 + ks][0], qf[part * 2 + ks][1],
                       qf[part * 2 + ks][2], qf[part * 2 + ks][3],
                       swaddr(qb, arow, poa[part] + ks * 2 + au));
    }

    float acc[2][8][4];                        // c-major: [ct][q-frag][d]
#pragma unroll
    for (int i = 0; i < 2; i++)
#pragma unroll
        for (int j = 0; j < 8; j++)
#pragma unroll
            for (int k = 0; k < 4; k++) acc[i][j][k] = 0.f;

    // lane roles
    const int krow = wh * 32 + (lane & 7) + ((lane >> 4) << 3);   // K B rows
    const int ku   = (lane >> 3) & 1;
    const int varow = w * 32 + (lane & 15);                       // V A rows (c)
    const int vau   = lane >> 4;
    const int pbrow = (lane & 7) + ((lane >> 4) << 3);            // P B rows (q)
    const int pbu   = (lane >> 3) & 1;
    const int r0   = lane >> 2;                                   // stat row

    const int NTJ = NN / 64;   // 64
    for (int jt = 0; jt < NTJ; jt++) {
        const int par = jt & 1, nxt = par ^ 1;

        asm volatile("cp.async.wait_group 0;" ::: "memory");  // tile jt landed
        __syncthreads();            // (1) visibility; bufs[nxt] fully consumed

        if (jt + 1 < NTJ)
            fa_load_kv(kbuf[nxt], vbuf[nxt], b, jt + 1, tid);  // overlaps compute

        // ---- S: 16q x 32j (j-half wh) with register Q frags ----
        float s[4][4];
#pragma unroll
        for (int i = 0; i < 4; i++)
#pragma unroll
            for (int k = 0; k < 4; k++) s[i][k] = 0.f;
        {
            const int pob[3] = {0, 4, 0};
            const uint32_t kcur = kbuf[par];
#pragma unroll
            for (int part = 0; part < 3; part++)
#pragma unroll
                for (int ks = 0; ks < 2; ks++) {
#pragma unroll
                    for (int nt2 = 0; nt2 < 2; nt2++) {
                        uint32_t b0, b1, b2, b3;
                        ldm_x4(b0, b1, b2, b3,
                               swaddr(kcur, krow + nt2 * 16,
                                      pob[part] + ks * 2 + ku));
                        mma16816(s[nt2 * 2],     qf[part * 2 + ks], b0, b1);
                        mma16816(s[nt2 * 2 + 1], qf[part * 2 + ks], b2, b3);
                    }
                }
        }

        // ---- partial row max over this j-half ----
#pragma unroll
        for (int h = 0; h < 2; h++) {
            float t = -1e30f;
#pragma unroll
            for (int nt = 0; nt < 4; nt++)
                t = fmaxf(t, fmaxf(s[nt][2 * h], s[nt][2 * h + 1]));
            t = fmaxf(t, __shfl_xor_sync(0xffffffffu, t, 1));
            t = fmaxf(t, __shfl_xor_sync(0xffffffffu, t, 2));
            if ((lane & 3) == 0) pmS[wh][wq * 16 + r0 + h * 8] = t;
        }
        __syncthreads();                    // (2) pm ready

        // ---- combine stats, exp, write P + partial sums + corrS ----
#pragma unroll
        for (int h = 0; h < 2; h++) {
            const int row = wq * 16 + r0 + h * 8;
            float mold = Mb[par][row];
            float mn = fmaxf(mold, fmaxf(pmS[0][row], pmS[1][row]));
            float corr = __expf(mold - mn);
            float lp = 0.f;
#pragma unroll
            for (int nt = 0; nt < 4; nt++) {
                float p0 = __expf(s[nt][2 * h]     - mn);
                float p1 = __expf(s[nt][2 * h + 1] - mn);
                lp += p0 + p1;
                int col = wh * 32 + nt * 8 + 2 * (lane & 3);
                int byte = col * 2;
                sts32(swaddr(ptile, row, byte >> 4) + (byte & 15), pkh2(p0, p1));
            }
            lp += __shfl_xor_sync(0xffffffffu, lp, 1);
            lp += __shfl_xor_sync(0xffffffffu, lp, 2);
            if ((lane & 3) == 0) {
                plS[wh][row] = lp;
                if (wh == 0) { Mb[nxt][row] = mn; corrS[row] = corr; }
            }
        }
        __syncthreads();                    // (3) ptile + pl + Mnew + corr ready

        if (tid < 64) {
            float corr = __expf(Mb[par][tid] - Mb[nxt][tid]);
            Lb[nxt][tid] = Lb[par][tid] * corr + plS[0][tid] + plS[1][tid];
        }

        // ---- PV (transposed): acc(c,q) += V(c,j) P(q,j)^T ----
        {
            // per-q rescale of c-major acc using corrS (float2 per q-pair)
            const float2* c2 = (const float2*)corrS;
            const int qoff = lane & 3;      // q pair index base = nt*4 + qoff
#pragma unroll
            for (int nf = 0; nf < 8; nf++) {
                float2 cc = c2[nf * 4 + qoff];
#pragma unroll
                for (int ct = 0; ct < 2; ct++) {
                    acc[ct][nf][0] *= cc.x;
                    acc[ct][nf][1] *= cc.y;
                    acc[ct][nf][2] *= cc.x;
                    acc[ct][nf][3] *= cc.y;
                }
            }
            const uint32_t vcur = vbuf[par];
#pragma unroll
            for (int ks = 0; ks < 4; ks++) {
                uint32_t a0[4], a1[4];
                ldm_x4(a0[0], a0[1], a0[2], a0[3],
                       swaddr(vcur, varow,      vau + ks * 2));
                ldm_x4(a1[0], a1[1], a1[2], a1[3],
                       swaddr(vcur, varow + 16, vau + ks * 2));
#pragma unroll
                for (int qt = 0; qt < 4; qt++) {
                    uint32_t b0, b1, b2, b3;
                    ldm_x4(b0, b1, b2, b3,
                           swaddr(ptile, pbrow + qt * 16, pbu + ks * 2));
                    mma16816(acc[0][qt * 2],     a0, b0, b1);
                    mma16816(acc[0][qt * 2 + 1], a0, b2, b3);
                    mma16816(acc[1][qt * 2],     a1, b0, b1);
                    mma16816(acc[1][qt * 2 + 1], a1, b2, b3);
                }
            }
        }
    }
    __syncthreads();                        // final Lb[0] ready (NTJ even)

    // ---- epilogue: per-q normalize + residual, float2 stores ----
    {
        const float2* l2 = (const float2*)Lb[0];
        const int qoff = lane & 3;
#pragma unroll
        for (int nf = 0; nf < 8; nf++) {
            float2 lv = l2[nf * 4 + qoff];
            float inv0 = 1.f / lv.x, inv1 = 1.f / lv.y;
            int q = q0 + nf * 8 + 2 * qoff;
#pragma unroll
            for (int ct = 0; ct < 2; ct++) {
                int c = w * 32 + ct * 16 + (lane >> 2);
                size_t i00 = ((size_t)b * CC + c) * NN + q;
                float2 xr0 = *(const float2*)(x + i00);
                float2 o0;
                o0.x = acc[ct][nf][0] * inv0 + xr0.x;
                o0.y = acc[ct][nf][1] * inv1 + xr0.y;
                *(float2*)(out + i00) = o0;
                size_t i08 = i00 + (size_t)8 * NN;
                float2 xr1 = *(const float2*)(x + i08);
                float2 o1;
                o1.x = acc[ct][nf][2] * inv0 + xr1.x;
                o1.y = acc[ct][nf][3] * inv1 + xr1.y;
                *(float2*)(out + i08) = o1;
            }
        }
    }
}

// ---------------------------------------------------------------------------
extern "C" void kernel_launch(void* const* d_in, const int* in_sizes, int n_in,
                              void* d_out, int out_size)
{
    const float* x  = (const float*)d_in[0];
    const float* Wq = (const float*)d_in[1];
    const float* Wk = (const float*)d_in[2];
    const float* Wv = (const float*)d_in[3];
    float* out = (float*)d_out;

    cudaFuncSetAttribute(fattn_kernel,
                         cudaFuncAttributeMaxDynamicSharedMemorySize, FA_SMEM);
    cudaFuncSetAttribute(proj_v_mma_kernel,
                         cudaFuncAttributeMaxDynamicSharedMemorySize, PVW_SMEM);

    wsplit_kernel    <<<64, 256>>>(Wv);
    proj_qk_kernel   <<<dim3(NN / 64, 1, BB), 256>>>(x, Wq, Wk);
    proj_v_mma_kernel<<<dim3(NN / 128, CC / 128, BB), 256, PVW_SMEM>>>(x);
    fattn_kernel     <<<dim3(NN / 64, 1, BB), 256, FA_SMEM>>>(x, out);
}

// round 13
// speedup vs baseline: 9.2687x; 1.0245x over previous
#include <cuda_runtime.h>
#include <cuda_fp16.h>
#include <math.h>
#include <stdint.h>

#define BB 4
#define CC 256
#define NN 4096

// ---------------- scratch (__device__ globals; no allocs allowed) ----------
__device__ __half g_qh[(size_t)BB * NN * 64];   // [b][n][32 q_hi | 32 q_lo] (2 MB)
__device__ __half g_kh[(size_t)BB * NN * 64];   // [b][n][32 k_hi | 32 k_lo] (2 MB)
__device__ __half g_vh[(size_t)BB * CC * NN];   // [b][c][j] fp16 V (8 MB)
__device__ __half g_wvh[CC * CC];               // Wv hi (128 KB)
__device__ __half g_wvl[CC * CC];               // Wv lo (128 KB)
__device__ __half g_wqkh[64 * CC];              // [Wq;Wk] hi (32 KB)
__device__ __half g_wqkl[64 * CC];              // [Wq;Wk] lo (32 KB)

// ---------------- helpers ---------------------------------------------------
__device__ __forceinline__ uint32_t smem_u32(const void* p) {
    uint32_t a;
    asm("{ .reg .u64 t; cvta.to.shared.u64 t, %1; cvt.u32.u64 %0, t; }"
        : "=r"(a) : "l"(p));
    return a;
}
__device__ __forceinline__ void cp16(uint32_t dst, const void* src) {
    asm volatile("cp.async.cg.shared.global [%0], [%1], 16;" :: "r"(dst), "l"(src)
                 : "memory");
}
__device__ __forceinline__ void sts16(uint32_t a, __half v) {
    unsigned short u = *reinterpret_cast<unsigned short*>(&v);
    asm volatile("st.shared.u16 [%0], %1;" :: "r"(a), "h"(u) : "memory");
}
__device__ __forceinline__ void sts32(uint32_t a, uint32_t v) {
    asm volatile("st.shared.u32 [%0], %1;" :: "r"(a), "r"(v) : "memory");
}
__device__ __forceinline__ uint32_t swaddr(uint32_t base, int row, int u) {
    return base + row * 128 + (((u) ^ (row & 7)) << 4);
}
__device__ __forceinline__ void ldm_x4(uint32_t& r0, uint32_t& r1,
                                       uint32_t& r2, uint32_t& r3, uint32_t a) {
    asm volatile("ldmatrix.sync.aligned.m8n8.x4.shared.b16 {%0,%1,%2,%3}, [%4];"
                 : "=r"(r0), "=r"(r1), "=r"(r2), "=r"(r3) : "r"(a));
}
__device__ __forceinline__ void mma16816(float* d, const uint32_t* a,
                                         uint32_t b0, uint32_t b1) {
    asm volatile(
        "mma.sync.aligned.m16n8k16.row.col.f32.f16.f16.f32 "
        "{%0,%1,%2,%3}, {%4,%5,%6,%7}, {%8,%9}, {%0,%1,%2,%3};"
        : "+f"(d[0]), "+f"(d[1]), "+f"(d[2]), "+f"(d[3])
        : "r"(a[0]), "r"(a[1]), "r"(a[2]), "r"(a[3]), "r"(b0), "r"(b1));
}
__device__ __forceinline__ uint32_t pkh2(float a, float b) {
    __half2 h = __floats2half2_rn(a, b);
    return *reinterpret_cast<uint32_t*>(&h);
}

// ---------------------------------------------------------------------------
// wsplit: Wv fp32 -> hi/lo fp16
// ---------------------------------------------------------------------------
__global__ __launch_bounds__(256) void wsplit_kernel(const float* __restrict__ Wv)
{
    int e4 = blockIdx.x * 256 + threadIdx.x;
    float4 v = ((const float4*)Wv)[e4];
    int base = e4 * 4;
    float f[4] = {v.x, v.y, v.z, v.w};
#pragma unroll
    for (int t = 0; t < 4; t++) {
        __half hi = __float2half_rn(f[t]);
        __half lo = __float2half_rn(f[t] - __half2float(hi));
        g_wvh[base + t] = hi;
        g_wvl[base + t] = lo;
    }
}

// wsplit_qk: [Wq;Wk] fp32 -> hi/lo fp16 (combined 64x256)
__global__ __launch_bounds__(256) void wsplit_qk_kernel(
    const float* __restrict__ Wq, const float* __restrict__ Wk)
{
    int e4 = blockIdx.x * 256 + threadIdx.x;   // 16 blocks -> 4096 float4
    float4 v = (e4 < 2048) ? ((const float4*)Wq)[e4]
                           : ((const float4*)Wk)[e4 - 2048];
    int base = e4 * 4;
    float f[4] = {v.x, v.y, v.z, v.w};
#pragma unroll
    for (int t = 0; t < 4; t++) {
        __half hi = __float2half_rn(f[t]);
        __half lo = __float2half_rn(f[t] - __half2float(hi));
        g_wqkh[base + t] = hi;
        g_wqkl[base + t] = lo;
    }
}

// ---------------------------------------------------------------------------
// proj_qk_mma: [q;k][o, n] = [Wq;Wk] x via split-fp16 mma.
// CTA 64c x 128n. Epilogue: split fp32 result -> hi/lo fp16 into g_qh/g_kh.
// ---------------------------------------------------------------------------
#define PQK_SMEM (2 * 8192 + 2 * 16384 + 256)

__global__ __launch_bounds__(256) void proj_qk_mma_kernel(
    const float* __restrict__ x)
{
    extern __shared__ char dsm[];
    const int b = blockIdx.z, n0 = blockIdx.x * 128;
    const int tid = threadIdx.x, wid = tid >> 5, lane = tid & 31;
    const int wcc = wid >> 2, wn = wid & 3;    // wcc 0..1 (32c), wn 0..3 (32n)
    const uint32_t whb = (smem_u32(dsm) + 127) & ~127u;
    const uint32_t wlb = whb + 8192;
    const uint32_t xhb = wlb + 8192;
    const uint32_t xlb = xhb + 16384;

    float acc[2][4][4];
#pragma unroll
    for (int i = 0; i < 2; i++)
#pragma unroll
        for (int j = 0; j < 4; j++)
#pragma unroll
            for (int k = 0; k < 4; k++) acc[i][j][k] = 0.f;

    const int a_row = wcc * 32 + (lane & 15);
    const int a_uo  = lane >> 4;
    const int b_row = wn * 32 + (lane & 7) + ((lane >> 4) << 3);
    const int b_uo  = (lane >> 3) & 1;

    for (int kc = 0; kc < 4; kc++) {
        __syncthreads();
        // W tiles: 64 rows x 8 units each buffer
#pragma unroll
        for (int i = 0; i < 2; i++) {
            int e = tid + i * 256, row = e >> 3, u = e & 7;
            cp16(swaddr(whb, row, u), g_wqkh + (size_t)row * CC + kc * 64 + u * 8);
            cp16(swaddr(wlb, row, u), g_wqkl + (size_t)row * CC + kc * 64 + u * 8);
        }
        asm volatile("cp.async.commit_group;" ::: "memory");

        // x chunk transpose+split (identical to proj_v_mma)
#pragma unroll
        for (int i = 0; i < 8; i++) {
            int e = tid + i * 256;
            int k = e >> 5, n4 = (e & 31) * 4;
            const float* src = x + ((size_t)b * CC + kc * 64 + k) * NN + n0 + n4;
            float4 v = *(const float4*)src;
            float f[4] = {v.x, v.y, v.z, v.w};
            uint32_t ucol = (uint32_t)(k >> 3);
            uint32_t boff = (uint32_t)(k & 7) * 2;
#pragma unroll
            for (int t = 0; t < 4; t++) {
                __half hi = __float2half_rn(f[t]);
                __half lo = __float2half_rn(f[t] - __half2float(hi));
                sts16(swaddr(xhb, n4 + t, ucol) + boff, hi);
                sts16(swaddr(xlb, n4 + t, ucol) + boff, lo);
            }
        }
        asm volatile("cp.async.wait_group 0;" ::: "memory");
        __syncthreads();

#pragma unroll
        for (int ks = 0; ks < 4; ks++) {
            uint32_t ah[2][4], al[2][4];
#pragma unroll
            for (int qt = 0; qt < 2; qt++) {
                ldm_x4(ah[qt][0], ah[qt][1], ah[qt][2], ah[qt][3],
                       swaddr(whb, a_row + qt * 16, a_uo + ks * 2));
                ldm_x4(al[qt][0], al[qt][1], al[qt][2], al[qt][3],
                       swaddr(wlb, a_row + qt * 16, a_uo + ks * 2));
            }
            uint32_t bh[4][2], bl[4][2];
#pragma unroll
            for (int nt2 = 0; nt2 < 2; nt2++) {
                uint32_t r0, r1, r2, r3;
                ldm_x4(r0, r1, r2, r3,
                       swaddr(xhb, b_row + nt2 * 16, b_uo + ks * 2));
                bh[nt2 * 2][0] = r0;     bh[nt2 * 2][1] = r1;
                bh[nt2 * 2 + 1][0] = r2; bh[nt2 * 2 + 1][1] = r3;
                ldm_x4(r0, r1, r2, r3,
                       swaddr(xlb, b_row + nt2 * 16, b_uo + ks * 2));
                bl[nt2 * 2][0] = r0;     bl[nt2 * 2][1] = r1;
                bl[nt2 * 2 + 1][0] = r2; bl[nt2 * 2 + 1][1] = r3;
            }
#pragma unroll
            for (int qt = 0; qt < 2; qt++)
#pragma unroll
                for (int nt = 0; nt < 4; nt++) {
                    mma16816(acc[qt][nt], ah[qt], bh[nt][0], bh[nt][1]);
                    mma16816(acc[qt][nt], al[qt], bh[nt][0], bh[nt][1]);
                    mma16816(acc[qt][nt], ah[qt], bl[nt][0], bl[nt][1]);
                }
        }
    }

    // epilogue: split each fp32 value to hi/lo fp16, write g_qh / g_kh
#pragma unroll
    for (int qt = 0; qt < 2; qt++)
#pragma unroll
        for (int nt = 0; nt < 4; nt++) {
            int o_base = wcc * 32 + qt * 16 + (lane >> 2);
            int n_base = n0 + wn * 32 + nt * 8 + 2 * (lane & 3);
#pragma unroll
            for (int dd = 0; dd < 4; dd++) {
                int o = o_base + ((dd >> 1) << 3);   // +8 for dd=2,3
                int n = n_base + (dd & 1);
                float a = acc[qt][nt][dd];
                __half hi = __float2half_rn(a);
                __half lo = __float2half_rn(a - __half2float(hi));
                size_t base = ((size_t)b * NN + n) * 64;
                if (o < 32) { g_qh[base + o] = hi;      g_qh[base + 32 + o] = lo; }
                else        { g_kh[base + o - 32] = hi; g_kh[base + o] = lo; }
            }
        }
}

// ---------------------------------------------------------------------------
// proj_v_mma: V[c, n] = Wv x via split-fp16 mma (proven round 8)
// ---------------------------------------------------------------------------
#define PVW_SMEM (4 * 16384 + 256)

__global__ __launch_bounds__(256) void proj_v_mma_kernel(
    const float* __restrict__ x)
{
    extern __shared__ char dsm[];
    const int b = blockIdx.z, n0 = blockIdx.x * 128, c0 = blockIdx.y * 128;
    const int tid = threadIdx.x, wid = tid >> 5, lane = tid & 31;
    const int wcc = wid >> 2, wn = wid & 3;
    const uint32_t whb = (smem_u32(dsm) + 127) & ~127u;
    const uint32_t wlb = whb + 16384;
    const uint32_t xhb = wlb + 16384;
    const uint32_t xlb = xhb + 16384;

    float acc[4][4][4];
#pragma unroll
    for (int i = 0; i < 4; i++)
#pragma unroll
        for (int j = 0; j < 4; j++)
#pragma unroll
            for (int k = 0; k < 4; k++) acc[i][j][k] = 0.f;

    const int a_row = wcc * 64 + (lane & 15);
    const int a_uo  = lane >> 4;
    const int b_row = wn * 32 + (lane & 7) + ((lane >> 4) << 3);
    const int b_uo  = (lane >> 3) & 1;

    for (int kc = 0; kc < 4; kc++) {
        __syncthreads();
#pragma unroll
        for (int i = 0; i < 4; i++) {
            int e = tid + i * 256, row = e >> 3, u = e & 7;
            const __half* sh = g_wvh + (size_t)(c0 + row) * CC + kc * 64 + u * 8;
            const __half* sl = g_wvl + (size_t)(c0 + row) * CC + kc * 64 + u * 8;
            cp16(swaddr(whb, row, u), sh);
            cp16(swaddr(wlb, row, u), sl);
        }
        asm volatile("cp.async.commit_group;" ::: "memory");

#pragma unroll
        for (int i = 0; i < 8; i++) {
            int e = tid + i * 256;
            int k = e >> 5, n4 = (e & 31) * 4;
            const float* src = x + ((size_t)b * CC + kc * 64 + k) * NN + n0 + n4;
            float4 v = *(const float4*)src;
            float f[4] = {v.x, v.y, v.z, v.w};
            uint32_t ucol = (uint32_t)(k >> 3);
            uint32_t boff = (uint32_t)(k & 7) * 2;
#pragma unroll
            for (int t = 0; t < 4; t++) {
                __half hi = __float2half_rn(f[t]);
                __half lo = __float2half_rn(f[t] - __half2float(hi));
                sts16(swaddr(xhb, n4 + t, ucol) + boff, hi);
                sts16(swaddr(xlb, n4 + t, ucol) + boff, lo);
            }
        }
        asm volatile("cp.async.wait_group 0;" ::: "memory");
        __syncthreads();

#pragma unroll
        for (int ks = 0; ks < 4; ks++) {
            uint32_t ah[4][4], al[4][4];
#pragma unroll
            for (int qt = 0; qt < 4; qt++) {
                ldm_x4(ah[qt][0], ah[qt][1], ah[qt][2], ah[qt][3],
                       swaddr(whb, a_row + qt * 16, a_uo + ks * 2));
                ldm_x4(al[qt][0], al[qt][1], al[qt][2], al[qt][3],
                       swaddr(wlb, a_row + qt * 16, a_uo + ks * 2));
            }
            uint32_t bh[4][2], bl[4][2];
#pragma unroll
            for (int nt2 = 0; nt2 < 2; nt2++) {
                uint32_t r0, r1, r2, r3;
                ldm_x4(r0, r1, r2, r3,
                       swaddr(xhb, b_row + nt2 * 16, b_uo + ks * 2));
                bh[nt2 * 2][0] = r0;     bh[nt2 * 2][1] = r1;
                bh[nt2 * 2 + 1][0] = r2; bh[nt2 * 2 + 1][1] = r3;
                ldm_x4(r0, r1, r2, r3,
                       swaddr(xlb, b_row + nt2 * 16, b_uo + ks * 2));
                bl[nt2 * 2][0] = r0;     bl[nt2 * 2][1] = r1;
                bl[nt2 * 2 + 1][0] = r2; bl[nt2 * 2 + 1][1] = r3;
            }
#pragma unroll
            for (int qt = 0; qt < 4; qt++)
#pragma unroll
                for (int nt = 0; nt < 4; nt++) {
                    mma16816(acc[qt][nt], ah[qt], bh[nt][0], bh[nt][1]);
                    mma16816(acc[qt][nt], al[qt], bh[nt][0], bh[nt][1]);
                    mma16816(acc[qt][nt], ah[qt], bl[nt][0], bl[nt][1]);
                }
        }
    }

#pragma unroll
    for (int qt = 0; qt < 4; qt++)
#pragma unroll
        for (int nt = 0; nt < 4; nt++) {
            int c = c0 + wcc * 64 + qt * 16 + (lane >> 2);
            int n = n0 + wn * 32 + nt * 8 + 2 * (lane & 3);
            *(uint32_t*)(g_vh + ((size_t)b * CC + c) * NN + n) =
                pkh2(acc[qt][nt][0], acc[qt][nt][1]);
            *(uint32_t*)(g_vh + ((size_t)b * CC + c + 8) * NN + n) =
                pkh2(acc[qt][nt][2], acc[qt][nt][3]);
        }
}

// ---------------------------------------------------------------------------
// fattn: fused flash attention + residual (round 12 proven + skip-rescale)
// ---------------------------------------------------------------------------
#define FA_SMEM (8192 + 2 * 8192 + 2 * 32768 + 8192 + 128)

__device__ __forceinline__ void fa_load_kv(uint32_t kbuf, uint32_t vbuf,
                                           int b, int jt, int tid)
{
    const __half* ksrc = g_kh + ((size_t)b * NN + jt * 64) * 64;
#pragma unroll
    for (int rr = 0; rr < 2; rr++) {
        int e = tid + rr * 256, row = e >> 3, u = e & 7;
        cp16(swaddr(kbuf, row, u), ksrc + (size_t)row * 64 + u * 8);
    }
    const __half* vsrc = g_vh + (size_t)b * CC * NN + jt * 64;
#pragma unroll
    for (int rr = 0; rr < 8; rr++) {
        int e = tid + rr * 256, row = e >> 3, u = e & 7;
        cp16(swaddr(vbuf, row, u), vsrc + (size_t)row * NN + u * 8);
    }
    asm volatile("cp.async.commit_group;" ::: "memory");
}

__global__ __launch_bounds__(256, 2) void fattn_kernel(
    const float* __restrict__ x, float* __restrict__ out)
{
    extern __shared__ char dsm[];
    __shared__ float Mb[2][64], Lb[2][64];
    __shared__ float pmS[2][64], plS[2][64];
    __shared__ float corrS[64];

    const int b = blockIdx.z, q0 = blockIdx.x * 64;
    const int tid = threadIdx.x, w = tid >> 5, lane = tid & 31;
    const int wq = w & 3, wh = w >> 2;
    const uint32_t qb = (smem_u32(dsm) + 127) & ~127u;
    const uint32_t kbuf[2] = {qb + 8192,  qb + 16384};
    const uint32_t vbuf[2] = {qb + 24576, qb + 57344};
    const uint32_t ptile   = qb + 90112;

    {
        const __half* qsrc = g_qh + ((size_t)b * NN + q0) * 64;
#pragma unroll
        for (int rr = 0; rr < 2; rr++) {
            int e = tid + rr * 256, row = e >> 3, u = e & 7;
            cp16(swaddr(qb, row, u), qsrc + (size_t)row * 64 + u * 8);
        }
        asm volatile("cp.async.commit_group;" ::: "memory");
    }
    fa_load_kv(kbuf[0], vbuf[0], b, 0, tid);
    if (tid < 64) { Mb[0][tid] = -1e30f; Lb[0][tid] = 0.f; }

    const int arow = wq * 16 + (lane & 15);
    const int au   = lane >> 4;
    uint32_t qf[6][4];
    {
        asm volatile("cp.async.wait_group 1;" ::: "memory");
        __syncthreads();
        const int poa[3] = {0, 0, 4};
#pragma unroll
        for (int part = 0; part < 3; part++)
#pragma unroll
            for (int ks = 0; ks < 2; ks++)
                ldm_x4(qf[part * 2 + ks][0], qf[part * 2 + ks][1],
                       qf[part * 2 + ks][2], qf[part * 2 + ks][3],
                       swaddr(qb, arow, poa[part] + ks * 2 + au));
    }

    float acc[2][8][4];
#pragma unroll
    for (int i = 0; i < 2; i++)
#pragma unroll
        for (int j = 0; j < 8; j++)
#pragma unroll
            for (int k = 0; k < 4; k++) acc[i][j][k] = 0.f;

    const int krow = wh * 32 + (lane & 7) + ((lane >> 4) << 3);
    const int ku   = (lane >> 3) & 1;
    const int varow = w * 32 + (lane & 15);
    const int vau   = lane >> 4;
    const int pbrow = (lane & 7) + ((lane >> 4) << 3);
    const int pbu   = (lane >> 3) & 1;
    const int r0   = lane >> 2;

    const int NTJ = NN / 64;
    for (int jt = 0; jt < NTJ; jt++) {
        const int par = jt & 1, nxt = par ^ 1;

        asm volatile("cp.async.wait_group 0;" ::: "memory");
        __syncthreads();            // (1)

        if (jt + 1 < NTJ)
            fa_load_kv(kbuf[nxt], vbuf[nxt], b, jt + 1, tid);

        // ---- S ----
        float s[4][4];
#pragma unroll
        for (int i = 0; i < 4; i++)
#pragma unroll
            for (int k = 0; k < 4; k++) s[i][k] = 0.f;
        {
            const int pob[3] = {0, 4, 0};
            const uint32_t kcur = kbuf[par];
#pragma unroll
            for (int part = 0; part < 3; part++)
#pragma unroll
                for (int ks = 0; ks < 2; ks++) {
#pragma unroll
                    for (int nt2 = 0; nt2 < 2; nt2++) {
                        uint32_t b0, b1, b2, b3;
                        ldm_x4(b0, b1, b2, b3,
                               swaddr(kcur, krow + nt2 * 16,
                                      pob[part] + ks * 2 + ku));
                        mma16816(s[nt2 * 2],     qf[part * 2 + ks], b0, b1);
                        mma16816(s[nt2 * 2 + 1], qf[part * 2 + ks], b2, b3);
                    }
                }
        }

        // ---- partial row max ----
#pragma unroll
        for (int h = 0; h < 2; h++) {
            float t = -1e30f;
#pragma unroll
            for (int nt = 0; nt < 4; nt++)
                t = fmaxf(t, fmaxf(s[nt][2 * h], s[nt][2 * h + 1]));
            t = fmaxf(t, __shfl_xor_sync(0xffffffffu, t, 1));
            t = fmaxf(t, __shfl_xor_sync(0xffffffffu, t, 2));
            if ((lane & 3) == 0) pmS[wh][wq * 16 + r0 + h * 8] = t;
        }
        __syncthreads();                    // (2)

        // ---- stats + exp + P + corr ----
#pragma unroll
        for (int h = 0; h < 2; h++) {
            const int row = wq * 16 + r0 + h * 8;
            float mold = Mb[par][row];
            float mn = fmaxf(mold, fmaxf(pmS[0][row], pmS[1][row]));
            float corr = __expf(mold - mn);
            float lp = 0.f;
#pragma unroll
            for (int nt = 0; nt < 4; nt++) {
                float p0 = __expf(s[nt][2 * h]     - mn);
                float p1 = __expf(s[nt][2 * h + 1] - mn);
                lp += p0 + p1;
                int col = wh * 32 + nt * 8 + 2 * (lane & 3);
                int byte = col * 2;
                sts32(swaddr(ptile, row, byte >> 4) + (byte & 15), pkh2(p0, p1));
            }
            lp += __shfl_xor_sync(0xffffffffu, lp, 1);
            lp += __shfl_xor_sync(0xffffffffu, lp, 2);
            if ((lane & 3) == 0) {
                plS[wh][row] = lp;
                if (wh == 0) { Mb[nxt][row] = mn; corrS[row] = corr; }
            }
        }
        __syncthreads();                    // (3)

        if (tid < 64) {
            float corr = __expf(Mb[par][tid] - Mb[nxt][tid]);
            Lb[nxt][tid] = Lb[par][tid] * corr + plS[0][tid] + plS[1][tid];
        }

        // ---- PV (transposed): acc(c,q) += V(c,j) P(q,j)^T ----
        {
            // skip-rescale: corr == 1.0 exactly once the row max stabilizes
            const float2* c2 = (const float2*)corrS;
            const int qoff = lane & 3;
            float2 ccv[8];
            bool anyc = false;
#pragma unroll
            for (int nf = 0; nf < 8; nf++) {
                ccv[nf] = c2[nf * 4 + qoff];
                anyc = anyc || (ccv[nf].x != 1.f) || (ccv[nf].y != 1.f);
            }
            if (__any_sync(0xffffffffu, anyc)) {
#pragma unroll
                for (int nf = 0; nf < 8; nf++)
#pragma unroll
                    for (int ct = 0; ct < 2; ct++) {
                        acc[ct][nf][0] *= ccv[nf].x;
                        acc[ct][nf][1] *= ccv[nf].y;
                        acc[ct][nf][2] *= ccv[nf].x;
                        acc[ct][nf][3] *= ccv[nf].y;
                    }
            }
            const uint32_t vcur = vbuf[par];
#pragma unroll
            for (int ks = 0; ks < 4; ks++) {
                uint32_t a0[4], a1[4];
                ldm_x4(a0[0], a0[1], a0[2], a0[3],
                       swaddr(vcur, varow,      vau + ks * 2));
                ldm_x4(a1[0], a1[1], a1[2], a1[3],
                       swaddr(vcur, varow + 16, vau + ks * 2));
#pragma unroll
                for (int qt = 0; qt < 4; qt++) {
                    uint32_t b0, b1, b2, b3;
                    ldm_x4(b0, b1, b2, b3,
                           swaddr(ptile, pbrow + qt * 16, pbu + ks * 2));
                    mma16816(acc[0][qt * 2],     a0, b0, b1);
                    mma16816(acc[0][qt * 2 + 1], a0, b2, b3);
                    mma16816(acc[1][qt * 2],     a1, b0, b1);
                    mma16816(acc[1][qt * 2 + 1], a1, b2, b3);
                }
            }
        }
    }
    __syncthreads();

    // ---- epilogue ----
    {
        const float2* l2 = (const float2*)Lb[0];
        const int qoff = lane & 3;
#pragma unroll
        for (int nf = 0; nf < 8; nf++) {
            float2 lv = l2[nf * 4 + qoff];
            float inv0 = 1.f / lv.x, inv1 = 1.f / lv.y;
            int q = q0 + nf * 8 + 2 * qoff;
#pragma unroll
            for (int ct = 0; ct < 2; ct++) {
                int c = w * 32 + ct * 16 + (lane >> 2);
                size_t i00 = ((size_t)b * CC + c) * NN + q;
                float2 xr0 = *(const float2*)(x + i00);
                float2 o0;
                o0.x = acc[ct][nf][0] * inv0 + xr0.x;
                o0.y = acc[ct][nf][1] * inv1 + xr0.y;
                *(float2*)(out + i00) = o0;
                size_t i08 = i00 + (size_t)8 * NN;
                float2 xr1 = *(const float2*)(x + i08);
                float2 o1;
                o1.x = acc[ct][nf][2] * inv0 + xr1.x;
                o1.y = acc[ct][nf][3] * inv1 + xr1.y;
                *(float2*)(out + i08) = o1;
            }
        }
    }
}

// ---------------------------------------------------------------------------
extern "C" void kernel_launch(void* const* d_in, const int* in_sizes, int n_in,
                              void* d_out, int out_size)
{
    const float* x  = (const float*)d_in[0];
    const float* Wq = (const float*)d_in[1];
    const float* Wk = (const float*)d_in[2];
    const float* Wv = (const float*)d_in[3];
    float* out = (float*)d_out;

    cudaFuncSetAttribute(fattn_kernel,
                         cudaFuncAttributeMaxDynamicSharedMemorySize, FA_SMEM);
    cudaFuncSetAttribute(proj_v_mma_kernel,
                         cudaFuncAttributeMaxDynamicSharedMemorySize, PVW_SMEM);
    cudaFuncSetAttribute(proj_qk_mma_kernel,
                         cudaFuncAttributeMaxDynamicSharedMemorySize, PQK_SMEM);

    wsplit_kernel     <<<64, 256>>>(Wv);
    wsplit_qk_kernel  <<<16, 256>>>(Wq, Wk);
    proj_qk_mma_kernel<<<dim3(NN / 128, 1, BB), 256, PQK_SMEM>>>(x);
    proj_v_mma_kernel <<<dim3(NN / 128, CC / 128, BB), 256, PVW_SMEM>>>(x);
    fattn_kernel      <<<dim3(NN / 64, 1, BB), 256, FA_SMEM>>>(x, out);
}

// round 14
// speedup vs baseline: 11.1968x; 1.2080x over previous
#include <cuda_runtime.h>
#include <cuda_fp16.h>
#include <math.h>
#include <stdint.h>

#define BB 4
#define CC 256
#define NN 4096

// ---------------- scratch (__device__ globals; no allocs allowed) ----------
__device__ __half g_qh[(size_t)BB * NN * 64];   // [b][n][32 q_hi | 32 q_lo] (2 MB)
__device__ __half g_kh[(size_t)BB * NN * 64];   // [b][n][32 k_hi | 32 k_lo] (2 MB)
__device__ __half g_vh[(size_t)BB * CC * NN];   // [b][c][j] fp16 V (8 MB)
__device__ __half g_wvh[CC * CC];               // Wv hi (128 KB)
__device__ __half g_wvl[CC * CC];               // Wv lo (128 KB)
__device__ __half g_wqkh[64 * CC];              // [Wq;Wk] hi (32 KB)
__device__ __half g_wqkl[64 * CC];              // [Wq;Wk] lo (32 KB)

// ---------------- helpers ---------------------------------------------------
__device__ __forceinline__ uint32_t smem_u32(const void* p) {
    uint32_t a;
    asm("{ .reg .u64 t; cvta.to.shared.u64 t, %1; cvt.u32.u64 %0, t; }"
        : "=r"(a) : "l"(p));
    return a;
}
__device__ __forceinline__ void cp16(uint32_t dst, const void* src) {
    asm volatile("cp.async.cg.shared.global [%0], [%1], 16;" :: "r"(dst), "l"(src)
                 : "memory");
}
__device__ __forceinline__ void sts32(uint32_t a, uint32_t v) {
    asm volatile("st.shared.u32 [%0], %1;" :: "r"(a), "r"(v) : "memory");
}
__device__ __forceinline__ void sts128(uint32_t a, uint32_t r0, uint32_t r1,
                                       uint32_t r2, uint32_t r3) {
    asm volatile("st.shared.v4.b32 [%0], {%1,%2,%3,%4};"
                 :: "r"(a), "r"(r0), "r"(r1), "r"(r2), "r"(r3) : "memory");
}
__device__ __forceinline__ uint32_t swaddr(uint32_t base, int row, int u) {
    return base + row * 128 + (((u) ^ (row & 7)) << 4);
}
__device__ __forceinline__ void ldm_x4(uint32_t& r0, uint32_t& r1,
                                       uint32_t& r2, uint32_t& r3, uint32_t a) {
    asm volatile("ldmatrix.sync.aligned.m8n8.x4.shared.b16 {%0,%1,%2,%3}, [%4];"
                 : "=r"(r0), "=r"(r1), "=r"(r2), "=r"(r3) : "r"(a));
}
__device__ __forceinline__ void mma16816(float* d, const uint32_t* a,
                                         uint32_t b0, uint32_t b1) {
    asm volatile(
        "mma.sync.aligned.m16n8k16.row.col.f32.f16.f16.f32 "
        "{%0,%1,%2,%3}, {%4,%5,%6,%7}, {%8,%9}, {%0,%1,%2,%3};"
        : "+f"(d[0]), "+f"(d[1]), "+f"(d[2]), "+f"(d[3])
        : "r"(a[0]), "r"(a[1]), "r"(a[2]), "r"(a[3]), "r"(b0), "r"(b1));
}
__device__ __forceinline__ uint32_t pkh2(float a, float b) {
    __half2 h = __floats2half2_rn(a, b);
    return *reinterpret_cast<uint32_t*>(&h);
}
__device__ __forceinline__ uint32_t packh(__half a, __half b) {
    __half2 h = __halves2half2(a, b);
    return *reinterpret_cast<uint32_t*>(&h);
}

// conflict-free x chunk staging: transpose + hi/lo split.
// thread = (row n = tid&127, k-half = tid>>7); 4 octets of 8 k; 16B v4 stores.
// Layout identical to previous staging: unit u holds k = 8u..8u+7.
__device__ __forceinline__ void stage_x_chunk(
    const float* __restrict__ x, int b, int kc, int n0,
    uint32_t xhb, uint32_t xlb, int tid)
{
    const int n = tid & 127, khalf = tid >> 7;
    const float* xcol =
        x + ((size_t)b * CC + kc * 64 + khalf * 32) * NN + n0 + n;
#pragma unroll
    for (int oct = 0; oct < 4; oct++) {
        float f[8];
#pragma unroll
        for (int j = 0; j < 8; j++)
            f[j] = xcol[(size_t)(oct * 8 + j) * NN];
        uint32_t hh[4], ll[4];
#pragma unroll
        for (int p = 0; p < 4; p++) {
            __half h0 = __float2half_rn(f[2 * p]);
            __half h1 = __float2half_rn(f[2 * p + 1]);
            hh[p] = packh(h0, h1);
            ll[p] = pkh2(f[2 * p]     - __half2float(h0),
                         f[2 * p + 1] - __half2float(h1));
        }
        int u = khalf * 4 + oct;
        sts128(swaddr(xhb, n, u), hh[0], hh[1], hh[2], hh[3]);
        sts128(swaddr(xlb, n, u), ll[0], ll[1], ll[2], ll[3]);
    }
}

// ---------------------------------------------------------------------------
// wsplit: Wv fp32 -> hi/lo fp16
// ---------------------------------------------------------------------------
__global__ __launch_bounds__(256) void wsplit_kernel(const float* __restrict__ Wv)
{
    int e4 = blockIdx.x * 256 + threadIdx.x;
    float4 v = ((const float4*)Wv)[e4];
    int base = e4 * 4;
    float f[4] = {v.x, v.y, v.z, v.w};
#pragma unroll
    for (int t = 0; t < 4; t++) {
        __half hi = __float2half_rn(f[t]);
        __half lo = __float2half_rn(f[t] - __half2float(hi));
        g_wvh[base + t] = hi;
        g_wvl[base + t] = lo;
    }
}

__global__ __launch_bounds__(256) void wsplit_qk_kernel(
    const float* __restrict__ Wq, const float* __restrict__ Wk)
{
    int e4 = blockIdx.x * 256 + threadIdx.x;
    float4 v = (e4 < 2048) ? ((const float4*)Wq)[e4]
                           : ((const float4*)Wk)[e4 - 2048];
    int base = e4 * 4;
    float f[4] = {v.x, v.y, v.z, v.w};
#pragma unroll
    for (int t = 0; t < 4; t++) {
        __half hi = __float2half_rn(f[t]);
        __half lo = __float2half_rn(f[t] - __half2float(hi));
        g_wqkh[base + t] = hi;
        g_wqkl[base + t] = lo;
    }
}

// ---------------------------------------------------------------------------
// proj_qk_mma: [q;k][o, n] = [Wq;Wk] x via split-fp16 mma.
// ---------------------------------------------------------------------------
#define PQK_SMEM (2 * 8192 + 2 * 16384 + 256)

__global__ __launch_bounds__(256) void proj_qk_mma_kernel(
    const float* __restrict__ x)
{
    extern __shared__ char dsm[];
    const int b = blockIdx.z, n0 = blockIdx.x * 128;
    const int tid = threadIdx.x, wid = tid >> 5, lane = tid & 31;
    const int wcc = wid >> 2, wn = wid & 3;
    const uint32_t whb = (smem_u32(dsm) + 127) & ~127u;
    const uint32_t wlb = whb + 8192;
    const uint32_t xhb = wlb + 8192;
    const uint32_t xlb = xhb + 16384;

    float acc[2][4][4];
#pragma unroll
    for (int i = 0; i < 2; i++)
#pragma unroll
        for (int j = 0; j < 4; j++)
#pragma unroll
            for (int k = 0; k < 4; k++) acc[i][j][k] = 0.f;

    const int a_row = wcc * 32 + (lane & 15);
    const int a_uo  = lane >> 4;
    const int b_row = wn * 32 + (lane & 7) + ((lane >> 4) << 3);
    const int b_uo  = (lane >> 3) & 1;

    for (int kc = 0; kc < 4; kc++) {
        __syncthreads();
#pragma unroll
        for (int i = 0; i < 2; i++) {
            int e = tid + i * 256, row = e >> 3, u = e & 7;
            cp16(swaddr(whb, row, u), g_wqkh + (size_t)row * CC + kc * 64 + u * 8);
            cp16(swaddr(wlb, row, u), g_wqkl + (size_t)row * CC + kc * 64 + u * 8);
        }
        asm volatile("cp.async.commit_group;" ::: "memory");

        stage_x_chunk(x, b, kc, n0, xhb, xlb, tid);

        asm volatile("cp.async.wait_group 0;" ::: "memory");
        __syncthreads();

#pragma unroll
        for (int ks = 0; ks < 4; ks++) {
            uint32_t ah[2][4], al[2][4];
#pragma unroll
            for (int qt = 0; qt < 2; qt++) {
                ldm_x4(ah[qt][0], ah[qt][1], ah[qt][2], ah[qt][3],
                       swaddr(whb, a_row + qt * 16, a_uo + ks * 2));
                ldm_x4(al[qt][0], al[qt][1], al[qt][2], al[qt][3],
                       swaddr(wlb, a_row + qt * 16, a_uo + ks * 2));
            }
            uint32_t bh[4][2], bl[4][2];
#pragma unroll
            for (int nt2 = 0; nt2 < 2; nt2++) {
                uint32_t r0, r1, r2, r3;
                ldm_x4(r0, r1, r2, r3,
                       swaddr(xhb, b_row + nt2 * 16, b_uo + ks * 2));
                bh[nt2 * 2][0] = r0;     bh[nt2 * 2][1] = r1;
                bh[nt2 * 2 + 1][0] = r2; bh[nt2 * 2 + 1][1] = r3;
                ldm_x4(r0, r1, r2, r3,
                       swaddr(xlb, b_row + nt2 * 16, b_uo + ks * 2));
                bl[nt2 * 2][0] = r0;     bl[nt2 * 2][1] = r1;
                bl[nt2 * 2 + 1][0] = r2; bl[nt2 * 2 + 1][1] = r3;
            }
#pragma unroll
            for (int qt = 0; qt < 2; qt++)
#pragma unroll
                for (int nt = 0; nt < 4; nt++) {
                    mma16816(acc[qt][nt], ah[qt], bh[nt][0], bh[nt][1]);
                    mma16816(acc[qt][nt], al[qt], bh[nt][0], bh[nt][1]);
                    mma16816(acc[qt][nt], ah[qt], bl[nt][0], bl[nt][1]);
                }
        }
    }

    // epilogue: split each fp32 value to hi/lo fp16, write g_qh / g_kh
#pragma unroll
    for (int qt = 0; qt < 2; qt++)
#pragma unroll
        for (int nt = 0; nt < 4; nt++) {
            int o_base = wcc * 32 + qt * 16 + (lane >> 2);
            int n_base = n0 + wn * 32 + nt * 8 + 2 * (lane & 3);
#pragma unroll
            for (int dd = 0; dd < 4; dd++) {
                int o = o_base + ((dd >> 1) << 3);
                int n = n_base + (dd & 1);
                float a = acc[qt][nt][dd];
                __half hi = __float2half_rn(a);
                __half lo = __float2half_rn(a - __half2float(hi));
                size_t base = ((size_t)b * NN + n) * 64;
                if (o < 32) { g_qh[base + o] = hi;      g_qh[base + 32 + o] = lo; }
                else        { g_kh[base + o - 32] = hi; g_kh[base + o] = lo; }
            }
        }
}

// ---------------------------------------------------------------------------
// proj_v_mma: V[c, n] = Wv x via split-fp16 mma
// ---------------------------------------------------------------------------
#define PVW_SMEM (4 * 16384 + 256)

__global__ __launch_bounds__(256) void proj_v_mma_kernel(
    const float* __restrict__ x)
{
    extern __shared__ char dsm[];
    const int b = blockIdx.z, n0 = blockIdx.x * 128, c0 = blockIdx.y * 128;
    const int tid = threadIdx.x, wid = tid >> 5, lane = tid & 31;
    const int wcc = wid >> 2, wn = wid & 3;
    const uint32_t whb = (smem_u32(dsm) + 127) & ~127u;
    const uint32_t wlb = whb + 16384;
    const uint32_t xhb = wlb + 16384;
    const uint32_t xlb = xhb + 16384;

    float acc[4][4][4];
#pragma unroll
    for (int i = 0; i < 4; i++)
#pragma unroll
        for (int j = 0; j < 4; j++)
#pragma unroll
            for (int k = 0; k < 4; k++) acc[i][j][k] = 0.f;

    const int a_row = wcc * 64 + (lane & 15);
    const int a_uo  = lane >> 4;
    const int b_row = wn * 32 + (lane & 7) + ((lane >> 4) << 3);
    const int b_uo  = (lane >> 3) & 1;

    for (int kc = 0; kc < 4; kc++) {
        __syncthreads();
#pragma unroll
        for (int i = 0; i < 4; i++) {
            int e = tid + i * 256, row = e >> 3, u = e & 7;
            cp16(swaddr(whb, row, u), g_wvh + (size_t)(c0 + row) * CC + kc * 64 + u * 8);
            cp16(swaddr(wlb, row, u), g_wvl + (size_t)(c0 + row) * CC + kc * 64 + u * 8);
        }
        asm volatile("cp.async.commit_group;" ::: "memory");

        stage_x_chunk(x, b, kc, n0, xhb, xlb, tid);

        asm volatile("cp.async.wait_group 0;" ::: "memory");
        __syncthreads();

#pragma unroll
        for (int ks = 0; ks < 4; ks++) {
            uint32_t ah[4][4], al[4][4];
#pragma unroll
            for (int qt = 0; qt < 4; qt++) {
                ldm_x4(ah[qt][0], ah[qt][1], ah[qt][2], ah[qt][3],
                       swaddr(whb, a_row + qt * 16, a_uo + ks * 2));
                ldm_x4(al[qt][0], al[qt][1], al[qt][2], al[qt][3],
                       swaddr(wlb, a_row + qt * 16, a_uo + ks * 2));
            }
            uint32_t bh[4][2], bl[4][2];
#pragma unroll
            for (int nt2 = 0; nt2 < 2; nt2++) {
                uint32_t r0, r1, r2, r3;
                ldm_x4(r0, r1, r2, r3,
                       swaddr(xhb, b_row + nt2 * 16, b_uo + ks * 2));
                bh[nt2 * 2][0] = r0;     bh[nt2 * 2][1] = r1;
                bh[nt2 * 2 + 1][0] = r2; bh[nt2 * 2 + 1][1] = r3;
                ldm_x4(r0, r1, r2, r3,
                       swaddr(xlb, b_row + nt2 * 16, b_uo + ks * 2));
                bl[nt2 * 2][0] = r0;     bl[nt2 * 2][1] = r1;
                bl[nt2 * 2 + 1][0] = r2; bl[nt2 * 2 + 1][1] = r3;
            }
#pragma unroll
            for (int qt = 0; qt < 4; qt++)
#pragma unroll
                for (int nt = 0; nt < 4; nt++) {
                    mma16816(acc[qt][nt], ah[qt], bh[nt][0], bh[nt][1]);
                    mma16816(acc[qt][nt], al[qt], bh[nt][0], bh[nt][1]);
                    mma16816(acc[qt][nt], ah[qt], bl[nt][0], bl[nt][1]);
                }
        }
    }

#pragma unroll
    for (int qt = 0; qt < 4; qt++)
#pragma unroll
        for (int nt = 0; nt < 4; nt++) {
            int c = c0 + wcc * 64 + qt * 16 + (lane >> 2);
            int n = n0 + wn * 32 + nt * 8 + 2 * (lane & 3);
            *(uint32_t*)(g_vh + ((size_t)b * CC + c) * NN + n) =
                pkh2(acc[qt][nt][0], acc[qt][nt][1]);
            *(uint32_t*)(g_vh + ((size_t)b * CC + c + 8) * NN + n) =
                pkh2(acc[qt][nt][2], acc[qt][nt][3]);
        }
}

// ---------------------------------------------------------------------------
// fattn: fused flash attention + residual (round 13 proven)
// ---------------------------------------------------------------------------
#define FA_SMEM (8192 + 2 * 8192 + 2 * 32768 + 8192 + 128)

__device__ __forceinline__ void fa_load_kv(uint32_t kbuf, uint32_t vbuf,
                                           int b, int jt, int tid)
{
    const __half* ksrc = g_kh + ((size_t)b * NN + jt * 64) * 64;
#pragma unroll
    for (int rr = 0; rr < 2; rr++) {
        int e = tid + rr * 256, row = e >> 3, u = e & 7;
        cp16(swaddr(kbuf, row, u), ksrc + (size_t)row * 64 + u * 8);
    }
    const __half* vsrc = g_vh + (size_t)b * CC * NN + jt * 64;
#pragma unroll
    for (int rr = 0; rr < 8; rr++) {
        int e = tid + rr * 256, row = e >> 3, u = e & 7;
        cp16(swaddr(vbuf, row, u), vsrc + (size_t)row * NN + u * 8);
    }
    asm volatile("cp.async.commit_group;" ::: "memory");
}

__global__ __launch_bounds__(256, 2) void fattn_kernel(
    const float* __restrict__ x, float* __restrict__ out)
{
    extern __shared__ char dsm[];
    __shared__ float Mb[2][64], Lb[2][64];
    __shared__ float pmS[2][64], plS[2][64];
    __shared__ float corrS[64];

    const int b = blockIdx.z, q0 = blockIdx.x * 64;
    const int tid = threadIdx.x, w = tid >> 5, lane = tid & 31;
    const int wq = w & 3, wh = w >> 2;
    const uint32_t qb = (smem_u32(dsm) + 127) & ~127u;
    const uint32_t kbuf[2] = {qb + 8192,  qb + 16384};
    const uint32_t vbuf[2] = {qb + 24576, qb + 57344};
    const uint32_t ptile   = qb + 90112;

    {
        const __half* qsrc = g_qh + ((size_t)b * NN + q0) * 64;
#pragma unroll
        for (int rr = 0; rr < 2; rr++) {
            int e = tid + rr * 256, row = e >> 3, u = e & 7;
            cp16(swaddr(qb, row, u), qsrc + (size_t)row * 64 + u * 8);
        }
        asm volatile("cp.async.commit_group;" ::: "memory");
    }
    fa_load_kv(kbuf[0], vbuf[0], b, 0, tid);
    if (tid < 64) { Mb[0][tid] = -1e30f; Lb[0][tid] = 0.f; }

    const int arow = wq * 16 + (lane & 15);
    const int au   = lane >> 4;
    uint32_t qf[6][4];
    {
        asm volatile("cp.async.wait_group 1;" ::: "memory");
        __syncthreads();
        const int poa[3] = {0, 0, 4};
#pragma unroll
        for (int part = 0; part < 3; part++)
#pragma unroll
            for (int ks = 0; ks < 2; ks++)
                ldm_x4(qf[part * 2 + ks][0], qf[part * 2 + ks][1],
                       qf[part * 2 + ks][2], qf[part * 2 + ks][3],
                       swaddr(qb, arow, poa[part] + ks * 2 + au));
    }

    float acc[2][8][4];
#pragma unroll
    for (int i = 0; i < 2; i++)
#pragma unroll
        for (int j = 0; j < 8; j++)
#pragma unroll
            for (int k = 0; k < 4; k++) acc[i][j][k] = 0.f;

    const int krow = wh * 32 + (lane & 7) + ((lane >> 4) << 3);
    const int ku   = (lane >> 3) & 1;
    const int varow = w * 32 + (lane & 15);
    const int vau   = lane >> 4;
    const int pbrow = (lane & 7) + ((lane >> 4) << 3);
    const int pbu   = (lane >> 3) & 1;
    const int r0   = lane >> 2;

    const int NTJ = NN / 64;
    for (int jt = 0; jt < NTJ; jt++) {
        const int par = jt & 1, nxt = par ^ 1;

        asm volatile("cp.async.wait_group 0;" ::: "memory");
        __syncthreads();            // (1)

        if (jt + 1 < NTJ)
            fa_load_kv(kbuf[nxt], vbuf[nxt], b, jt + 1, tid);

        // ---- S ----
        float s[4][4];
#pragma unroll
        for (int i = 0; i < 4; i++)
#pragma unroll
            for (int k = 0; k < 4; k++) s[i][k] = 0.f;
        {
            const int pob[3] = {0, 4, 0};
            const uint32_t kcur = kbuf[par];
#pragma unroll
            for (int part = 0; part < 3; part++)
#pragma unroll
                for (int ks = 0; ks < 2; ks++) {
#pragma unroll
                    for (int nt2 = 0; nt2 < 2; nt2++) {
                        uint32_t b0, b1, b2, b3;
                        ldm_x4(b0, b1, b2, b3,
                               swaddr(kcur, krow + nt2 * 16,
                                      pob[part] + ks * 2 + ku));
                        mma16816(s[nt2 * 2],     qf[part * 2 + ks], b0, b1);
                        mma16816(s[nt2 * 2 + 1], qf[part * 2 + ks], b2, b3);
                    }
                }
        }

        // ---- partial row max ----
#pragma unroll
        for (int h = 0; h < 2; h++) {
            float t = -1e30f;
#pragma unroll
            for (int nt = 0; nt < 4; nt++)
                t = fmaxf(t, fmaxf(s[nt][2 * h], s[nt][2 * h + 1]));
            t = fmaxf(t, __shfl_xor_sync(0xffffffffu, t, 1));
            t = fmaxf(t, __shfl_xor_sync(0xffffffffu, t, 2));
            if ((lane & 3) == 0) pmS[wh][wq * 16 + r0 + h * 8] = t;
        }
        __syncthreads();                    // (2)

        // ---- stats + exp + P + corr ----
#pragma unroll
        for (int h = 0; h < 2; h++) {
            const int row = wq * 16 + r0 + h * 8;
            float mold = Mb[par][row];
            float mn = fmaxf(mold, fmaxf(pmS[0][row], pmS[1][row]));
            float corr = __expf(mold - mn);
            float lp = 0.f;
#pragma unroll
            for (int nt = 0; nt < 4; nt++) {
                float p0 = __expf(s[nt][2 * h]     - mn);
                float p1 = __expf(s[nt][2 * h + 1] - mn);
                lp += p0 + p1;
                int col = wh * 32 + nt * 8 + 2 * (lane & 3);
                int byte = col * 2;
                sts32(swaddr(ptile, row, byte >> 4) + (byte & 15), pkh2(p0, p1));
            }
            lp += __shfl_xor_sync(0xffffffffu, lp, 1);
            lp += __shfl_xor_sync(0xffffffffu, lp, 2);
            if ((lane & 3) == 0) {
                plS[wh][row] = lp;
                if (wh == 0) { Mb[nxt][row] = mn; corrS[row] = corr; }
            }
        }
        __syncthreads();                    // (3)

        if (tid < 64) {
            float corr = __expf(Mb[par][tid] - Mb[nxt][tid]);
            Lb[nxt][tid] = Lb[par][tid] * corr + plS[0][tid] + plS[1][tid];
        }

        // ---- PV (transposed): acc(c,q) += V(c,j) P(q,j)^T ----
        {
            const float2* c2 = (const float2*)corrS;
            const int qoff = lane & 3;
            float2 ccv[8];
            bool anyc = false;
#pragma unroll
            for (int nf = 0; nf < 8; nf++) {
                ccv[nf] = c2[nf * 4 + qoff];
                anyc = anyc || (ccv[nf].x != 1.f) || (ccv[nf].y != 1.f);
            }
            if (__any_sync(0xffffffffu, anyc)) {
#pragma unroll
                for (int nf = 0; nf < 8; nf++)
#pragma unroll
                    for (int ct = 0; ct < 2; ct++) {
                        acc[ct][nf][0] *= ccv[nf].x;
                        acc[ct][nf][1] *= ccv[nf].y;
                        acc[ct][nf][2] *= ccv[nf].x;
                        acc[ct][nf][3] *= ccv[nf].y;
                    }
            }
            const uint32_t vcur = vbuf[par];
#pragma unroll
            for (int ks = 0; ks < 4; ks++) {
                uint32_t a0[4], a1[4];
                ldm_x4(a0[0], a0[1], a0[2], a0[3],
                       swaddr(vcur, varow,      vau + ks * 2));
                ldm_x4(a1[0], a1[1], a1[2], a1[3],
                       swaddr(vcur, varow + 16, vau + ks * 2));
#pragma unroll
                for (int qt = 0; qt < 4; qt++) {
                    uint32_t b0, b1, b2, b3;
                    ldm_x4(b0, b1, b2, b3,
                           swaddr(ptile, pbrow + qt * 16, pbu + ks * 2));
                    mma16816(acc[0][qt * 2],     a0, b0, b1);
                    mma16816(acc[0][qt * 2 + 1], a0, b2, b3);
                    mma16816(acc[1][qt * 2],     a1, b0, b1);
                    mma16816(acc[1][qt * 2 + 1], a1, b2, b3);
                }
            }
        }
    }
    __syncthreads();

    // ---- epilogue ----
    {
        const float2* l2 = (const float2*)Lb[0];
        const int qoff = lane & 3;
#pragma unroll
        for (int nf = 0; nf < 8; nf++) {
            float2 lv = l2[nf * 4 + qoff];
            float inv0 = 1.f / lv.x, inv1 = 1.f / lv.y;
            int q = q0 + nf * 8 + 2 * qoff;
#pragma unroll
            for (int ct = 0; ct < 2; ct++) {
                int c = w * 32 + ct * 16 + (lane >> 2);
                size_t i00 = ((size_t)b * CC + c) * NN + q;
                float2 xr0 = *(const float2*)(x + i00);
                float2 o0;
                o0.x = acc[ct][nf][0] * inv0 + xr0.x;
                o0.y = acc[ct][nf][1] * inv1 + xr0.y;
                *(float2*)(out + i00) = o0;
                size_t i08 = i00 + (size_t)8 * NN;
                float2 xr1 = *(const float2*)(x + i08);
                float2 o1;
                o1.x = acc[ct][nf][2] * inv0 + xr1.x;
                o1.y = acc[ct][nf][3] * inv1 + xr1.y;
                *(float2*)(out + i08) = o1;
            }
        }
    }
}

// ---------------------------------------------------------------------------
extern "C" void kernel_launch(void* const* d_in, const int* in_sizes, int n_in,
                              void* d_out, int out_size)
{
    const float* x  = (const float*)d_in[0];
    const float* Wq = (const float*)d_in[1];
    const float* Wk = (const float*)d_in[2];
    const float* Wv = (const float*)d_in[3];
    float* out = (float*)d_out;

    cudaFuncSetAttribute(fattn_kernel,
                         cudaFuncAttributeMaxDynamicSharedMemorySize, FA_SMEM);
    cudaFuncSetAttribute(proj_v_mma_kernel,
                         cudaFuncAttributeMaxDynamicSharedMemorySize, PVW_SMEM);
    cudaFuncSetAttribute(proj_qk_mma_kernel,
                         cudaFuncAttributeMaxDynamicSharedMemorySize, PQK_SMEM);

    wsplit_kernel     <<<64, 256>>>(Wv);
    wsplit_qk_kernel  <<<16, 256>>>(Wq, Wk);
    proj_qk_mma_kernel<<<dim3(NN / 128, 1, BB), 256, PQK_SMEM>>>(x);
    proj_v_mma_kernel <<<dim3(NN / 128, CC / 128, BB), 256, PVW_SMEM>>>(x);
    fattn_kernel      <<<dim3(NN / 64, 1, BB), 256, FA_SMEM>>>(x, out);
}

// round 15
// speedup vs baseline: 11.4154x; 1.0195x over previous
#include <cuda_runtime.h>
#include <cuda_fp16.h>
#include <math.h>
#include <stdint.h>

#define BB 4
#define CC 256
#define NN 4096

// ---------------- scratch (__device__ globals; no allocs allowed) ----------
__device__ __half g_qh[(size_t)BB * NN * 64];   // [b][n][32 q_hi | 32 q_lo] (2 MB)
__device__ __half g_kh[(size_t)BB * NN * 64];   // [b][n][32 k_hi | 32 k_lo] (2 MB)
__device__ __half g_vh[(size_t)BB * CC * NN];   // [b][c][j] fp16 V (8 MB)
__device__ __half g_wvh[CC * CC];               // Wv hi (128 KB)
__device__ __half g_wvl[CC * CC];               // Wv lo (128 KB)
__device__ __half g_wqkh[64 * CC];              // [Wq;Wk] hi (32 KB)
__device__ __half g_wqkl[64 * CC];              // [Wq;Wk] lo (32 KB)

// ---------------- helpers ---------------------------------------------------
__device__ __forceinline__ uint32_t smem_u32(const void* p) {
    uint32_t a;
    asm("{ .reg .u64 t; cvta.to.shared.u64 t, %1; cvt.u32.u64 %0, t; }"
        : "=r"(a) : "l"(p));
    return a;
}
__device__ __forceinline__ void cp16(uint32_t dst, const void* src) {
    asm volatile("cp.async.cg.shared.global [%0], [%1], 16;" :: "r"(dst), "l"(src)
                 : "memory");
}
__device__ __forceinline__ void sts32(uint32_t a, uint32_t v) {
    asm volatile("st.shared.u32 [%0], %1;" :: "r"(a), "r"(v) : "memory");
}
__device__ __forceinline__ void sts128(uint32_t a, uint32_t r0, uint32_t r1,
                                       uint32_t r2, uint32_t r3) {
    asm volatile("st.shared.v4.b32 [%0], {%1,%2,%3,%4};"
                 :: "r"(a), "r"(r0), "r"(r1), "r"(r2), "r"(r3) : "memory");
}
__device__ __forceinline__ uint32_t swaddr(uint32_t base, int row, int u) {
    return base + row * 128 + (((u) ^ (row & 7)) << 4);
}
__device__ __forceinline__ void ldm_x4(uint32_t& r0, uint32_t& r1,
                                       uint32_t& r2, uint32_t& r3, uint32_t a) {
    asm volatile("ldmatrix.sync.aligned.m8n8.x4.shared.b16 {%0,%1,%2,%3}, [%4];"
                 : "=r"(r0), "=r"(r1), "=r"(r2), "=r"(r3) : "r"(a));
}
__device__ __forceinline__ void mma16816(float* d, const uint32_t* a,
                                         uint32_t b0, uint32_t b1) {
    asm volatile(
        "mma.sync.aligned.m16n8k16.row.col.f32.f16.f16.f32 "
        "{%0,%1,%2,%3}, {%4,%5,%6,%7}, {%8,%9}, {%0,%1,%2,%3};"
        : "+f"(d[0]), "+f"(d[1]), "+f"(d[2]), "+f"(d[3])
        : "r"(a[0]), "r"(a[1]), "r"(a[2]), "r"(a[3]), "r"(b0), "r"(b1));
}
__device__ __forceinline__ uint32_t pkh2(float a, float b) {
    __half2 h = __floats2half2_rn(a, b);
    return *reinterpret_cast<uint32_t*>(&h);
}
__device__ __forceinline__ uint32_t packh(__half a, __half b) {
    __half2 h = __halves2half2(a, b);
    return *reinterpret_cast<uint32_t*>(&h);
}

// conflict-free x chunk staging (proven round 14)
__device__ __forceinline__ void stage_x_chunk(
    const float* __restrict__ x, int b, int kc, int n0,
    uint32_t xhb, uint32_t xlb, int tid)
{
    const int n = tid & 127, khalf = tid >> 7;
    const float* xcol =
        x + ((size_t)b * CC + kc * 64 + khalf * 32) * NN + n0 + n;
#pragma unroll
    for (int oct = 0; oct < 4; oct++) {
        float f[8];
#pragma unroll
        for (int j = 0; j < 8; j++)
            f[j] = xcol[(size_t)(oct * 8 + j) * NN];
        uint32_t hh[4], ll[4];
#pragma unroll
        for (int p = 0; p < 4; p++) {
            __half h0 = __float2half_rn(f[2 * p]);
            __half h1 = __float2half_rn(f[2 * p + 1]);
            hh[p] = packh(h0, h1);
            ll[p] = pkh2(f[2 * p]     - __half2float(h0),
                         f[2 * p + 1] - __half2float(h1));
        }
        int u = khalf * 4 + oct;
        sts128(swaddr(xhb, n, u), hh[0], hh[1], hh[2], hh[3]);
        sts128(swaddr(xlb, n, u), ll[0], ll[1], ll[2], ll[3]);
    }
}

// ---------------------------------------------------------------------------
// wsplit kernels
// ---------------------------------------------------------------------------
__global__ __launch_bounds__(256) void wsplit_kernel(const float* __restrict__ Wv)
{
    int e4 = blockIdx.x * 256 + threadIdx.x;
    float4 v = ((const float4*)Wv)[e4];
    int base = e4 * 4;
    float f[4] = {v.x, v.y, v.z, v.w};
#pragma unroll
    for (int t = 0; t < 4; t++) {
        __half hi = __float2half_rn(f[t]);
        __half lo = __float2half_rn(f[t] - __half2float(hi));
        g_wvh[base + t] = hi;
        g_wvl[base + t] = lo;
    }
}

__global__ __launch_bounds__(256) void wsplit_qk_kernel(
    const float* __restrict__ Wq, const float* __restrict__ Wk)
{
    int e4 = blockIdx.x * 256 + threadIdx.x;
    float4 v = (e4 < 2048) ? ((const float4*)Wq)[e4]
                           : ((const float4*)Wk)[e4 - 2048];
    int base = e4 * 4;
    float f[4] = {v.x, v.y, v.z, v.w};
#pragma unroll
    for (int t = 0; t < 4; t++) {
        __half hi = __float2half_rn(f[t]);
        __half lo = __float2half_rn(f[t] - __half2float(hi));
        g_wqkh[base + t] = hi;
        g_wqkl[base + t] = lo;
    }
}

// ---------------------------------------------------------------------------
// proj_kernel: fused V + QK projections via split-fp16 mma.
//   blockIdx.y = 0,1 -> V c-half (c0 = y*128), proven proj_v_mma body.
//   blockIdx.y = 2   -> QK path (64 outputs), proven proj_qk_mma body.
// One grid -> one wave; 2 CTAs/SM.
// ---------------------------------------------------------------------------
#define PVW_SMEM (4 * 16384 + 256)

__global__ __launch_bounds__(256, 2) void proj_kernel(
    const float* __restrict__ x)
{
    extern __shared__ char dsm[];
    const int b = blockIdx.z, n0 = blockIdx.x * 128;
    const int path = blockIdx.y;               // 0,1 = V halves; 2 = QK
    const int tid = threadIdx.x, wid = tid >> 5, lane = tid & 31;
    const int wcc = wid >> 2, wn = wid & 3;

    if (path < 2) {
        // ================= V path: 128c x 128n =================
        const int c0 = path * 128;
        const uint32_t whb = (smem_u32(dsm) + 127) & ~127u;
        const uint32_t wlb = whb + 16384;
        const uint32_t xhb = wlb + 16384;
        const uint32_t xlb = xhb + 16384;

        float acc[4][4][4];
#pragma unroll
        for (int i = 0; i < 4; i++)
#pragma unroll
            for (int j = 0; j < 4; j++)
#pragma unroll
                for (int k = 0; k < 4; k++) acc[i][j][k] = 0.f;

        const int a_row = wcc * 64 + (lane & 15);
        const int a_uo  = lane >> 4;
        const int b_row = wn * 32 + (lane & 7) + ((lane >> 4) << 3);
        const int b_uo  = (lane >> 3) & 1;

        for (int kc = 0; kc < 4; kc++) {
            __syncthreads();
#pragma unroll
            for (int i = 0; i < 4; i++) {
                int e = tid + i * 256, row = e >> 3, u = e & 7;
                cp16(swaddr(whb, row, u),
                     g_wvh + (size_t)(c0 + row) * CC + kc * 64 + u * 8);
                cp16(swaddr(wlb, row, u),
                     g_wvl + (size_t)(c0 + row) * CC + kc * 64 + u * 8);
            }
            asm volatile("cp.async.commit_group;" ::: "memory");

            stage_x_chunk(x, b, kc, n0, xhb, xlb, tid);

            asm volatile("cp.async.wait_group 0;" ::: "memory");
            __syncthreads();

#pragma unroll
            for (int ks = 0; ks < 4; ks++) {
                uint32_t ah[4][4], al[4][4];
#pragma unroll
                for (int qt = 0; qt < 4; qt++) {
                    ldm_x4(ah[qt][0], ah[qt][1], ah[qt][2], ah[qt][3],
                           swaddr(whb, a_row + qt * 16, a_uo + ks * 2));
                    ldm_x4(al[qt][0], al[qt][1], al[qt][2], al[qt][3],
                           swaddr(wlb, a_row + qt * 16, a_uo + ks * 2));
                }
                uint32_t bh[4][2], bl[4][2];
#pragma unroll
                for (int nt2 = 0; nt2 < 2; nt2++) {
                    uint32_t r0, r1, r2, r3;
                    ldm_x4(r0, r1, r2, r3,
                           swaddr(xhb, b_row + nt2 * 16, b_uo + ks * 2));
                    bh[nt2 * 2][0] = r0;     bh[nt2 * 2][1] = r1;
                    bh[nt2 * 2 + 1][0] = r2; bh[nt2 * 2 + 1][1] = r3;
                    ldm_x4(r0, r1, r2, r3,
                           swaddr(xlb, b_row + nt2 * 16, b_uo + ks * 2));
                    bl[nt2 * 2][0] = r0;     bl[nt2 * 2][1] = r1;
                    bl[nt2 * 2 + 1][0] = r2; bl[nt2 * 2 + 1][1] = r3;
                }
#pragma unroll
                for (int qt = 0; qt < 4; qt++)
#pragma unroll
                    for (int nt = 0; nt < 4; nt++) {
                        mma16816(acc[qt][nt], ah[qt], bh[nt][0], bh[nt][1]);
                        mma16816(acc[qt][nt], al[qt], bh[nt][0], bh[nt][1]);
                        mma16816(acc[qt][nt], ah[qt], bl[nt][0], bl[nt][1]);
                    }
            }
        }

#pragma unroll
        for (int qt = 0; qt < 4; qt++)
#pragma unroll
            for (int nt = 0; nt < 4; nt++) {
                int c = c0 + wcc * 64 + qt * 16 + (lane >> 2);
                int n = n0 + wn * 32 + nt * 8 + 2 * (lane & 3);
                *(uint32_t*)(g_vh + ((size_t)b * CC + c) * NN + n) =
                    pkh2(acc[qt][nt][0], acc[qt][nt][1]);
                *(uint32_t*)(g_vh + ((size_t)b * CC + c + 8) * NN + n) =
                    pkh2(acc[qt][nt][2], acc[qt][nt][3]);
            }
    } else {
        // ================= QK path: 64o x 128n =================
        const uint32_t whb = (smem_u32(dsm) + 127) & ~127u;
        const uint32_t wlb = whb + 8192;
        const uint32_t xhb = wlb + 8192;
        const uint32_t xlb = xhb + 16384;

        float acc[2][4][4];
#pragma unroll
        for (int i = 0; i < 2; i++)
#pragma unroll
            for (int j = 0; j < 4; j++)
#pragma unroll
                for (int k = 0; k < 4; k++) acc[i][j][k] = 0.f;

        const int a_row = wcc * 32 + (lane & 15);
        const int a_uo  = lane >> 4;
        const int b_row = wn * 32 + (lane & 7) + ((lane >> 4) << 3);
        const int b_uo  = (lane >> 3) & 1;

        for (int kc = 0; kc < 4; kc++) {
            __syncthreads();
#pragma unroll
            for (int i = 0; i < 2; i++) {
                int e = tid + i * 256, row = e >> 3, u = e & 7;
                cp16(swaddr(whb, row, u),
                     g_wqkh + (size_t)row * CC + kc * 64 + u * 8);
                cp16(swaddr(wlb, row, u),
                     g_wqkl + (size_t)row * CC + kc * 64 + u * 8);
            }
            asm volatile("cp.async.commit_group;" ::: "memory");

            stage_x_chunk(x, b, kc, n0, xhb, xlb, tid);

            asm volatile("cp.async.wait_group 0;" ::: "memory");
            __syncthreads();

#pragma unroll
            for (int ks = 0; ks < 4; ks++) {
                uint32_t ah[2][4], al[2][4];
#pragma unroll
                for (int qt = 0; qt < 2; qt++) {
                    ldm_x4(ah[qt][0], ah[qt][1], ah[qt][2], ah[qt][3],
                           swaddr(whb, a_row + qt * 16, a_uo + ks * 2));
                    ldm_x4(al[qt][0], al[qt][1], al[qt][2], al[qt][3],
                           swaddr(wlb, a_row + qt * 16, a_uo + ks * 2));
                }
                uint32_t bh[4][2], bl[4][2];
#pragma unroll
                for (int nt2 = 0; nt2 < 2; nt2++) {
                    uint32_t r0, r1, r2, r3;
                    ldm_x4(r0, r1, r2, r3,
                           swaddr(xhb, b_row + nt2 * 16, b_uo + ks * 2));
                    bh[nt2 * 2][0] = r0;     bh[nt2 * 2][1] = r1;
                    bh[nt2 * 2 + 1][0] = r2; bh[nt2 * 2 + 1][1] = r3;
                    ldm_x4(r0, r1, r2, r3,
                           swaddr(xlb, b_row + nt2 * 16, b_uo + ks * 2));
                    bl[nt2 * 2][0] = r0;     bl[nt2 * 2][1] = r1;
                    bl[nt2 * 2 + 1][0] = r2; bl[nt2 * 2 + 1][1] = r3;
                }
#pragma unroll
                for (int qt = 0; qt < 2; qt++)
#pragma unroll
                    for (int nt = 0; nt < 4; nt++) {
                        mma16816(acc[qt][nt], ah[qt], bh[nt][0], bh[nt][1]);
                        mma16816(acc[qt][nt], al[qt], bh[nt][0], bh[nt][1]);
                        mma16816(acc[qt][nt], ah[qt], bl[nt][0], bl[nt][1]);
                    }
            }
        }

#pragma unroll
        for (int qt = 0; qt < 2; qt++)
#pragma unroll
            for (int nt = 0; nt < 4; nt++) {
                int o_base = wcc * 32 + qt * 16 + (lane >> 2);
                int n_base = n0 + wn * 32 + nt * 8 + 2 * (lane & 3);
#pragma unroll
                for (int dd = 0; dd < 4; dd++) {
                    int o = o_base + ((dd >> 1) << 3);
                    int n = n_base + (dd & 1);
                    float a = acc[qt][nt][dd];
                    __half hi = __float2half_rn(a);
                    __half lo = __float2half_rn(a - __half2float(hi));
                    size_t base = ((size_t)b * NN + n) * 64;
                    if (o < 32) { g_qh[base + o] = hi;      g_qh[base + 32 + o] = lo; }
                    else        { g_kh[base + o - 32] = hi; g_kh[base + o] = lo; }
                }
            }
    }
}

// ---------------------------------------------------------------------------
// fattn: fused flash attention + residual (round 13/14 proven, unchanged)
// ---------------------------------------------------------------------------
#define FA_SMEM (8192 + 2 * 8192 + 2 * 32768 + 8192 + 128)

__device__ __forceinline__ void fa_load_kv(uint32_t kbuf, uint32_t vbuf,
                                           int b, int jt, int tid)
{
    const __half* ksrc = g_kh + ((size_t)b * NN + jt * 64) * 64;
#pragma unroll
    for (int rr = 0; rr < 2; rr++) {
        int e = tid + rr * 256, row = e >> 3, u = e & 7;
        cp16(swaddr(kbuf, row, u), ksrc + (size_t)row * 64 + u * 8);
    }
    const __half* vsrc = g_vh + (size_t)b * CC * NN + jt * 64;
#pragma unroll
    for (int rr = 0; rr < 8; rr++) {
        int e = tid + rr * 256, row = e >> 3, u = e & 7;
        cp16(swaddr(vbuf, row, u), vsrc + (size_t)row * NN + u * 8);
    }
    asm volatile("cp.async.commit_group;" ::: "memory");
}

__global__ __launch_bounds__(256, 2) void fattn_kernel(
    const float* __restrict__ x, float* __restrict__ out)
{
    extern __shared__ char dsm[];
    __shared__ float Mb[2][64], Lb[2][64];
    __shared__ float pmS[2][64], plS[2][64];
    __shared__ float corrS[64];

    const int b = blockIdx.z, q0 = blockIdx.x * 64;
    const int tid = threadIdx.x, w = tid >> 5, lane = tid & 31;
    const int wq = w & 3, wh = w >> 2;
    const uint32_t qb = (smem_u32(dsm) + 127) & ~127u;
    const uint32_t kbuf[2] = {qb + 8192,  qb + 16384};
    const uint32_t vbuf[2] = {qb + 24576, qb + 57344};
    const uint32_t ptile   = qb + 90112;

    {
        const __half* qsrc = g_qh + ((size_t)b * NN + q0) * 64;
#pragma unroll
        for (int rr = 0; rr < 2; rr++) {
            int e = tid + rr * 256, row = e >> 3, u = e & 7;
            cp16(swaddr(qb, row, u), qsrc + (size_t)row * 64 + u * 8);
        }
        asm volatile("cp.async.commit_group;" ::: "memory");
    }
    fa_load_kv(kbuf[0], vbuf[0], b, 0, tid);
    if (tid < 64) { Mb[0][tid] = -1e30f; Lb[0][tid] = 0.f; }

    const int arow = wq * 16 + (lane & 15);
    const int au   = lane >> 4;
    uint32_t qf[6][4];
    {
        asm volatile("cp.async.wait_group 1;" ::: "memory");
        __syncthreads();
        const int poa[3] = {0, 0, 4};
#pragma unroll
        for (int part = 0; part < 3; part++)
#pragma unroll
            for (int ks = 0; ks < 2; ks++)
                ldm_x4(qf[part * 2 + ks][0], qf[part * 2 + ks][1],
                       qf[part * 2 + ks][2], qf[part * 2 + ks][3],
                       swaddr(qb, arow, poa[part] + ks * 2 + au));
    }

    float acc[2][8][4];
#pragma unroll
    for (int i = 0; i < 2; i++)
#pragma unroll
        for (int j = 0; j < 8; j++)
#pragma unroll
            for (int k = 0; k < 4; k++) acc[i][j][k] = 0.f;

    const int krow = wh * 32 + (lane & 7) + ((lane >> 4) << 3);
    const int ku   = (lane >> 3) & 1;
    const int varow = w * 32 + (lane & 15);
    const int vau   = lane >> 4;
    const int pbrow = (lane & 7) + ((lane >> 4) << 3);
    const int pbu   = (lane >> 3) & 1;
    const int r0   = lane >> 2;

    const int NTJ = NN / 64;
    for (int jt = 0; jt < NTJ; jt++) {
        const int par = jt & 1, nxt = par ^ 1;

        asm volatile("cp.async.wait_group 0;" ::: "memory");
        __syncthreads();            // (1)

        if (jt + 1 < NTJ)
            fa_load_kv(kbuf[nxt], vbuf[nxt], b, jt + 1, tid);

        // ---- S ----
        float s[4][4];
#pragma unroll
        for (int i = 0; i < 4; i++)
#pragma unroll
            for (int k = 0; k < 4; k++) s[i][k] = 0.f;
        {
            const int pob[3] = {0, 4, 0};
            const uint32_t kcur = kbuf[par];
#pragma unroll
            for (int part = 0; part < 3; part++)
#pragma unroll
                for (int ks = 0; ks < 2; ks++) {
#pragma unroll
                    for (int nt2 = 0; nt2 < 2; nt2++) {
                        uint32_t b0, b1, b2, b3;
                        ldm_x4(b0, b1, b2, b3,
                               swaddr(kcur, krow + nt2 * 16,
                                      pob[part] + ks * 2 + ku));
                        mma16816(s[nt2 * 2],     qf[part * 2 + ks], b0, b1);
                        mma16816(s[nt2 * 2 + 1], qf[part * 2 + ks], b2, b3);
                    }
                }
        }

        // ---- partial row max ----
#pragma unroll
        for (int h = 0; h < 2; h++) {
            float t = -1e30f;
#pragma unroll
            for (int nt = 0; nt < 4; nt++)
                t = fmaxf(t, fmaxf(s[nt][2 * h], s[nt][2 * h + 1]));
            t = fmaxf(t, __shfl_xor_sync(0xffffffffu, t, 1));
            t = fmaxf(t, __shfl_xor_sync(0xffffffffu, t, 2));
            if ((lane & 3) == 0) pmS[wh][wq * 16 + r0 + h * 8] = t;
        }
        __syncthreads();                    // (2)

        // ---- stats + exp + P + corr ----
#pragma unroll
        for (int h = 0; h < 2; h++) {
            const int row = wq * 16 + r0 + h * 8;
            float mold = Mb[par][row];
            float mn = fmaxf(mold, fmaxf(pmS[0][row], pmS[1][row]));
            float corr = __expf(mold - mn);
            float lp = 0.f;
#pragma unroll
            for (int nt = 0; nt < 4; nt++) {
                float p0 = __expf(s[nt][2 * h]     - mn);
                float p1 = __expf(s[nt][2 * h + 1] - mn);
                lp += p0 + p1;
                int col = wh * 32 + nt * 8 + 2 * (lane & 3);
                int byte = col * 2;
                sts32(swaddr(ptile, row, byte >> 4) + (byte & 15), pkh2(p0, p1));
            }
            lp += __shfl_xor_sync(0xffffffffu, lp, 1);
            lp += __shfl_xor_sync(0xffffffffu, lp, 2);
            if ((lane & 3) == 0) {
                plS[wh][row] = lp;
                if (wh == 0) { Mb[nxt][row] = mn; corrS[row] = corr; }
            }
        }
        __syncthreads();                    // (3)

        if (tid < 64) {
            float corr = __expf(Mb[par][tid] - Mb[nxt][tid]);
            Lb[nxt][tid] = Lb[par][tid] * corr + plS[0][tid] + plS[1][tid];
        }

        // ---- PV (transposed): acc(c,q) += V(c,j) P(q,j)^T ----
        {
            const float2* c2 = (const float2*)corrS;
            const int qoff = lane & 3;
            float2 ccv[8];
            bool anyc = false;
#pragma unroll
            for (int nf = 0; nf < 8; nf++) {
                ccv[nf] = c2[nf * 4 + qoff];
                anyc = anyc || (ccv[nf].x != 1.f) || (ccv[nf].y != 1.f);
            }
            if (__any_sync(0xffffffffu, anyc)) {
#pragma unroll
                for (int nf = 0; nf < 8; nf++)
#pragma unroll
                    for (int ct = 0; ct < 2; ct++) {
                        acc[ct][nf][0] *= ccv[nf].x;
                        acc[ct][nf][1] *= ccv[nf].y;
                        acc[ct][nf][2] *= ccv[nf].x;
                        acc[ct][nf][3] *= ccv[nf].y;
                    }
            }
            const uint32_t vcur = vbuf[par];
#pragma unroll
            for (int ks = 0; ks < 4; ks++) {
                uint32_t a0[4], a1[4];
                ldm_x4(a0[0], a0[1], a0[2], a0[3],
                       swaddr(vcur, varow,      vau + ks * 2));
                ldm_x4(a1[0], a1[1], a1[2], a1[3],
                       swaddr(vcur, varow + 16, vau + ks * 2));
#pragma unroll
                for (int qt = 0; qt < 4; qt++) {
                    uint32_t b0, b1, b2, b3;
                    ldm_x4(b0, b1, b2, b3,
                           swaddr(ptile, pbrow + qt * 16, pbu + ks * 2));
                    mma16816(acc[0][qt * 2],     a0, b0, b1);
                    mma16816(acc[0][qt * 2 + 1], a0, b2, b3);
                    mma16816(acc[1][qt * 2],     a1, b0, b1);
                    mma16816(acc[1][qt * 2 + 1], a1, b2, b3);
                }
            }
        }
    }
    __syncthreads();

    // ---- epilogue ----
    {
        const float2* l2 = (const float2*)Lb[0];
        const int qoff = lane & 3;
#pragma unroll
        for (int nf = 0; nf < 8; nf++) {
            float2 lv = l2[nf * 4 + qoff];
            float inv0 = 1.f / lv.x, inv1 = 1.f / lv.y;
            int q = q0 + nf * 8 + 2 * qoff;
#pragma unroll
            for (int ct = 0; ct < 2; ct++) {
                int c = w * 32 + ct * 16 + (lane >> 2);
                size_t i00 = ((size_t)b * CC + c) * NN + q;
                float2 xr0 = *(const float2*)(x + i00);
                float2 o0;
                o0.x = acc[ct][nf][0] * inv0 + xr0.x;
                o0.y = acc[ct][nf][1] * inv1 + xr0.y;
                *(float2*)(out + i00) = o0;
                size_t i08 = i00 + (size_t)8 * NN;
                float2 xr1 = *(const float2*)(x + i08);
                float2 o1;
                o1.x = acc[ct][nf][2] * inv0 + xr1.x;
                o1.y = acc[ct][nf][3] * inv1 + xr1.y;
                *(float2*)(out + i08) = o1;
            }
        }
    }
}

// ---------------------------------------------------------------------------
extern "C" void kernel_launch(void* const* d_in, const int* in_sizes, int n_in,
                              void* d_out, int out_size)
{
    const float* x  = (const float*)d_in[0];
    const float* Wq = (const float*)d_in[1];
    const float* Wk = (const float*)d_in[2];
    const float* Wv = (const float*)d_in[3];
    float* out = (float*)d_out;

    cudaFuncSetAttribute(fattn_kernel,
                         cudaFuncAttributeMaxDynamicSharedMemorySize, FA_SMEM);
    cudaFuncSetAttribute(proj_kernel,
                         cudaFuncAttributeMaxDynamicSharedMemorySize, PVW_SMEM);

    wsplit_kernel   <<<64, 256>>>(Wv);
    wsplit_qk_kernel<<<16, 256>>>(Wq, Wk);
    proj_kernel     <<<dim3(NN / 128, 3, BB), 256, PVW_SMEM>>>(x);
    fattn_kernel    <<<dim3(NN / 64, 1, BB), 256, FA_SMEM>>>(x, out);
}